// round 1
// baseline (speedup 1.0000x reference)
#include <cuda_runtime.h>
#include <math.h>

#define BATCH 2
#define SEQ 128
#define NH 4
#define DKK 128
#define DD 512
#define NBB 4

// ---------------- scratch (device globals; no allocation allowed) ----------------
__device__ float g_qkv[2][3][BATCH][NH][SEQ][DKK]; // [fam(m/c)][q/k/v][b][h][n][k]
__device__ float g_bbQ[BATCH][NH][NBB][NBB][DKK];
__device__ float g_bbK[BATCH][NH][NBB][NBB][DKK];
__device__ float g_pq[BATCH][NH][SEQ][DKK];
__device__ float g_pk[BATCH][NH][SEQ][DKK];
__device__ float g_FQ[BATCH][NH][SEQ][NBB][2*DKK]; // [m(0..127) | sqrt(c)(128..255)]
__device__ float g_FK[BATCH][NH][SEQ][NBB][2*DKK];
__device__ float g_ctx[2][BATCH][SEQ][DD];          // [mean/cov][b][i][d]
__device__ float g_tmp[2][BATCH][SEQ][DD];          // pre-LN

// =====================================================================
// K1: fused projections. out[fam][s][b][h][n][k] =
//      sum_d X1[b,n,d]*W1[s,d,h,k] + X2[b,n,d]*W2[s,d,h,k]  (+elu1 if fam==1)
// GEMM: M=256 (b,n), N=1536 (s,h,k), K=512, two A/B pairs summed.
// =====================================================================
__global__ void proj_kernel(const float* __restrict__ X1, const float* __restrict__ X2,
                            const float* __restrict__ W1, const float* __restrict__ W2,
                            int fam)
{
    const int m0 = blockIdx.x * 64;
    const int n0 = blockIdx.y * 64;
    const int tid = threadIdx.x;           // 256 threads
    const int tx = tid & 15, ty = tid >> 4;

    __shared__ float As[16][64];
    __shared__ float Bs[16][68];

    float acc[4][4] = {};

    const int s_idx = n0 / 512;
    const int cbase = n0 % 512;            // column base inside W row (h*128+k)

    const int a_row = tid >> 2;            // 0..63
    const int a_k4  = (tid & 3) * 4;
    const int b_kd  = tid >> 4;            // 0..15
    const int b_c4  = (tid & 15) * 4;

    for (int pair = 0; pair < 2; ++pair) {
        const float* X = pair ? X2 : X1;
        const float* W = (pair ? W2 : W1) + (size_t)s_idx * 262144 + cbase;
        for (int kk = 0; kk < 512; kk += 16) {
            float4 av = *(const float4*)&X[(size_t)(m0 + a_row) * 512 + kk + a_k4];
            As[a_k4 + 0][a_row] = av.x;
            As[a_k4 + 1][a_row] = av.y;
            As[a_k4 + 2][a_row] = av.z;
            As[a_k4 + 3][a_row] = av.w;
            float4 bv = *(const float4*)&W[(size_t)(kk + b_kd) * 512 + b_c4];
            *(float4*)&Bs[b_kd][b_c4] = bv;
            __syncthreads();
#pragma unroll
            for (int kd = 0; kd < 16; ++kd) {
                float a[4], bb[4];
#pragma unroll
                for (int r = 0; r < 4; ++r) a[r] = As[kd][ty * 4 + r];
#pragma unroll
                for (int c = 0; c < 4; ++c) bb[c] = Bs[kd][tx * 4 + c];
#pragma unroll
                for (int r = 0; r < 4; ++r)
#pragma unroll
                    for (int c = 0; c < 4; ++c) acc[r][c] += a[r] * bb[c];
            }
            __syncthreads();
        }
    }

    const int h_idx = cbase / 128;
    const int k0 = cbase % 128;
#pragma unroll
    for (int r = 0; r < 4; ++r) {
        int m = m0 + ty * 4 + r;
        int b = m >> 7, n = m & 127;
#pragma unroll
        for (int c = 0; c < 4; ++c) {
            int k = k0 + tx * 4 + c;
            float v = acc[r][c];
            if (fam == 1) v = (v > 0.f) ? (v + 1.f) : expf(v);  // elu(x)+1
            g_qkv[fam][s_idx][b][h_idx][n][k] = v;
        }
    }
}

// =====================================================================
// K2a: bb linear — out[r,k] = bias[k] + sum_k' bbm[r,k'] * W[k,k']
// rows r = (b,h,n1,n2), 128 rows; grid.y selects Q(Wq1)/K(Wk1).
// =====================================================================
__global__ void lin_bb_kernel(const float* __restrict__ bb_m,
                              const float* __restrict__ Wq1_w, const float* __restrict__ Wq1_b,
                              const float* __restrict__ Wk1_w, const float* __restrict__ Wk1_b)
{
    int r = blockIdx.x;                 // 0..127
    int t = threadIdx.x;                // 128
    int b  = r >> 6;
    int hh = (r >> 4) & 3;
    int n1 = (r >> 2) & 3;
    int n2 = r & 3;

    const float* W    = blockIdx.y ? Wk1_w : Wq1_w;
    const float* bias = blockIdx.y ? Wk1_b : Wq1_b;
    float* out = blockIdx.y ? &g_bbK[0][0][0][0][0] : &g_bbQ[0][0][0][0][0];

    __shared__ float xs[128];
    xs[t] = bb_m[(size_t)(b * 16 + n1 * 4 + n2) * 512 + hh * 128 + t];
    __syncthreads();

    float acc = bias[t];
    const float4* w4 = (const float4*)(W + (size_t)t * 128);
#pragma unroll 8
    for (int q = 0; q < 32; ++q) {
        float4 w = w4[q];
        acc += xs[4*q] * w.x + xs[4*q+1] * w.y + xs[4*q+2] * w.z + xs[4*q+3] * w.w;
    }
    out[(size_t)r * 128 + t] = acc;
}

// =====================================================================
// K2b: p linear — rows (b,h,n) = 1024; grid.y selects q(Wq2)/k(Wk2).
// =====================================================================
__global__ void lin_p_kernel(const float* __restrict__ p_m,
                             const float* __restrict__ Wq2_w, const float* __restrict__ Wq2_b,
                             const float* __restrict__ Wk2_w, const float* __restrict__ Wk2_b)
{
    int r = blockIdx.x;                 // 0..1023
    int t = threadIdx.x;                // 128
    int b  = r >> 9;
    int hh = (r >> 7) & 3;
    int n  = r & 127;

    const float* W    = blockIdx.y ? Wk2_w : Wq2_w;
    const float* bias = blockIdx.y ? Wk2_b : Wq2_b;
    float* out = blockIdx.y ? &g_pk[0][0][0][0] : &g_pq[0][0][0][0];

    __shared__ float xs[128];
    xs[t] = p_m[(size_t)(b * 128 + n) * 512 + hh * 128 + t];
    __syncthreads();

    float acc = bias[t];
    const float4* w4 = (const float4*)(W + (size_t)t * 128);
#pragma unroll 8
    for (int q = 0; q < 32; ++q) {
        float4 w = w4[q];
        acc += xs[4*q] * w.x + xs[4*q+1] * w.y + xs[4*q+2] * w.z + xs[4*q+3] * w.w;
    }
    out[(size_t)r * 128 + t] = acc;
}

// =====================================================================
// K3: tri-SAGP fusion -> FQ[b,h,i,sb,0:256], FK[b,h,j,sa,0:256]
//   fQ(i,sb): m1=q1[i], c1=q2[i]; m2=bbQ[sb,si], c2=bb_c[sb,si]; m3=pq[i], c3=pc[i]
//   fK(j,sa): m1=k1[j], c1=k2[j]; m2=bbK[sj,sa], c2=bb_c[sj,sa]; m3=pk[j], c3=pc[j]
// =====================================================================
__global__ void build_fqfk(const float* __restrict__ bb_c,
                           const float* __restrict__ p_c,
                           const int* __restrict__ b_seq)
{
    int r = blockIdx.x;                 // 0..1023 = (b,h,i)
    int b  = r >> 9;
    int hh = (r >> 7) & 3;
    int i  = r & 127;
    int t  = threadIdx.x;               // 128
    const float eps = 1e-24f;

    int si = b_seq[b * 128 + i];
    float c3 = p_c[(size_t)(b * 128 + i) * 512 + hh * 128 + t];
    float p3 = 1.f / fmaxf(c3, eps);

    // ---- Q side ----
    {
        float m1 = g_qkv[0][0][b][hh][i][t];
        float c1 = g_qkv[1][0][b][hh][i][t];
        float m3 = g_pq[b][hh][i][t];
        float p1 = 1.f / fmaxf(c1, eps);
        float base_m = m1 * p1 + m3 * p3;
        float base_p = p1 + p3;
#pragma unroll
        for (int sb = 0; sb < 4; ++sb) {
            float m2 = g_bbQ[b][hh][sb][si][t];
            float c2 = bb_c[(size_t)((b * 4 + sb) * 4 + si) * 512 + hh * 128 + t];
            float p2 = 1.f / fmaxf(c2, eps);
            float cf = 1.f / (base_p + p2);
            float mf = cf * (base_m + m2 * p2);
            g_FQ[b][hh][i][sb][t]       = mf;
            g_FQ[b][hh][i][sb][128 + t] = sqrtf(fmaxf(cf, eps));
        }
    }
    // ---- K side (j = i) ----
    {
        float m1 = g_qkv[0][1][b][hh][i][t];
        float c1 = g_qkv[1][1][b][hh][i][t];
        float m3 = g_pk[b][hh][i][t];
        float p1 = 1.f / fmaxf(c1, eps);
        float base_m = m1 * p1 + m3 * p3;
        float base_p = p1 + p3;
        int sj = si;   // b_seq[j] with j == i
#pragma unroll
        for (int sa = 0; sa < 4; ++sa) {
            float m2 = g_bbK[b][hh][sj][sa][t];
            float c2 = bb_c[(size_t)((b * 4 + sj) * 4 + sa) * 512 + hh * 128 + t];
            float p2 = 1.f / fmaxf(c2, eps);
            float cf = 1.f / (base_p + p2);
            float mf = cf * (base_m + m2 * p2);
            g_FK[b][hh][i][sa][t]       = mf;
            g_FK[b][hh][i][sa][128 + t] = sqrtf(fmaxf(cf, eps));
        }
    }
}

// =====================================================================
// K4: w2 + softmax. Block per (b,h,i); 256 threads = 8 warps, each warp
// handles 16 j's; 256-d squared-distance per (i,j); then row softmax.
// =====================================================================
__global__ void attn_kernel(const int* __restrict__ b_seq, float* __restrict__ out_probs)
{
    int r = blockIdx.x;                 // (b,h,i)
    int b  = r >> 9;
    int hh = (r >> 7) & 3;
    int i  = r & 127;
    int tid = threadIdx.x;
    int w = tid >> 5, lane = tid & 31;

    __shared__ float fq[4][256];
    __shared__ int   seqj[128];
    __shared__ float sc[128];
    __shared__ float red[8];

    const float* fqg = &g_FQ[b][hh][i][0][0];
    for (int x = tid; x < 1024; x += 256) ((float*)fq)[x] = fqg[x];
    if (tid < 128) seqj[tid] = b_seq[b * 128 + tid];
    __syncthreads();

    int si = seqj[i];
    const float* fkbase = &g_FK[b][hh][0][si][0];   // + j*1024

    for (int jj = 0; jj < 16; ++jj) {
        int j = w * 16 + jj;
        int sb = seqj[j];
        const float* fk = fkbase + (size_t)j * 1024;
        float acc = 0.f;
#pragma unroll
        for (int q = 0; q < 8; ++q) {
            int d = lane + q * 32;
            float df = fq[sb][d] - fk[d];
            acc += df * df;
        }
#pragma unroll
        for (int o = 16; o; o >>= 1) acc += __shfl_xor_sync(0xFFFFFFFFu, acc, o);
        if (lane == 0) sc[j] = -acc * 0.08838834764831845f;  // -w2 / sqrt(128)
    }
    __syncthreads();

    // softmax over 128 (first 128 threads hold values)
    float x = (tid < 128) ? sc[tid] : -1e30f;
    float m = x;
#pragma unroll
    for (int o = 16; o; o >>= 1) m = fmaxf(m, __shfl_xor_sync(0xFFFFFFFFu, m, o));
    if (lane == 0) red[w] = m;
    __syncthreads();
    if (tid == 0) {
        float mm = red[0];
        for (int q = 1; q < 8; ++q) mm = fmaxf(mm, red[q]);
        red[0] = mm;
    }
    __syncthreads();
    float mx = red[0];
    float e = (tid < 128) ? expf(x - mx) : 0.f;
    float s = e;
#pragma unroll
    for (int o = 16; o; o >>= 1) s += __shfl_xor_sync(0xFFFFFFFFu, s, o);
    __syncthreads();              // everyone done reading red[0]
    if (lane == 0) red[w] = s;
    __syncthreads();
    if (tid == 0) {
        float ss = 0.f;
        for (int q = 0; q < 8; ++q) ss += red[q];
        red[0] = ss;
    }
    __syncthreads();
    float inv = 1.f / red[0];
    if (tid < 128)
        out_probs[(size_t)((b * 4 + hh) * 128 + i) * 128 + tid] = e * inv;
}

// =====================================================================
// K5: context GEMMs: mean_ctx = P @ v1 ; cov_ctx = (P*P) @ v2
// Block per (b,h,itile of 16); 128 threads (k). Outputs in [b,i,h*128+k].
// =====================================================================
__global__ void ctx_kernel(const float* __restrict__ probs)
{
    int blk = blockIdx.x;               // 64 blocks
    int b  = blk / 32;
    int hh = (blk / 8) & 3;
    int i0 = (blk & 7) * 16;
    int t = threadIdx.x;

    __shared__ float P[16][128];
    __shared__ float P2[16][128];
    const float* pb = probs + (size_t)((b * 4 + hh) * 128 + i0) * 128;
    for (int x = t; x < 16 * 128; x += 128) {
        float p = pb[x];
        ((float*)P)[x]  = p;
        ((float*)P2)[x] = p * p;
    }
    __syncthreads();

    float am[16] = {}, ac[16] = {};
    const float* v1 = &g_qkv[0][2][b][hh][0][0];
    const float* v2 = &g_qkv[1][2][b][hh][0][0];
    for (int j = 0; j < 128; ++j) {
        float x1 = v1[(size_t)j * 128 + t];
        float x2 = v2[(size_t)j * 128 + t];
#pragma unroll
        for (int ii = 0; ii < 16; ++ii) {
            am[ii] += P[ii][j]  * x1;
            ac[ii] += P2[ii][j] * x2;
        }
    }
#pragma unroll
    for (int ii = 0; ii < 16; ++ii) {
        g_ctx[0][b][i0 + ii][hh * 128 + t] = am[ii];
        g_ctx[1][b][i0 + ii][hh * 128 + t] = ac[ii];
    }
}

// =====================================================================
// K6: output GEMM + bias + residual.  tmp = ctx @ W.T + b + resid
// M=256 (b,i), N=512 (d), K=512 (d'). grid.z: 0=mean, 1=cov.
// =====================================================================
__global__ void outgemm_kernel(const float* __restrict__ mean_w, const float* __restrict__ mean_b,
                               const float* __restrict__ cov_w,  const float* __restrict__ cov_b,
                               const float* __restrict__ x_m,    const float* __restrict__ x_c)
{
    int z = blockIdx.z;
    const float* W     = z ? cov_w  : mean_w;
    const float* bias  = z ? cov_b  : mean_b;
    const float* resid = z ? x_c    : x_m;
    const float* A = &g_ctx[z][0][0][0];
    float* out = &g_tmp[z][0][0][0];

    const int m0 = blockIdx.x * 64;
    const int n0 = blockIdx.y * 64;
    const int tid = threadIdx.x;
    const int tx = tid & 15, ty = tid >> 4;

    __shared__ float As[16][64];
    __shared__ float Bs[16][68];
    float acc[4][4] = {};

    const int a_row = tid >> 2;
    const int a_k4  = (tid & 3) * 4;

    for (int kk = 0; kk < 512; kk += 16) {
        float4 av = *(const float4*)&A[(size_t)(m0 + a_row) * 512 + kk + a_k4];
        As[a_k4 + 0][a_row] = av.x;
        As[a_k4 + 1][a_row] = av.y;
        As[a_k4 + 2][a_row] = av.z;
        As[a_k4 + 3][a_row] = av.w;
        // B[kd][c] = W[(n0+c)*512 + kk+kd]
        float4 bv = *(const float4*)&W[(size_t)(n0 + a_row) * 512 + kk + a_k4];
        Bs[a_k4 + 0][a_row] = bv.x;
        Bs[a_k4 + 1][a_row] = bv.y;
        Bs[a_k4 + 2][a_row] = bv.z;
        Bs[a_k4 + 3][a_row] = bv.w;
        __syncthreads();
#pragma unroll
        for (int kd = 0; kd < 16; ++kd) {
            float a[4], bb[4];
#pragma unroll
            for (int rr = 0; rr < 4; ++rr) a[rr] = As[kd][ty * 4 + rr];
#pragma unroll
            for (int c = 0; c < 4; ++c) bb[c] = Bs[kd][tx * 4 + c];
#pragma unroll
            for (int rr = 0; rr < 4; ++rr)
#pragma unroll
                for (int c = 0; c < 4; ++c) acc[rr][c] += a[rr] * bb[c];
        }
        __syncthreads();
    }

#pragma unroll
    for (int rr = 0; rr < 4; ++rr) {
        int m = m0 + ty * 4 + rr;
#pragma unroll
        for (int c = 0; c < 4; ++c) {
            int d = n0 + tx * 4 + c;
            out[(size_t)m * 512 + d] = acc[rr][c] + bias[d] + resid[(size_t)m * 512 + d];
        }
    }
}

// =====================================================================
// K7: LayerNorm -> d_out (mean region then cov region)
// =====================================================================
__global__ void ln_kernel(const float* __restrict__ ln_w, const float* __restrict__ ln_b,
                          float* __restrict__ d_out_f)
{
    int blk = blockIdx.x;               // 512 blocks: z*256 + row
    int z = blk >> 8;
    int row = blk & 255;
    int tid = threadIdx.x;              // 256
    int w = tid >> 5, lane = tid & 31;
    __shared__ float red[8];

    const float* x = &g_tmp[z][0][0][0] + (size_t)row * 512;
    float a0 = x[tid], a1 = x[tid + 256];

    float s = a0 + a1;
#pragma unroll
    for (int o = 16; o; o >>= 1) s += __shfl_xor_sync(0xFFFFFFFFu, s, o);
    if (lane == 0) red[w] = s;
    __syncthreads();
    if (tid == 0) { float t2 = 0.f; for (int q = 0; q < 8; ++q) t2 += red[q]; red[0] = t2; }
    __syncthreads();
    float mean = red[0] * (1.f / 512.f);
    float d0 = a0 - mean, d1 = a1 - mean;
    float v = d0 * d0 + d1 * d1;
    __syncthreads();                    // everyone done reading red[0]
#pragma unroll
    for (int o = 16; o; o >>= 1) v += __shfl_xor_sync(0xFFFFFFFFu, v, o);
    if (lane == 0) red[w] = v;
    __syncthreads();
    if (tid == 0) { float t2 = 0.f; for (int q = 0; q < 8; ++q) t2 += red[q]; red[0] = t2; }
    __syncthreads();
    float var = red[0] * (1.f / 512.f);
    float inv = 1.f / sqrtf(var + 1e-12f);

    float* o = d_out_f + (size_t)z * 131072 + (size_t)row * 512;
    o[tid]       = d0 * inv * ln_w[tid]       + ln_b[tid];
    o[tid + 256] = d1 * inv * ln_w[tid + 256] + ln_b[tid + 256];
}

// =====================================================================
extern "C" void kernel_launch(void* const* d_in, const int* in_sizes, int n_in,
                              void* d_out, int out_size)
{
    const float* x_m    = (const float*)d_in[0];
    const float* x_c    = (const float*)d_in[1];
    const float* b_m    = (const float*)d_in[2];
    const float* b_c    = (const float*)d_in[3];
    const float* bb_m   = (const float*)d_in[4];
    const float* bb_c   = (const float*)d_in[5];
    const float* p_m    = (const float*)d_in[6];
    const float* p_c    = (const float*)d_in[7];
    const float* W_xm   = (const float*)d_in[8];
    const float* W_xc   = (const float*)d_in[9];
    const float* W_bm   = (const float*)d_in[10];
    const float* W_bc   = (const float*)d_in[11];
    const float* Wq1_w  = (const float*)d_in[12];
    const float* Wq1_b  = (const float*)d_in[13];
    const float* Wq2_w  = (const float*)d_in[14];
    const float* Wq2_b  = (const float*)d_in[15];
    const float* Wk1_w  = (const float*)d_in[16];
    const float* Wk1_b  = (const float*)d_in[17];
    const float* Wk2_w  = (const float*)d_in[18];
    const float* Wk2_b  = (const float*)d_in[19];
    const float* mean_w = (const float*)d_in[20];
    const float* mean_b = (const float*)d_in[21];
    const float* cov_w  = (const float*)d_in[22];
    const float* cov_b  = (const float*)d_in[23];
    const float* ln_w   = (const float*)d_in[24];
    const float* ln_b   = (const float*)d_in[25];
    const int*   b_seq  = (const int*)d_in[26];

    float* out = (float*)d_out;
    float* out_probs = out + 262144;   // [mean(131072) | cov(131072) | probs(131072)]

    dim3 gproj(4, 24);
    proj_kernel<<<gproj, 256>>>(x_m, b_m, W_xm, W_bm, 0);
    proj_kernel<<<gproj, 256>>>(x_c, b_c, W_xc, W_bc, 1);
    lin_bb_kernel<<<dim3(128, 2), 128>>>(bb_m, Wq1_w, Wq1_b, Wk1_w, Wk1_b);
    lin_p_kernel<<<dim3(1024, 2), 128>>>(p_m, Wq2_w, Wq2_b, Wk2_w, Wk2_b);
    build_fqfk<<<1024, 128>>>(bb_c, p_c, b_seq);
    attn_kernel<<<1024, 256>>>(b_seq, out_probs);
    ctx_kernel<<<64, 128>>>(out_probs);
    outgemm_kernel<<<dim3(4, 8, 2), 256>>>(mean_w, mean_b, cov_w, cov_b, x_m, x_c);
    ln_kernel<<<512, 256>>>(ln_w, ln_b, out);
}

// round 2
// speedup vs baseline: 1.6648x; 1.6648x over previous
#include <cuda_runtime.h>
#include <math.h>

#define BATCH 2
#define SEQ 128
#define NH 4
#define DKK 128
#define DD 512
#define NBB 4

// ---------------- scratch (device globals; no allocation allowed) ----------------
__device__ float g_qkv[2][3][BATCH][NH][SEQ][DKK]; // [fam(m/c)][q/k/v][b][h][n][k]
__device__ float g_bbQ[BATCH][NH][NBB][NBB][DKK];
__device__ float g_bbK[BATCH][NH][NBB][NBB][DKK];
__device__ float g_pq[BATCH][NH][SEQ][DKK];
__device__ float g_pk[BATCH][NH][SEQ][DKK];
__device__ float g_FQ[BATCH][NH][SEQ][NBB][2*DKK]; // [m(0..127) | sqrt(c)(128..255)]
__device__ float g_FK[BATCH][NH][SEQ][NBB][2*DKK];
__device__ float g_ctx[2][BATCH][SEQ][DD];          // [mean/cov][b][i][d]
__device__ float g_tmp[2][BATCH][SEQ][DD];          // pre-LN

// =====================================================================
// K1: fused projections, single launch.
// grid (8, 24, 2fam), 128 threads, 32x64 tile, K=512 x 2 pairs.
// out[fam][s][b][h][n][k] = sum_d X1*W1 + X2*W2   (+elu1 if fam==1)
// =====================================================================
__global__ void __launch_bounds__(128) proj_kernel(
    const float* __restrict__ x_m, const float* __restrict__ b_m,
    const float* __restrict__ Wxm, const float* __restrict__ Wbm,
    const float* __restrict__ x_c, const float* __restrict__ b_c,
    const float* __restrict__ Wxc, const float* __restrict__ Wbc)
{
    const int fam = blockIdx.z;
    const float* X1 = fam ? x_c : x_m;
    const float* X2 = fam ? b_c : b_m;
    const float* W1 = fam ? Wxc : Wxm;
    const float* W2 = fam ? Wbc : Wbm;

    const int m0 = blockIdx.x * 32;        // 0..255
    const int n0 = blockIdx.y * 64;        // 0..1535
    const int s_idx = n0 >> 9;
    const int cbase = n0 & 511;

    const int tid = threadIdx.x;           // 128
    const int tx = tid & 15, ty = tid >> 4;  // tx: 16 col-groups, ty: 8 row-groups

    __shared__ __align__(16) float As[16][36];
    __shared__ __align__(16) float Bs[16][64];

    float acc[4][4] = {};

    const int a_row = tid >> 2;            // 0..31
    const int a_k4  = (tid & 3) * 4;
    const int b_kd  = tid >> 4;            // 0..7
    const int b_c4  = (tid & 15) * 4;

    for (int pair = 0; pair < 2; ++pair) {
        const float* X = pair ? X2 : X1;
        const float* W = (pair ? W2 : W1) + (size_t)s_idx * 262144 + cbase;
        for (int kk = 0; kk < 512; kk += 16) {
            float4 av = *(const float4*)&X[(size_t)(m0 + a_row) * 512 + kk + a_k4];
            As[a_k4 + 0][a_row] = av.x;
            As[a_k4 + 1][a_row] = av.y;
            As[a_k4 + 2][a_row] = av.z;
            As[a_k4 + 3][a_row] = av.w;
            *(float4*)&Bs[b_kd][b_c4]     = *(const float4*)&W[(size_t)(kk + b_kd) * 512 + b_c4];
            *(float4*)&Bs[b_kd + 8][b_c4] = *(const float4*)&W[(size_t)(kk + b_kd + 8) * 512 + b_c4];
            __syncthreads();
#pragma unroll
            for (int kd = 0; kd < 16; ++kd) {
                float4 a4 = *(const float4*)&As[kd][ty * 4];
                float4 b4 = *(const float4*)&Bs[kd][tx * 4];
                float a[4] = {a4.x, a4.y, a4.z, a4.w};
                float bb[4] = {b4.x, b4.y, b4.z, b4.w};
#pragma unroll
                for (int r = 0; r < 4; ++r)
#pragma unroll
                    for (int c = 0; c < 4; ++c) acc[r][c] += a[r] * bb[c];
            }
            __syncthreads();
        }
    }

#pragma unroll
    for (int r = 0; r < 4; ++r) {
        int m = m0 + ty * 4 + r;
        int b = m >> 7, n = m & 127;
#pragma unroll
        for (int c = 0; c < 4; ++c) {
            int col = cbase + tx * 4 + c;
            int h = col >> 7, k = col & 127;
            float v = acc[r][c];
            if (fam == 1) v = (v > 0.f) ? (v + 1.f) : expf(v);  // elu(x)+1
            g_qkv[fam][s_idx][b][h][n][k] = v;
        }
    }
}

// =====================================================================
// K2: fused small linears as one GEMM. M = 1024(p rows) + 128(bb rows),
// N=128, K=128. grid (18, 2, 2sel), 256 threads, 64x64 tiles.
// =====================================================================
__global__ void __launch_bounds__(256) linqk_kernel(
    const float* __restrict__ p_m,  const float* __restrict__ bb_m,
    const float* __restrict__ Wq1_w, const float* __restrict__ Wq1_b,
    const float* __restrict__ Wq2_w, const float* __restrict__ Wq2_b,
    const float* __restrict__ Wk1_w, const float* __restrict__ Wk1_b,
    const float* __restrict__ Wk2_w, const float* __restrict__ Wk2_b)
{
    const int sel = blockIdx.z;
    const int m0 = blockIdx.x * 64;        // 0..1151
    const int n0 = blockIdx.y * 64;        // 0 or 64
    const bool bbreg = (m0 >= 1024);

    const float* W    = sel ? (bbreg ? Wk1_w : Wk2_w) : (bbreg ? Wq1_w : Wq2_w);
    const float* bias = sel ? (bbreg ? Wk1_b : Wk2_b) : (bbreg ? Wq1_b : Wq2_b);

    const int tid = threadIdx.x;           // 256
    const int tx = tid & 15, ty = tid >> 4;

    __shared__ __align__(16) float As[16][68];
    __shared__ __align__(16) float Bs[16][68];

    float acc[4][4] = {};

    const int a_row = tid >> 2;            // 0..63
    const int a_k4  = (tid & 3) * 4;

    for (int kk = 0; kk < 128; kk += 16) {
        // A row address (generic per-row mapping)
        {
            int r = m0 + a_row;
            const float* src;
            if (r < 1024) {
                int b = r >> 9, h = (r >> 7) & 3, n = r & 127;
                src = p_m + (size_t)(b * 128 + n) * 512 + h * 128 + kk + a_k4;
            } else {
                int r2 = r - 1024;
                int b = r2 >> 6, h = (r2 >> 4) & 3, nn = r2 & 15;
                src = bb_m + (size_t)(b * 16 + nn) * 512 + h * 128 + kk + a_k4;
            }
            float4 av = *(const float4*)src;
            As[a_k4 + 0][a_row] = av.x;
            As[a_k4 + 1][a_row] = av.y;
            As[a_k4 + 2][a_row] = av.z;
            As[a_k4 + 3][a_row] = av.w;
        }
        // B: Bs[kd][c] = W[(n0+c)*128 + kk+kd], loaded float4 along k
        {
            int c = tid >> 2, k4 = (tid & 3) * 4;
            float4 bv = *(const float4*)&W[(size_t)(n0 + c) * 128 + kk + k4];
            Bs[k4 + 0][c] = bv.x;
            Bs[k4 + 1][c] = bv.y;
            Bs[k4 + 2][c] = bv.z;
            Bs[k4 + 3][c] = bv.w;
        }
        __syncthreads();
#pragma unroll
        for (int kd = 0; kd < 16; ++kd) {
            float4 a4 = *(const float4*)&As[kd][ty * 4];
            float4 b4 = *(const float4*)&Bs[kd][tx * 4];
            float a[4] = {a4.x, a4.y, a4.z, a4.w};
            float bb[4] = {b4.x, b4.y, b4.z, b4.w};
#pragma unroll
            for (int r = 0; r < 4; ++r)
#pragma unroll
                for (int c = 0; c < 4; ++c) acc[r][c] += a[r] * bb[c];
        }
        __syncthreads();
    }

    float* outp = sel ? &g_pk[0][0][0][0] : &g_pq[0][0][0][0];
    float* outb = sel ? &g_bbK[0][0][0][0][0] : &g_bbQ[0][0][0][0][0];
#pragma unroll
    for (int r = 0; r < 4; ++r) {
        int rr = m0 + ty * 4 + r;
#pragma unroll
        for (int c = 0; c < 4; ++c) {
            int col = n0 + tx * 4 + c;
            float v = acc[r][c] + bias[col];
            if (rr < 1024) outp[(size_t)rr * 128 + col] = v;
            else           outb[(size_t)(rr - 1024) * 128 + col] = v;
        }
    }
}

// =====================================================================
// K3: tri-SAGP fusion -> FQ[b,h,i,sb,0:256], FK[b,h,j,sa,0:256]
// =====================================================================
__global__ void build_fqfk(const float* __restrict__ bb_c,
                           const float* __restrict__ p_c,
                           const int* __restrict__ b_seq)
{
    int r = blockIdx.x;                 // 0..1023 = (b,h,i)
    int b  = r >> 9;
    int hh = (r >> 7) & 3;
    int i  = r & 127;
    int t  = threadIdx.x;               // 128
    const float eps = 1e-24f;

    int si = b_seq[b * 128 + i];
    float c3 = p_c[(size_t)(b * 128 + i) * 512 + hh * 128 + t];
    float p3 = 1.f / fmaxf(c3, eps);

    // ---- Q side ----
    {
        float m1 = g_qkv[0][0][b][hh][i][t];
        float c1 = g_qkv[1][0][b][hh][i][t];
        float m3 = g_pq[b][hh][i][t];
        float p1 = 1.f / fmaxf(c1, eps);
        float base_m = m1 * p1 + m3 * p3;
        float base_p = p1 + p3;
#pragma unroll
        for (int sb = 0; sb < 4; ++sb) {
            float m2 = g_bbQ[b][hh][sb][si][t];
            float c2 = bb_c[(size_t)((b * 4 + sb) * 4 + si) * 512 + hh * 128 + t];
            float p2 = 1.f / fmaxf(c2, eps);
            float cf = 1.f / (base_p + p2);
            float mf = cf * (base_m + m2 * p2);
            g_FQ[b][hh][i][sb][t]       = mf;
            g_FQ[b][hh][i][sb][128 + t] = sqrtf(fmaxf(cf, eps));
        }
    }
    // ---- K side (j = i) ----
    {
        float m1 = g_qkv[0][1][b][hh][i][t];
        float c1 = g_qkv[1][1][b][hh][i][t];
        float m3 = g_pk[b][hh][i][t];
        float p1 = 1.f / fmaxf(c1, eps);
        float base_m = m1 * p1 + m3 * p3;
        float base_p = p1 + p3;
        int sj = si;
#pragma unroll
        for (int sa = 0; sa < 4; ++sa) {
            float m2 = g_bbK[b][hh][sj][sa][t];
            float c2 = bb_c[(size_t)((b * 4 + sj) * 4 + sa) * 512 + hh * 128 + t];
            float p2 = 1.f / fmaxf(c2, eps);
            float cf = 1.f / (base_p + p2);
            float mf = cf * (base_m + m2 * p2);
            g_FK[b][hh][i][sa][t]       = mf;
            g_FK[b][hh][i][sa][128 + t] = sqrtf(fmaxf(cf, eps));
        }
    }
}

// =====================================================================
// K4: fused w2 + softmax + context. Block per (b,h, 8-i tile): 128 blocks,
// 256 threads, ~111KB dynamic smem.
//   thread map (scores): jl = t>>4 (16 j per chunk), ln = t&15 (d partition)
//   thread d-coverage: d in {4*ln + 64*q + e}, interleaved (conflict-free f4)
// =====================================================================
__global__ void __launch_bounds__(256) attn2_kernel(const int* __restrict__ b_seq,
                                                    float* __restrict__ out_probs)
{
    extern __shared__ __align__(16) float sm[];
    float* fq   = sm;            // 8192 floats  [il][sb][256]
    float* fks  = sm + 8192;     // 16384 floats [jj][sa][256]
    float* sc   = sm + 24576;    // 1024 floats  [il][128]
    float* ctxm = sm + 25600;    // 1024
    float* ctxc = sm + 26624;    // 1024
    int*   seq_s = (int*)(sm + 27648);  // 128
    int*   sai   = seq_s + 128;         // 8

    const int blk = blockIdx.x;         // 128
    const int bh = blk >> 4;            // 0..7
    const int b = bh >> 2, h = bh & 3;
    const int i0 = (blk & 15) * 8;
    const int t = threadIdx.x;          // 256
    const int lane = t & 31;

    if (t < 128) seq_s[t] = b_seq[b * 128 + t];
    __syncthreads();
    if (t < 8) sai[t] = seq_s[i0 + t];

    // load fq tile: 8 i rows x 1024 floats
    {
        const float4* src = (const float4*)&g_FQ[b][h][i0][0][0];
        float4* dst = (float4*)fq;
        for (int x = t; x < 2048; x += 256) dst[x] = src[x];
    }
    __syncthreads();

    const int jl = t >> 4;      // 0..15
    const int ln = t & 15;
    const float4* fq4 = (const float4*)fq;
    float4* fks4 = (float4*)fks;
    const float4* FKg = (const float4*)&g_FK[b][h][0][0][0];
    const float scale = 0.08838834764831845f;   // 1/sqrt(128)

    for (int c = 0; c < 8; ++c) {
        // stage 16 j rows (16K floats)
        const float4* src = FKg + (size_t)c * 4096;
        for (int x = t; x < 4096; x += 256) fks4[x] = src[x];
        __syncthreads();

        // register cache of this thread's fk slices for all 4 sa
        float4 fk0[4], fk1[4], fk2[4], fk3[4];
        {
            int base = jl * 256;        // (jl*4+sa)*64 with sa=0
#pragma unroll
            for (int q = 0; q < 4; ++q) {
                fk0[q] = fks4[base +       q * 16 + ln];
                fk1[q] = fks4[base + 64  + q * 16 + ln];
                fk2[q] = fks4[base + 128 + q * 16 + ln];
                fk3[q] = fks4[base + 192 + q * 16 + ln];
            }
        }

        int j = c * 16 + jl;
        int sb = seq_s[j];
        float acc[8];
#pragma unroll
        for (int il = 0; il < 8; ++il) {
            const float4* fr = fq4 + (il * 4 + sb) * 64;
            int sa = sai[il];
            const float4* fk = (sa == 0) ? fk0 : (sa == 1) ? fk1 : (sa == 2) ? fk2 : fk3;
            float a = 0.f;
#pragma unroll
            for (int q = 0; q < 4; ++q) {
                float4 qv = fr[q * 16 + ln];
                float4 kv = fk[q];
                float d0 = qv.x - kv.x, d1 = qv.y - kv.y;
                float d2 = qv.z - kv.z, d3 = qv.w - kv.w;
                a += d0 * d0 + d1 * d1 + d2 * d2 + d3 * d3;
            }
            acc[il] = a;
        }
#pragma unroll
        for (int il = 0; il < 8; ++il) {
            float a = acc[il];
            a += __shfl_xor_sync(0xFFFFFFFFu, a, 1);
            a += __shfl_xor_sync(0xFFFFFFFFu, a, 2);
            a += __shfl_xor_sync(0xFFFFFFFFu, a, 4);
            a += __shfl_xor_sync(0xFFFFFFFFu, a, 8);
            if (ln == 0) sc[il * 128 + j] = -a * scale;
        }
        __syncthreads();
    }

    // softmax: warp w owns row il=w (8 warps)
    {
        int w = t >> 5;
        float4* row = (float4*)(sc + w * 128);
        float4 x4 = row[lane];
        float m = fmaxf(fmaxf(x4.x, x4.y), fmaxf(x4.z, x4.w));
#pragma unroll
        for (int o = 16; o; o >>= 1) m = fmaxf(m, __shfl_xor_sync(0xFFFFFFFFu, m, o));
        float e0 = expf(x4.x - m), e1 = expf(x4.y - m);
        float e2 = expf(x4.z - m), e3 = expf(x4.w - m);
        float s = e0 + e1 + e2 + e3;
#pragma unroll
        for (int o = 16; o; o >>= 1) s += __shfl_xor_sync(0xFFFFFFFFu, s, o);
        float inv = 1.f / s;
        float4 p4 = make_float4(e0 * inv, e1 * inv, e2 * inv, e3 * inv);
        row[lane] = p4;
        float4* op = (float4*)(out_probs + (size_t)(bh * 128 + i0 + w) * 128);
        op[lane] = p4;
    }
    __syncthreads();

    // context: mean = P @ v1, cov = P^2 @ v2 for the 8 rows
    {
        int k = t & 127, half = t >> 7;
        float am[8] = {}, ac[8] = {};
        const float* v1 = &g_qkv[0][2][b][h][0][0];
        const float* v2 = &g_qkv[1][2][b][h][0][0];
        int j0 = half * 64;
#pragma unroll 4
        for (int j = j0; j < j0 + 64; ++j) {
            float x1 = v1[(size_t)j * 128 + k];
            float x2 = v2[(size_t)j * 128 + k];
#pragma unroll
            for (int il = 0; il < 8; ++il) {
                float p = sc[il * 128 + j];
                am[il] += p * x1;
                ac[il] += p * p * x2;
            }
        }
        if (half == 0) {
#pragma unroll
            for (int il = 0; il < 8; ++il) {
                ctxm[il * 128 + k] = am[il];
                ctxc[il * 128 + k] = ac[il];
            }
        }
        __syncthreads();
        if (half == 1) {
#pragma unroll
            for (int il = 0; il < 8; ++il) {
                g_ctx[0][b][i0 + il][h * 128 + k] = am[il] + ctxm[il * 128 + k];
                g_ctx[1][b][i0 + il][h * 128 + k] = ac[il] + ctxc[il * 128 + k];
            }
        }
    }
}

// =====================================================================
// K5: output GEMM + bias + residual. grid (8, 8, 2z), 128 threads, 32x64.
// =====================================================================
__global__ void __launch_bounds__(128) outgemm_kernel(
    const float* __restrict__ mean_w, const float* __restrict__ mean_b,
    const float* __restrict__ cov_w,  const float* __restrict__ cov_b,
    const float* __restrict__ x_m,    const float* __restrict__ x_c)
{
    int z = blockIdx.z;
    const float* W     = z ? cov_w  : mean_w;
    const float* bias  = z ? cov_b  : mean_b;
    const float* resid = z ? x_c    : x_m;
    const float* A = &g_ctx[z][0][0][0];
    float* out = &g_tmp[z][0][0][0];

    const int m0 = blockIdx.x * 32;
    const int n0 = blockIdx.y * 64;
    const int tid = threadIdx.x;            // 128
    const int tx = tid & 15, ty = tid >> 4; // ty 0..7

    __shared__ __align__(16) float As[16][36];
    __shared__ __align__(16) float Bs[16][68];
    float acc[4][4] = {};

    const int a_row = tid >> 2;             // 0..31
    const int a_k4  = (tid & 3) * 4;

    for (int kk = 0; kk < 512; kk += 16) {
        float4 av = *(const float4*)&A[(size_t)(m0 + a_row) * 512 + kk + a_k4];
        As[a_k4 + 0][a_row] = av.x;
        As[a_k4 + 1][a_row] = av.y;
        As[a_k4 + 2][a_row] = av.z;
        As[a_k4 + 3][a_row] = av.w;
        // Bs[kd][c] = W[(n0+c)*512 + kk+kd] : 2 float4 per thread along k
        {
            int c = tid >> 2, k4 = (tid & 3) * 4;
            float4 bv = *(const float4*)&W[(size_t)(n0 + c) * 512 + kk + k4];
            Bs[k4 + 0][c] = bv.x; Bs[k4 + 1][c] = bv.y;
            Bs[k4 + 2][c] = bv.z; Bs[k4 + 3][c] = bv.w;
            int c2 = c + 32;
            float4 bw = *(const float4*)&W[(size_t)(n0 + c2) * 512 + kk + k4];
            Bs[k4 + 0][c2] = bw.x; Bs[k4 + 1][c2] = bw.y;
            Bs[k4 + 2][c2] = bw.z; Bs[k4 + 3][c2] = bw.w;
        }
        __syncthreads();
#pragma unroll
        for (int kd = 0; kd < 16; ++kd) {
            float4 a4 = *(const float4*)&As[kd][ty * 4];
            float4 b4 = *(const float4*)&Bs[kd][tx * 4];
            float a[4] = {a4.x, a4.y, a4.z, a4.w};
            float bb[4] = {b4.x, b4.y, b4.z, b4.w};
#pragma unroll
            for (int r = 0; r < 4; ++r)
#pragma unroll
                for (int c = 0; c < 4; ++c) acc[r][c] += a[r] * bb[c];
        }
        __syncthreads();
    }

#pragma unroll
    for (int r = 0; r < 4; ++r) {
        int m = m0 + ty * 4 + r;
#pragma unroll
        for (int c = 0; c < 4; ++c) {
            int d = n0 + tx * 4 + c;
            out[(size_t)m * 512 + d] = acc[r][c] + bias[d] + resid[(size_t)m * 512 + d];
        }
    }
}

// =====================================================================
// K6: LayerNorm -> d_out
// =====================================================================
__global__ void ln_kernel(const float* __restrict__ ln_w, const float* __restrict__ ln_b,
                          float* __restrict__ d_out_f)
{
    int blk = blockIdx.x;               // 512 blocks: z*256 + row
    int z = blk >> 8;
    int row = blk & 255;
    int tid = threadIdx.x;              // 256
    int w = tid >> 5, lane = tid & 31;
    __shared__ float red[8];

    const float* x = &g_tmp[z][0][0][0] + (size_t)row * 512;
    float a0 = x[tid], a1 = x[tid + 256];

    float s = a0 + a1;
#pragma unroll
    for (int o = 16; o; o >>= 1) s += __shfl_xor_sync(0xFFFFFFFFu, s, o);
    if (lane == 0) red[w] = s;
    __syncthreads();
    if (tid == 0) { float t2 = 0.f; for (int q = 0; q < 8; ++q) t2 += red[q]; red[0] = t2; }
    __syncthreads();
    float mean = red[0] * (1.f / 512.f);
    float d0 = a0 - mean, d1 = a1 - mean;
    float v = d0 * d0 + d1 * d1;
    __syncthreads();
#pragma unroll
    for (int o = 16; o; o >>= 1) v += __shfl_xor_sync(0xFFFFFFFFu, v, o);
    if (lane == 0) red[w] = v;
    __syncthreads();
    if (tid == 0) { float t2 = 0.f; for (int q = 0; q < 8; ++q) t2 += red[q]; red[0] = t2; }
    __syncthreads();
    float var = red[0] * (1.f / 512.f);
    float inv = 1.f / sqrtf(var + 1e-12f);

    float* o = d_out_f + (size_t)z * 131072 + (size_t)row * 512;
    o[tid]       = d0 * inv * ln_w[tid]       + ln_b[tid];
    o[tid + 256] = d1 * inv * ln_w[tid + 256] + ln_b[tid + 256];
}

// =====================================================================
extern "C" void kernel_launch(void* const* d_in, const int* in_sizes, int n_in,
                              void* d_out, int out_size)
{
    const float* x_m    = (const float*)d_in[0];
    const float* x_c    = (const float*)d_in[1];
    const float* b_m    = (const float*)d_in[2];
    const float* b_c    = (const float*)d_in[3];
    const float* bb_m   = (const float*)d_in[4];
    const float* bb_c   = (const float*)d_in[5];
    const float* p_m    = (const float*)d_in[6];
    const float* p_c    = (const float*)d_in[7];
    const float* W_xm   = (const float*)d_in[8];
    const float* W_xc   = (const float*)d_in[9];
    const float* W_bm   = (const float*)d_in[10];
    const float* W_bc   = (const float*)d_in[11];
    const float* Wq1_w  = (const float*)d_in[12];
    const float* Wq1_b  = (const float*)d_in[13];
    const float* Wq2_w  = (const float*)d_in[14];
    const float* Wq2_b  = (const float*)d_in[15];
    const float* Wk1_w  = (const float*)d_in[16];
    const float* Wk1_b  = (const float*)d_in[17];
    const float* Wk2_w  = (const float*)d_in[18];
    const float* Wk2_b  = (const float*)d_in[19];
    const float* mean_w = (const float*)d_in[20];
    const float* mean_b = (const float*)d_in[21];
    const float* cov_w  = (const float*)d_in[22];
    const float* cov_b  = (const float*)d_in[23];
    const float* ln_w   = (const float*)d_in[24];
    const float* ln_b   = (const float*)d_in[25];
    const int*   b_seq  = (const int*)d_in[26];

    float* out = (float*)d_out;
    float* out_probs = out + 262144;   // [mean(131072) | cov(131072) | probs(131072)]

    const int ATTN_SMEM = 27784 * 4;   // 111136 bytes
    cudaFuncSetAttribute(attn2_kernel, cudaFuncAttributeMaxDynamicSharedMemorySize, ATTN_SMEM);

    proj_kernel<<<dim3(8, 24, 2), 128>>>(x_m, b_m, W_xm, W_bm, x_c, b_c, W_xc, W_bc);
    linqk_kernel<<<dim3(18, 2, 2), 256>>>(p_m, bb_m,
                                          Wq1_w, Wq1_b, Wq2_w, Wq2_b,
                                          Wk1_w, Wk1_b, Wk2_w, Wk2_b);
    build_fqfk<<<1024, 128>>>(bb_c, p_c, b_seq);
    attn2_kernel<<<128, 256, ATTN_SMEM>>>(b_seq, out_probs);
    outgemm_kernel<<<dim3(8, 8, 2), 128>>>(mean_w, mean_b, cov_w, cov_b, x_m, x_c);
    ln_kernel<<<512, 256>>>(ln_w, ln_b, out);
}

// round 4
// speedup vs baseline: 1.7103x; 1.0273x over previous
#include <cuda_runtime.h>
#include <math.h>

#define BATCH 2
#define SEQ 128
#define NH 4
#define DKK 128
#define DD 512
#define NBB 4

// ---------------- scratch (device globals; no allocation allowed) ----------------
__device__ float g_qkv[2][3][BATCH][NH][SEQ][DKK]; // [fam(m/c)][q/k/v][b][h][n][k]
__device__ float g_bbQ[BATCH][NH][NBB][NBB][DKK];
__device__ float g_bbK[BATCH][NH][NBB][NBB][DKK];
__device__ float g_pq[BATCH][NH][SEQ][DKK];
__device__ float g_pk[BATCH][NH][SEQ][DKK];
__device__ float g_FQ[BATCH][NH][SEQ][NBB][2*DKK]; // [m(0..127) | sqrt(c)(128..255)]
__device__ float g_FK[BATCH][NH][SEQ][NBB][2*DKK];
__device__ float g_sqnq[BATCH][NH][SEQ][NBB];       // ||FQ[i,sb]||^2
__device__ float g_sqnk[BATCH][NH][SEQ][NBB];       // ||FK[j,sa]||^2
__device__ int   g_perm[BATCH][SEQ];                // sorted-by-bucket order
__device__ int   g_off[BATCH][NBB + 1];             // bucket offsets
__device__ float g_scs[BATCH*NH][SEQ][SEQ];         // sorted scores / probs
__device__ float g_ctx[2][BATCH][SEQ][DD];          // [mean/cov][b][i][d]
__device__ float g_tmp[2][BATCH][SEQ][DD];          // pre-LN

// =====================================================================
// K0: counting sort of sequence positions by bucket id. grid=2, 128 thr.
// =====================================================================
__global__ void perm_kernel(const int* __restrict__ b_seq)
{
    int b = blockIdx.x, t = threadIdx.x;
    __shared__ int keys[128];
    __shared__ int cnt[4];
    __shared__ int off[5];
    keys[t] = b_seq[b * 128 + t];
    if (t < 4) cnt[t] = 0;
    __syncthreads();
    int key = keys[t];
    int rank = 0;
    for (int u = 0; u < t; ++u) rank += (keys[u] == key);
    atomicAdd(&cnt[key], 1);
    __syncthreads();
    if (t == 0) {
        off[0] = 0;
        for (int q = 0; q < 4; ++q) off[q + 1] = off[q] + cnt[q];
    }
    __syncthreads();
    g_perm[b][off[key] + rank] = t;
    if (t < 5) g_off[b][t] = off[t];
}

// =====================================================================
// K1: fused projections, single launch.
// grid (8, 24, 2fam), 128 threads, 32x64 tile, K=512 x 2 pairs.
// =====================================================================
__global__ void __launch_bounds__(128) proj_kernel(
    const float* __restrict__ x_m, const float* __restrict__ b_m,
    const float* __restrict__ Wxm, const float* __restrict__ Wbm,
    const float* __restrict__ x_c, const float* __restrict__ b_c,
    const float* __restrict__ Wxc, const float* __restrict__ Wbc)
{
    const int fam = blockIdx.z;
    const float* X1 = fam ? x_c : x_m;
    const float* X2 = fam ? b_c : b_m;
    const float* W1 = fam ? Wxc : Wxm;
    const float* W2 = fam ? Wbc : Wbm;

    const int m0 = blockIdx.x * 32;
    const int n0 = blockIdx.y * 64;
    const int s_idx = n0 >> 9;
    const int cbase = n0 & 511;

    const int tid = threadIdx.x;
    const int tx = tid & 15, ty = tid >> 4;

    __shared__ __align__(16) float As[16][36];
    __shared__ __align__(16) float Bs[16][64];

    float acc[4][4] = {};

    const int a_row = tid >> 2;
    const int a_k4  = (tid & 3) * 4;
    const int b_kd  = tid >> 4;
    const int b_c4  = (tid & 15) * 4;

    for (int pair = 0; pair < 2; ++pair) {
        const float* X = pair ? X2 : X1;
        const float* W = (pair ? W2 : W1) + (size_t)s_idx * 262144 + cbase;
        for (int kk = 0; kk < 512; kk += 16) {
            float4 av = *(const float4*)&X[(size_t)(m0 + a_row) * 512 + kk + a_k4];
            As[a_k4 + 0][a_row] = av.x;
            As[a_k4 + 1][a_row] = av.y;
            As[a_k4 + 2][a_row] = av.z;
            As[a_k4 + 3][a_row] = av.w;
            *(float4*)&Bs[b_kd][b_c4]     = *(const float4*)&W[(size_t)(kk + b_kd) * 512 + b_c4];
            *(float4*)&Bs[b_kd + 8][b_c4] = *(const float4*)&W[(size_t)(kk + b_kd + 8) * 512 + b_c4];
            __syncthreads();
#pragma unroll
            for (int kd = 0; kd < 16; ++kd) {
                float4 a4 = *(const float4*)&As[kd][ty * 4];
                float4 b4 = *(const float4*)&Bs[kd][tx * 4];
                float a[4] = {a4.x, a4.y, a4.z, a4.w};
                float bb[4] = {b4.x, b4.y, b4.z, b4.w};
#pragma unroll
                for (int r = 0; r < 4; ++r)
#pragma unroll
                    for (int c = 0; c < 4; ++c) acc[r][c] += a[r] * bb[c];
            }
            __syncthreads();
        }
    }

#pragma unroll
    for (int r = 0; r < 4; ++r) {
        int m = m0 + ty * 4 + r;
        int b = m >> 7, n = m & 127;
#pragma unroll
        for (int c = 0; c < 4; ++c) {
            int col = cbase + tx * 4 + c;
            int h = col >> 7, k = col & 127;
            float v = acc[r][c];
            if (fam == 1) v = (v > 0.f) ? (v + 1.f) : expf(v);  // elu(x)+1
            g_qkv[fam][s_idx][b][h][n][k] = v;
        }
    }
}

// =====================================================================
// K2: fused small linears as one GEMM. M = 1024(p rows) + 128(bb rows).
// =====================================================================
__global__ void __launch_bounds__(256) linqk_kernel(
    const float* __restrict__ p_m,  const float* __restrict__ bb_m,
    const float* __restrict__ Wq1_w, const float* __restrict__ Wq1_b,
    const float* __restrict__ Wq2_w, const float* __restrict__ Wq2_b,
    const float* __restrict__ Wk1_w, const float* __restrict__ Wk1_b,
    const float* __restrict__ Wk2_w, const float* __restrict__ Wk2_b)
{
    const int sel = blockIdx.z;
    const int m0 = blockIdx.x * 64;
    const int n0 = blockIdx.y * 64;
    const bool bbreg = (m0 >= 1024);

    const float* W    = sel ? (bbreg ? Wk1_w : Wk2_w) : (bbreg ? Wq1_w : Wq2_w);
    const float* bias = sel ? (bbreg ? Wk1_b : Wk2_b) : (bbreg ? Wq1_b : Wq2_b);

    const int tid = threadIdx.x;
    const int tx = tid & 15, ty = tid >> 4;

    __shared__ __align__(16) float As[16][68];
    __shared__ __align__(16) float Bs[16][68];

    float acc[4][4] = {};

    const int a_row = tid >> 2;
    const int a_k4  = (tid & 3) * 4;

    for (int kk = 0; kk < 128; kk += 16) {
        {
            int r = m0 + a_row;
            const float* src;
            if (r < 1024) {
                int b = r >> 9, h = (r >> 7) & 3, n = r & 127;
                src = p_m + (size_t)(b * 128 + n) * 512 + h * 128 + kk + a_k4;
            } else {
                int r2 = r - 1024;
                int b = r2 >> 6, h = (r2 >> 4) & 3, nn = r2 & 15;
                src = bb_m + (size_t)(b * 16 + nn) * 512 + h * 128 + kk + a_k4;
            }
            float4 av = *(const float4*)src;
            As[a_k4 + 0][a_row] = av.x;
            As[a_k4 + 1][a_row] = av.y;
            As[a_k4 + 2][a_row] = av.z;
            As[a_k4 + 3][a_row] = av.w;
        }
        {
            int c = tid >> 2, k4 = (tid & 3) * 4;
            float4 bv = *(const float4*)&W[(size_t)(n0 + c) * 128 + kk + k4];
            Bs[k4 + 0][c] = bv.x;
            Bs[k4 + 1][c] = bv.y;
            Bs[k4 + 2][c] = bv.z;
            Bs[k4 + 3][c] = bv.w;
        }
        __syncthreads();
#pragma unroll
        for (int kd = 0; kd < 16; ++kd) {
            float4 a4 = *(const float4*)&As[kd][ty * 4];
            float4 b4 = *(const float4*)&Bs[kd][tx * 4];
            float a[4] = {a4.x, a4.y, a4.z, a4.w};
            float bb[4] = {b4.x, b4.y, b4.z, b4.w};
#pragma unroll
            for (int r = 0; r < 4; ++r)
#pragma unroll
                for (int c = 0; c < 4; ++c) acc[r][c] += a[r] * bb[c];
        }
        __syncthreads();
    }

    float* outp = sel ? &g_pk[0][0][0][0] : &g_pq[0][0][0][0];
    float* outb = sel ? &g_bbK[0][0][0][0][0] : &g_bbQ[0][0][0][0][0];
#pragma unroll
    for (int r = 0; r < 4; ++r) {
        int rr = m0 + ty * 4 + r;
#pragma unroll
        for (int c = 0; c < 4; ++c) {
            int col = n0 + tx * 4 + c;
            float v = acc[r][c] + bias[col];
            if (rr < 1024) outp[(size_t)rr * 128 + col] = v;
            else           outb[(size_t)(rr - 1024) * 128 + col] = v;
        }
    }
}

// =====================================================================
// K3: tri-SAGP fusion -> FQ/FK + squared norms.
// =====================================================================
__global__ void __launch_bounds__(128) build_fqfk(const float* __restrict__ bb_c,
                                                  const float* __restrict__ p_c,
                                                  const int* __restrict__ b_seq)
{
    int r = blockIdx.x;                 // 0..1023 = (b,h,i)
    int b  = r >> 9;
    int hh = (r >> 7) & 3;
    int i  = r & 127;
    int t  = threadIdx.x;               // 128
    int w = t >> 5, lane = t & 31;
    const float eps = 1e-24f;

    __shared__ float rq[4][4];          // [warp][sb]
    __shared__ float rk[4][4];

    int si = b_seq[b * 128 + i];
    float c3 = p_c[(size_t)(b * 128 + i) * 512 + hh * 128 + t];
    float p3 = 1.f / fmaxf(c3, eps);

    float nq[4], nk[4];

    // ---- Q side ----
    {
        float m1 = g_qkv[0][0][b][hh][i][t];
        float c1 = g_qkv[1][0][b][hh][i][t];
        float m3 = g_pq[b][hh][i][t];
        float p1 = 1.f / fmaxf(c1, eps);
        float base_m = m1 * p1 + m3 * p3;
        float base_p = p1 + p3;
#pragma unroll
        for (int sb = 0; sb < 4; ++sb) {
            float m2 = g_bbQ[b][hh][sb][si][t];
            float c2 = bb_c[(size_t)((b * 4 + sb) * 4 + si) * 512 + hh * 128 + t];
            float p2 = 1.f / fmaxf(c2, eps);
            float cf = 1.f / (base_p + p2);
            float mf = cf * (base_m + m2 * p2);
            float cfc = fmaxf(cf, eps);
            g_FQ[b][hh][i][sb][t]       = mf;
            g_FQ[b][hh][i][sb][128 + t] = sqrtf(cfc);
            nq[sb] = mf * mf + cfc;
        }
    }
    // ---- K side (j = i) ----
    {
        float m1 = g_qkv[0][1][b][hh][i][t];
        float c1 = g_qkv[1][1][b][hh][i][t];
        float m3 = g_pk[b][hh][i][t];
        float p1 = 1.f / fmaxf(c1, eps);
        float base_m = m1 * p1 + m3 * p3;
        float base_p = p1 + p3;
        int sj = si;
#pragma unroll
        for (int sa = 0; sa < 4; ++sa) {
            float m2 = g_bbK[b][hh][sj][sa][t];
            float c2 = bb_c[(size_t)((b * 4 + sj) * 4 + sa) * 512 + hh * 128 + t];
            float p2 = 1.f / fmaxf(c2, eps);
            float cf = 1.f / (base_p + p2);
            float mf = cf * (base_m + m2 * p2);
            float cfc = fmaxf(cf, eps);
            g_FK[b][hh][i][sa][t]       = mf;
            g_FK[b][hh][i][sa][128 + t] = sqrtf(cfc);
            nk[sa] = mf * mf + cfc;
        }
    }

    // reduce the 8 norms over 128 threads
#pragma unroll
    for (int sb = 0; sb < 4; ++sb) {
        float a = nq[sb], c = nk[sb];
#pragma unroll
        for (int o = 16; o; o >>= 1) {
            a += __shfl_xor_sync(0xFFFFFFFFu, a, o);
            c += __shfl_xor_sync(0xFFFFFFFFu, c, o);
        }
        if (lane == 0) { rq[w][sb] = a; rk[w][sb] = c; }
    }
    __syncthreads();
    if (t < 4)
        g_sqnq[b][hh][i][t] = rq[0][t] + rq[1][t] + rq[2][t] + rq[3][t];
    else if (t < 8) {
        int sb = t - 4;
        g_sqnk[b][hh][i][sb] = rk[0][sb] + rk[1][sb] + rk[2][sb] + rk[3][sb];
    }
}

// =====================================================================
// K4a: bucketed score GEMM. grid (16 subtiles, 16 (si,sb), 8 bh), 256 thr.
// Within a bucket pair, scores = -(|FQ|^2 + |FK|^2 - 2 FQ.FK)*scale.
// =====================================================================
__global__ void __launch_bounds__(256) scores_kernel()
{
    const int bh = blockIdx.z;
    const int b = bh >> 2, h = bh & 3;
    const int si = blockIdx.y >> 2, sb = blockIdx.y & 3;
    const int ti = (blockIdx.x >> 2) * 32, tj = (blockIdx.x & 3) * 32;

    const int rbase = g_off[b][si], rcnt = g_off[b][si + 1] - rbase;
    const int cbase = g_off[b][sb], ccnt = g_off[b][sb + 1] - cbase;
    if (ti >= rcnt || tj >= ccnt) return;

    const int t = threadIdx.x;
    const int tx = t & 15, ty = t >> 4;

    __shared__ __align__(16) float As[32][33];
    __shared__ __align__(16) float Bs[32][33];
    __shared__ int rid[32], cid[32];
    __shared__ float sqr[32], sqc[32];

    if (t < 32) {
        int pr = ti + t; if (pr > rcnt - 1) pr = rcnt - 1;
        int id = g_perm[b][rbase + pr];
        rid[t] = id;
        sqr[t] = g_sqnq[b][h][id][sb];
    } else if (t < 64) {
        int u = t - 32;
        int pc = tj + u; if (pc > ccnt - 1) pc = ccnt - 1;
        int id = g_perm[b][cbase + pc];
        cid[u] = id;
        sqc[u] = g_sqnk[b][h][id][si];
    }
    __syncthreads();

    float acc[2][2] = {};
    const int lr = t >> 3;
    const int d4 = (t & 7) * 4;

    for (int kk = 0; kk < 256; kk += 32) {
        float4 av = *(const float4*)&g_FQ[b][h][rid[lr]][sb][kk + d4];
        As[d4 + 0][lr] = av.x; As[d4 + 1][lr] = av.y;
        As[d4 + 2][lr] = av.z; As[d4 + 3][lr] = av.w;
        float4 bv = *(const float4*)&g_FK[b][h][cid[lr]][si][kk + d4];
        Bs[d4 + 0][lr] = bv.x; Bs[d4 + 1][lr] = bv.y;
        Bs[d4 + 2][lr] = bv.z; Bs[d4 + 3][lr] = bv.w;
        __syncthreads();
#pragma unroll
        for (int d = 0; d < 32; ++d) {
            float a0 = As[d][ty * 2], a1 = As[d][ty * 2 + 1];
            float b0 = Bs[d][tx * 2], b1 = Bs[d][tx * 2 + 1];
            acc[0][0] += a0 * b0; acc[0][1] += a0 * b1;
            acc[1][0] += a1 * b0; acc[1][1] += a1 * b1;
        }
        __syncthreads();
    }

    const float scale = 0.08838834764831845f;   // 1/sqrt(128)
#pragma unroll
    for (int r = 0; r < 2; ++r) {
        int pr = ti + ty * 2 + r;
        if (pr >= rcnt) continue;
#pragma unroll
        for (int c = 0; c < 2; ++c) {
            int pc = tj + tx * 2 + c;
            if (pc >= ccnt) continue;
            float w2v = sqr[ty * 2 + r] + sqc[tx * 2 + c] - 2.f * acc[r][c];
            g_scs[bh][rbase + pr][cbase + pc] = -w2v * scale;
        }
    }
}

// =====================================================================
// K4b: softmax + probs scatter + context. grid 128, 256 thr.
// =====================================================================
__global__ void __launch_bounds__(256) softmax_ctx_kernel(float* __restrict__ out_probs)
{
    const int blk = blockIdx.x;
    const int bh = blk >> 4;
    const int b = bh >> 2, h = bh & 3;
    const int i0 = (blk & 15) * 8;
    const int t = threadIdx.x;
    const int lane = t & 31;

    __shared__ float sc[8 * 128];
    __shared__ int perm_s[128];
    __shared__ float ctxm[1024], ctxc[1024];

    if (t < 128) perm_s[t] = g_perm[b][t];
    {
        const float4* src = (const float4*)&g_scs[bh][i0][0];
        ((float4*)sc)[t] = src[t];
    }
    __syncthreads();

    // softmax: warp w owns sorted row pi = i0 + w
    {
        int w = t >> 5;
        float4* row = (float4*)(sc + w * 128);
        float4 x4 = row[lane];
        float m = fmaxf(fmaxf(x4.x, x4.y), fmaxf(x4.z, x4.w));
#pragma unroll
        for (int o = 16; o; o >>= 1) m = fmaxf(m, __shfl_xor_sync(0xFFFFFFFFu, m, o));
        float e0 = expf(x4.x - m), e1 = expf(x4.y - m);
        float e2 = expf(x4.z - m), e3 = expf(x4.w - m);
        float s = e0 + e1 + e2 + e3;
#pragma unroll
        for (int o = 16; o; o >>= 1) s += __shfl_xor_sync(0xFFFFFFFFu, s, o);
        float inv = 1.f / s;
        float4 p4 = make_float4(e0 * inv, e1 * inv, e2 * inv, e3 * inv);
        row[lane] = p4;
        // scatter probs into true (i, j) layout
        int i = perm_s[i0 + w];
        float* op = out_probs + (size_t)(bh * 128 + i) * 128;
        op[perm_s[4 * lane + 0]] = p4.x;
        op[perm_s[4 * lane + 1]] = p4.y;
        op[perm_s[4 * lane + 2]] = p4.z;
        op[perm_s[4 * lane + 3]] = p4.w;
    }
    __syncthreads();

    // context: mean = P @ v1, cov = P^2 @ v2 (cols gathered by perm)
    {
        int k = t & 127, half = t >> 7;
        float am[8] = {}, ac[8] = {};
        const float* v1 = &g_qkv[0][2][b][h][0][0];
        const float* v2 = &g_qkv[1][2][b][h][0][0];
        int j0 = half * 64;
#pragma unroll 4
        for (int pj = j0; pj < j0 + 64; ++pj) {
            int jv = perm_s[pj];
            float x1 = v1[(size_t)jv * 128 + k];
            float x2 = v2[(size_t)jv * 128 + k];
#pragma unroll
            for (int il = 0; il < 8; ++il) {
                float p = sc[il * 128 + pj];
                am[il] += p * x1;
                ac[il] += p * p * x2;
            }
        }
        if (half == 0) {
#pragma unroll
            for (int il = 0; il < 8; ++il) {
                ctxm[il * 128 + k] = am[il];
                ctxc[il * 128 + k] = ac[il];
            }
        }
        __syncthreads();
        if (half == 1) {
#pragma unroll
            for (int il = 0; il < 8; ++il) {
                int i = perm_s[i0 + il];
                g_ctx[0][b][i][h * 128 + k] = am[il] + ctxm[il * 128 + k];
                g_ctx[1][b][i][h * 128 + k] = ac[il] + ctxc[il * 128 + k];
            }
        }
    }
}

// =====================================================================
// K5: output GEMM + bias + residual. grid (8, 8, 2z), 128 threads, 32x64.
// =====================================================================
__global__ void __launch_bounds__(128) outgemm_kernel(
    const float* __restrict__ mean_w, const float* __restrict__ mean_b,
    const float* __restrict__ cov_w,  const float* __restrict__ cov_b,
    const float* __restrict__ x_m,    const float* __restrict__ x_c)
{
    int z = blockIdx.z;
    const float* W     = z ? cov_w  : mean_w;
    const float* bias  = z ? cov_b  : mean_b;
    const float* resid = z ? x_c    : x_m;
    const float* A = &g_ctx[z][0][0][0];
    float* out = &g_tmp[z][0][0][0];

    const int m0 = blockIdx.x * 32;
    const int n0 = blockIdx.y * 64;
    const int tid = threadIdx.x;
    const int tx = tid & 15, ty = tid >> 4;

    __shared__ __align__(16) float As[16][36];
    __shared__ __align__(16) float Bs[16][68];
    float acc[4][4] = {};

    const int a_row = tid >> 2;
    const int a_k4  = (tid & 3) * 4;

    for (int kk = 0; kk < 512; kk += 16) {
        float4 av = *(const float4*)&A[(size_t)(m0 + a_row) * 512 + kk + a_k4];
        As[a_k4 + 0][a_row] = av.x;
        As[a_k4 + 1][a_row] = av.y;
        As[a_k4 + 2][a_row] = av.z;
        As[a_k4 + 3][a_row] = av.w;
        {
            int c = tid >> 2, k4 = (tid & 3) * 4;
            float4 bv = *(const float4*)&W[(size_t)(n0 + c) * 512 + kk + k4];
            Bs[k4 + 0][c] = bv.x; Bs[k4 + 1][c] = bv.y;
            Bs[k4 + 2][c] = bv.z; Bs[k4 + 3][c] = bv.w;
            int c2 = c + 32;
            float4 bw = *(const float4*)&W[(size_t)(n0 + c2) * 512 + kk + k4];
            Bs[k4 + 0][c2] = bw.x; Bs[k4 + 1][c2] = bw.y;
            Bs[k4 + 2][c2] = bw.z; Bs[k4 + 3][c2] = bw.w;
        }
        __syncthreads();
#pragma unroll
        for (int kd = 0; kd < 16; ++kd) {
            float4 a4 = *(const float4*)&As[kd][ty * 4];
            float4 b4 = *(const float4*)&Bs[kd][tx * 4];
            float a[4] = {a4.x, a4.y, a4.z, a4.w};
            float bb[4] = {b4.x, b4.y, b4.z, b4.w};
#pragma unroll
            for (int r = 0; r < 4; ++r)
#pragma unroll
                for (int c = 0; c < 4; ++c) acc[r][c] += a[r] * bb[c];
        }
        __syncthreads();
    }

#pragma unroll
    for (int r = 0; r < 4; ++r) {
        int m = m0 + ty * 4 + r;
#pragma unroll
        for (int c = 0; c < 4; ++c) {
            int d = n0 + tx * 4 + c;
            out[(size_t)m * 512 + d] = acc[r][c] + bias[d] + resid[(size_t)m * 512 + d];
        }
    }
}

// =====================================================================
// K6: LayerNorm -> d_out
// =====================================================================
__global__ void ln_kernel(const float* __restrict__ ln_w, const float* __restrict__ ln_b,
                          float* __restrict__ d_out_f)
{
    int blk = blockIdx.x;
    int z = blk >> 8;
    int row = blk & 255;
    int tid = threadIdx.x;
    int w = tid >> 5, lane = tid & 31;
    __shared__ float red[8];

    const float* x = &g_tmp[z][0][0][0] + (size_t)row * 512;
    float a0 = x[tid], a1 = x[tid + 256];

    float s = a0 + a1;
#pragma unroll
    for (int o = 16; o; o >>= 1) s += __shfl_xor_sync(0xFFFFFFFFu, s, o);
    if (lane == 0) red[w] = s;
    __syncthreads();
    if (tid == 0) { float t2 = 0.f; for (int q = 0; q < 8; ++q) t2 += red[q]; red[0] = t2; }
    __syncthreads();
    float mean = red[0] * (1.f / 512.f);
    float d0 = a0 - mean, d1 = a1 - mean;
    float v = d0 * d0 + d1 * d1;
    __syncthreads();
#pragma unroll
    for (int o = 16; o; o >>= 1) v += __shfl_xor_sync(0xFFFFFFFFu, v, o);
    if (lane == 0) red[w] = v;
    __syncthreads();
    if (tid == 0) { float t2 = 0.f; for (int q = 0; q < 8; ++q) t2 += red[q]; red[0] = t2; }
    __syncthreads();
    float var = red[0] * (1.f / 512.f);
    float inv = 1.f / sqrtf(var + 1e-12f);

    float* o = d_out_f + (size_t)z * 131072 + (size_t)row * 512;
    o[tid]       = d0 * inv * ln_w[tid]       + ln_b[tid];
    o[tid + 256] = d1 * inv * ln_w[tid + 256] + ln_b[tid + 256];
}

// =====================================================================
extern "C" void kernel_launch(void* const* d_in, const int* in_sizes, int n_in,
                              void* d_out, int out_size)
{
    const float* x_m    = (const float*)d_in[0];
    const float* x_c    = (const float*)d_in[1];
    const float* b_m    = (const float*)d_in[2];
    const float* b_c    = (const float*)d_in[3];
    const float* bb_m   = (const float*)d_in[4];
    const float* bb_c   = (const float*)d_in[5];
    const float* p_m    = (const float*)d_in[6];
    const float* p_c    = (const float*)d_in[7];
    const float* W_xm   = (const float*)d_in[8];
    const float* W_xc   = (const float*)d_in[9];
    const float* W_bm   = (const float*)d_in[10];
    const float* W_bc   = (const float*)d_in[11];
    const float* Wq1_w  = (const float*)d_in[12];
    const float* Wq1_b  = (const float*)d_in[13];
    const float* Wq2_w  = (const float*)d_in[14];
    const float* Wq2_b  = (const float*)d_in[15];
    const float* Wk1_w  = (const float*)d_in[16];
    const float* Wk1_b  = (const float*)d_in[17];
    const float* Wk2_w  = (const float*)d_in[18];
    const float* Wk2_b  = (const float*)d_in[19];
    const float* mean_w = (const float*)d_in[20];
    const float* mean_b = (const float*)d_in[21];
    const float* cov_w  = (const float*)d_in[22];
    const float* cov_b  = (const float*)d_in[23];
    const float* ln_w   = (const float*)d_in[24];
    const float* ln_b   = (const float*)d_in[25];
    const int*   b_seq  = (const int*)d_in[26];

    float* out = (float*)d_out;
    float* out_probs = out + 262144;   // [mean | cov | probs]

    perm_kernel<<<2, 128>>>(b_seq);
    proj_kernel<<<dim3(8, 24, 2), 128>>>(x_m, b_m, W_xm, W_bm, x_c, b_c, W_xc, W_bc);
    linqk_kernel<<<dim3(18, 2, 2), 256>>>(p_m, bb_m,
                                          Wq1_w, Wq1_b, Wq2_w, Wq2_b,
                                          Wk1_w, Wk1_b, Wk2_w, Wk2_b);
    build_fqfk<<<1024, 128>>>(bb_c, p_c, b_seq);
    scores_kernel<<<dim3(16, 16, 8), 256>>>();
    softmax_ctx_kernel<<<128, 256>>>(out_probs);
    outgemm_kernel<<<dim3(8, 8, 2), 128>>>(mean_w, mean_b, cov_w, cov_b, x_m, x_c);
    ln_kernel<<<512, 256>>>(ln_w, ln_b, out);
}

// round 5
// speedup vs baseline: 1.7143x; 1.0024x over previous
#include <cuda_runtime.h>
#include <cuda_bf16.h>
#include <mma.h>
#include <math.h>

using namespace nvcuda;

#define BATCH 2
#define SEQ 128
#define NH 4
#define DKK 128
#define DD 512
#define NBB 4

// ---------------- scratch (device globals; no allocation allowed) ----------------
__device__ float g_qkv[2][3][BATCH][NH][SEQ][DKK]; // [fam(m/c)][q/k/v][b][h][n][k]
__device__ float g_bbQ[BATCH][NH][NBB][NBB][DKK];
__device__ float g_bbK[BATCH][NH][NBB][NBB][DKK];
__device__ float g_pq[BATCH][NH][SEQ][DKK];
__device__ float g_pk[BATCH][NH][SEQ][DKK];
__device__ float g_FQ[BATCH][NH][SEQ][NBB][2*DKK]; // [m(0..127) | sqrt(c)(128..255)]
__device__ float g_FK[BATCH][NH][SEQ][NBB][2*DKK];
__device__ float g_sqnq[BATCH][NH][SEQ][NBB];       // ||FQ[i,sb]||^2
__device__ float g_sqnk[BATCH][NH][SEQ][NBB];       // ||FK[j,sa]||^2
__device__ int   g_perm[BATCH][SEQ];                // sorted-by-bucket order
__device__ int   g_off[BATCH][NBB + 1];             // bucket offsets
__device__ float g_scs[BATCH*NH][SEQ][SEQ];         // sorted scores / probs
__device__ float g_ctx[2][BATCH][SEQ][DD];          // [mean/cov][b][i][d]
__device__ float g_tmp[2][BATCH][SEQ][DD];          // pre-LN

// =====================================================================
// K0: counting sort of sequence positions by bucket id. grid=2, 128 thr.
// =====================================================================
__global__ void perm_kernel(const int* __restrict__ b_seq)
{
    int b = blockIdx.x, t = threadIdx.x;
    __shared__ int keys[128];
    __shared__ int cnt[4];
    __shared__ int off[5];
    keys[t] = b_seq[b * 128 + t];
    if (t < 4) cnt[t] = 0;
    __syncthreads();
    int key = keys[t];
    int rank = 0;
    for (int u = 0; u < t; ++u) rank += (keys[u] == key);
    atomicAdd(&cnt[key], 1);
    __syncthreads();
    if (t == 0) {
        off[0] = 0;
        for (int q = 0; q < 4; ++q) off[q + 1] = off[q] + cnt[q];
    }
    __syncthreads();
    g_perm[b][off[key] + rank] = t;
    if (t < 5) g_off[b][t] = off[t];
}

// =====================================================================
// K1: tensor-core fused projections (bf16 3-pass split, fp32-accurate).
// grid (2, 24, 2fam), 256 threads. Block tile 128(M) x 64(N), K=512 x 2.
// out[fam][s][b][h][n][k] = sum_d X1*W1 + X2*W2   (+elu1 if fam==1)
// =====================================================================
__global__ void __launch_bounds__(256) proj_tc_kernel(
    const float* __restrict__ x_m, const float* __restrict__ b_m,
    const float* __restrict__ Wxm, const float* __restrict__ Wbm,
    const float* __restrict__ x_c, const float* __restrict__ b_c,
    const float* __restrict__ Wxc, const float* __restrict__ Wbc)
{
    const int fam = blockIdx.z;
    const int m0  = blockIdx.x * 128;       // 0 or 128  (= batch b)
    const int n0g = blockIdx.y * 64;        // 0..1535
    const int s_idx = n0g >> 9;
    const int cbase = n0g & 511;

    const float* X1 = fam ? x_c : x_m;
    const float* X2 = fam ? b_c : b_m;
    const float* W1 = (fam ? Wxc : Wxm) + (size_t)s_idx * 262144 + cbase;
    const float* W2 = (fam ? Wbc : Wbm) + (size_t)s_idx * 262144 + cbase;

    __shared__ __align__(16) __nv_bfloat16 Ah[128][40];
    __shared__ __align__(16) __nv_bfloat16 Al[128][40];
    __shared__ __align__(16) __nv_bfloat16 Bh[64][40];
    __shared__ __align__(16) __nv_bfloat16 Bl[64][40];

    const int t = threadIdx.x;
    const int w = t >> 5;
    const int wm = (w >> 1) * 32;           // 0,32,64,96
    const int wn = (w & 1) * 32;            // 0,32

    wmma::fragment<wmma::accumulator, 16, 16, 16, float> acc[2][2];
#pragma unroll
    for (int r = 0; r < 2; ++r)
#pragma unroll
        for (int c = 0; c < 2; ++c) wmma::fill_fragment(acc[r][c], 0.f);

    // staging thread map
    const int ar = t >> 1;                  // A row 0..127
    const int ak = (t & 1) * 16;            // A k-offset 0 or 16 (4 float4)
    const int kr = t >> 3;                  // B k-row 0..31
    const int nq = (t & 7) * 8;             // B n-offset (2 float4)

    float4 aReg[4], bReg[2];

    // prefetch chunk 0
#pragma unroll
    for (int q = 0; q < 4; ++q)
        aReg[q] = *(const float4*)&X1[(size_t)(m0 + ar) * 512 + ak + q * 4];
    bReg[0] = *(const float4*)&W1[(size_t)kr * 512 + nq];
    bReg[1] = *(const float4*)&W1[(size_t)kr * 512 + nq + 4];

    for (int it = 0; it < 32; ++it) {
        // convert + store staged chunk to smem (hi/lo split)
#pragma unroll
        for (int q = 0; q < 4; ++q) {
            float v[4] = {aReg[q].x, aReg[q].y, aReg[q].z, aReg[q].w};
#pragma unroll
            for (int e = 0; e < 4; ++e) {
                __nv_bfloat16 hi = __float2bfloat16(v[e]);
                Ah[ar][ak + q * 4 + e] = hi;
                Al[ar][ak + q * 4 + e] = __float2bfloat16(v[e] - __bfloat162float(hi));
            }
        }
#pragma unroll
        for (int q = 0; q < 2; ++q) {
            float v[4] = {bReg[q].x, bReg[q].y, bReg[q].z, bReg[q].w};
#pragma unroll
            for (int e = 0; e < 4; ++e) {
                __nv_bfloat16 hi = __float2bfloat16(v[e]);
                Bh[nq + q * 4 + e][kr] = hi;
                Bl[nq + q * 4 + e][kr] = __float2bfloat16(v[e] - __bfloat162float(hi));
            }
        }
        __syncthreads();

        // prefetch next chunk (overlaps with the MMA phase below)
        int nx = it + 1;
        if (nx < 32) {
            const float* X = (nx < 16) ? X1 : X2;
            const float* W = (nx < 16) ? W1 : W2;
            int kk = (nx & 15) * 32;
#pragma unroll
            for (int q = 0; q < 4; ++q)
                aReg[q] = *(const float4*)&X[(size_t)(m0 + ar) * 512 + kk + ak + q * 4];
            bReg[0] = *(const float4*)&W[(size_t)(kk + kr) * 512 + nq];
            bReg[1] = *(const float4*)&W[(size_t)(kk + kr) * 512 + nq + 4];
        }

        // MMA on current chunk: 2 x k16 steps, 3-pass split
#pragma unroll
        for (int ks = 0; ks < 2; ++ks) {
            wmma::fragment<wmma::matrix_a, 16, 16, 16, __nv_bfloat16, wmma::row_major> ah[2], al[2];
            wmma::fragment<wmma::matrix_b, 16, 16, 16, __nv_bfloat16, wmma::col_major> bh[2], bl[2];
#pragma unroll
            for (int r = 0; r < 2; ++r) {
                wmma::load_matrix_sync(ah[r], &Ah[wm + 16 * r][ks * 16], 40);
                wmma::load_matrix_sync(al[r], &Al[wm + 16 * r][ks * 16], 40);
            }
#pragma unroll
            for (int c = 0; c < 2; ++c) {
                wmma::load_matrix_sync(bh[c], &Bh[wn + 16 * c][ks * 16], 40);
                wmma::load_matrix_sync(bl[c], &Bl[wn + 16 * c][ks * 16], 40);
            }
#pragma unroll
            for (int r = 0; r < 2; ++r)
#pragma unroll
                for (int c = 0; c < 2; ++c) {
                    wmma::mma_sync(acc[r][c], ah[r], bh[c], acc[r][c]);
                    wmma::mma_sync(acc[r][c], ah[r], bl[c], acc[r][c]);
                    wmma::mma_sync(acc[r][c], al[r], bh[c], acc[r][c]);
                }
        }
        __syncthreads();
    }

    // epilogue: optional elu1, direct store (m-tile = one batch, n-tile inside one head)
    const int h_idx = cbase >> 7;
    const int k0 = cbase & 127;
    const int b = m0 >> 7;
    float* outp = &g_qkv[fam][s_idx][b][h_idx][0][k0];

#pragma unroll
    for (int r = 0; r < 2; ++r)
#pragma unroll
        for (int c = 0; c < 2; ++c) {
            if (fam == 1) {
#pragma unroll
                for (int e = 0; e < acc[r][c].num_elements; ++e) {
                    float v = acc[r][c].x[e];
                    acc[r][c].x[e] = (v > 0.f) ? (v + 1.f) : expf(v);
                }
            }
            wmma::store_matrix_sync(&outp[(size_t)(wm + 16 * r) * 128 + wn + 16 * c],
                                    acc[r][c], 128, wmma::mem_row_major);
        }
}

// =====================================================================
// K2: fused small linears as one GEMM. M = 1024(p rows) + 128(bb rows).
// =====================================================================
__global__ void __launch_bounds__(256) linqk_kernel(
    const float* __restrict__ p_m,  const float* __restrict__ bb_m,
    const float* __restrict__ Wq1_w, const float* __restrict__ Wq1_b,
    const float* __restrict__ Wq2_w, const float* __restrict__ Wq2_b,
    const float* __restrict__ Wk1_w, const float* __restrict__ Wk1_b,
    const float* __restrict__ Wk2_w, const float* __restrict__ Wk2_b)
{
    const int sel = blockIdx.z;
    const int m0 = blockIdx.x * 64;
    const int n0 = blockIdx.y * 64;
    const bool bbreg = (m0 >= 1024);

    const float* W    = sel ? (bbreg ? Wk1_w : Wk2_w) : (bbreg ? Wq1_w : Wq2_w);
    const float* bias = sel ? (bbreg ? Wk1_b : Wk2_b) : (bbreg ? Wq1_b : Wq2_b);

    const int tid = threadIdx.x;
    const int tx = tid & 15, ty = tid >> 4;

    __shared__ __align__(16) float As[16][68];
    __shared__ __align__(16) float Bs[16][68];

    float acc[4][4] = {};

    const int a_row = tid >> 2;
    const int a_k4  = (tid & 3) * 4;

    for (int kk = 0; kk < 128; kk += 16) {
        {
            int r = m0 + a_row;
            const float* src;
            if (r < 1024) {
                int b = r >> 9, h = (r >> 7) & 3, n = r & 127;
                src = p_m + (size_t)(b * 128 + n) * 512 + h * 128 + kk + a_k4;
            } else {
                int r2 = r - 1024;
                int b = r2 >> 6, h = (r2 >> 4) & 3, nn = r2 & 15;
                src = bb_m + (size_t)(b * 16 + nn) * 512 + h * 128 + kk + a_k4;
            }
            float4 av = *(const float4*)src;
            As[a_k4 + 0][a_row] = av.x;
            As[a_k4 + 1][a_row] = av.y;
            As[a_k4 + 2][a_row] = av.z;
            As[a_k4 + 3][a_row] = av.w;
        }
        {
            int c = tid >> 2, k4 = (tid & 3) * 4;
            float4 bv = *(const float4*)&W[(size_t)(n0 + c) * 128 + kk + k4];
            Bs[k4 + 0][c] = bv.x;
            Bs[k4 + 1][c] = bv.y;
            Bs[k4 + 2][c] = bv.z;
            Bs[k4 + 3][c] = bv.w;
        }
        __syncthreads();
#pragma unroll
        for (int kd = 0; kd < 16; ++kd) {
            float4 a4 = *(const float4*)&As[kd][ty * 4];
            float4 b4 = *(const float4*)&Bs[kd][tx * 4];
            float a[4] = {a4.x, a4.y, a4.z, a4.w};
            float bb[4] = {b4.x, b4.y, b4.z, b4.w};
#pragma unroll
            for (int r = 0; r < 4; ++r)
#pragma unroll
                for (int c = 0; c < 4; ++c) acc[r][c] += a[r] * bb[c];
        }
        __syncthreads();
    }

    float* outp = sel ? &g_pk[0][0][0][0] : &g_pq[0][0][0][0];
    float* outb = sel ? &g_bbK[0][0][0][0][0] : &g_bbQ[0][0][0][0][0];
#pragma unroll
    for (int r = 0; r < 4; ++r) {
        int rr = m0 + ty * 4 + r;
#pragma unroll
        for (int c = 0; c < 4; ++c) {
            int col = n0 + tx * 4 + c;
            float v = acc[r][c] + bias[col];
            if (rr < 1024) outp[(size_t)rr * 128 + col] = v;
            else           outb[(size_t)(rr - 1024) * 128 + col] = v;
        }
    }
}

// =====================================================================
// K3: tri-SAGP fusion -> FQ/FK + squared norms.
// =====================================================================
__global__ void __launch_bounds__(128) build_fqfk(const float* __restrict__ bb_c,
                                                  const float* __restrict__ p_c,
                                                  const int* __restrict__ b_seq)
{
    int r = blockIdx.x;                 // 0..1023 = (b,h,i)
    int b  = r >> 9;
    int hh = (r >> 7) & 3;
    int i  = r & 127;
    int t  = threadIdx.x;               // 128
    int w = t >> 5, lane = t & 31;
    const float eps = 1e-24f;

    __shared__ float rq[4][4];          // [warp][sb]
    __shared__ float rk[4][4];

    int si = b_seq[b * 128 + i];
    float c3 = p_c[(size_t)(b * 128 + i) * 512 + hh * 128 + t];
    float p3 = 1.f / fmaxf(c3, eps);

    float nq[4], nk[4];

    // ---- Q side ----
    {
        float m1 = g_qkv[0][0][b][hh][i][t];
        float c1 = g_qkv[1][0][b][hh][i][t];
        float m3 = g_pq[b][hh][i][t];
        float p1 = 1.f / fmaxf(c1, eps);
        float base_m = m1 * p1 + m3 * p3;
        float base_p = p1 + p3;
#pragma unroll
        for (int sb = 0; sb < 4; ++sb) {
            float m2 = g_bbQ[b][hh][sb][si][t];
            float c2 = bb_c[(size_t)((b * 4 + sb) * 4 + si) * 512 + hh * 128 + t];
            float p2 = 1.f / fmaxf(c2, eps);
            float cf = 1.f / (base_p + p2);
            float mf = cf * (base_m + m2 * p2);
            float cfc = fmaxf(cf, eps);
            g_FQ[b][hh][i][sb][t]       = mf;
            g_FQ[b][hh][i][sb][128 + t] = sqrtf(cfc);
            nq[sb] = mf * mf + cfc;
        }
    }
    // ---- K side (j = i) ----
    {
        float m1 = g_qkv[0][1][b][hh][i][t];
        float c1 = g_qkv[1][1][b][hh][i][t];
        float m3 = g_pk[b][hh][i][t];
        float p1 = 1.f / fmaxf(c1, eps);
        float base_m = m1 * p1 + m3 * p3;
        float base_p = p1 + p3;
        int sj = si;
#pragma unroll
        for (int sa = 0; sa < 4; ++sa) {
            float m2 = g_bbK[b][hh][sj][sa][t];
            float c2 = bb_c[(size_t)((b * 4 + sj) * 4 + sa) * 512 + hh * 128 + t];
            float p2 = 1.f / fmaxf(c2, eps);
            float cf = 1.f / (base_p + p2);
            float mf = cf * (base_m + m2 * p2);
            float cfc = fmaxf(cf, eps);
            g_FK[b][hh][i][sa][t]       = mf;
            g_FK[b][hh][i][sa][128 + t] = sqrtf(cfc);
            nk[sa] = mf * mf + cfc;
        }
    }

    // reduce the 8 norms over 128 threads
#pragma unroll
    for (int sb = 0; sb < 4; ++sb) {
        float a = nq[sb], c = nk[sb];
#pragma unroll
        for (int o = 16; o; o >>= 1) {
            a += __shfl_xor_sync(0xFFFFFFFFu, a, o);
            c += __shfl_xor_sync(0xFFFFFFFFu, c, o);
        }
        if (lane == 0) { rq[w][sb] = a; rk[w][sb] = c; }
    }
    __syncthreads();
    if (t < 4)
        g_sqnq[b][hh][i][t] = rq[0][t] + rq[1][t] + rq[2][t] + rq[3][t];
    else if (t < 8) {
        int sb = t - 4;
        g_sqnk[b][hh][i][sb] = rk[0][sb] + rk[1][sb] + rk[2][sb] + rk[3][sb];
    }
}

// =====================================================================
// K4a: bucketed score GEMM. grid (16 subtiles, 16 (si,sb), 8 bh), 256 thr.
// =====================================================================
__global__ void __launch_bounds__(256) scores_kernel()
{
    const int bh = blockIdx.z;
    const int b = bh >> 2, h = bh & 3;
    const int si = blockIdx.y >> 2, sb = blockIdx.y & 3;
    const int ti = (blockIdx.x >> 2) * 32, tj = (blockIdx.x & 3) * 32;

    const int rbase = g_off[b][si], rcnt = g_off[b][si + 1] - rbase;
    const int cbase = g_off[b][sb], ccnt = g_off[b][sb + 1] - cbase;
    if (ti >= rcnt || tj >= ccnt) return;

    const int t = threadIdx.x;
    const int tx = t & 15, ty = t >> 4;

    __shared__ __align__(16) float As[32][33];
    __shared__ __align__(16) float Bs[32][33];
    __shared__ int rid[32], cid[32];
    __shared__ float sqr[32], sqc[32];

    if (t < 32) {
        int pr = ti + t; if (pr > rcnt - 1) pr = rcnt - 1;
        int id = g_perm[b][rbase + pr];
        rid[t] = id;
        sqr[t] = g_sqnq[b][h][id][sb];
    } else if (t < 64) {
        int u = t - 32;
        int pc = tj + u; if (pc > ccnt - 1) pc = ccnt - 1;
        int id = g_perm[b][cbase + pc];
        cid[u] = id;
        sqc[u] = g_sqnk[b][h][id][si];
    }
    __syncthreads();

    float acc[2][2] = {};
    const int lr = t >> 3;
    const int d4 = (t & 7) * 4;

    for (int kk = 0; kk < 256; kk += 32) {
        float4 av = *(const float4*)&g_FQ[b][h][rid[lr]][sb][kk + d4];
        As[d4 + 0][lr] = av.x; As[d4 + 1][lr] = av.y;
        As[d4 + 2][lr] = av.z; As[d4 + 3][lr] = av.w;
        float4 bv = *(const float4*)&g_FK[b][h][cid[lr]][si][kk + d4];
        Bs[d4 + 0][lr] = bv.x; Bs[d4 + 1][lr] = bv.y;
        Bs[d4 + 2][lr] = bv.z; Bs[d4 + 3][lr] = bv.w;
        __syncthreads();
#pragma unroll
        for (int d = 0; d < 32; ++d) {
            float a0 = As[d][ty * 2], a1 = As[d][ty * 2 + 1];
            float b0 = Bs[d][tx * 2], b1 = Bs[d][tx * 2 + 1];
            acc[0][0] += a0 * b0; acc[0][1] += a0 * b1;
            acc[1][0] += a1 * b0; acc[1][1] += a1 * b1;
        }
        __syncthreads();
    }

    const float scale = 0.08838834764831845f;   // 1/sqrt(128)
#pragma unroll
    for (int r = 0; r < 2; ++r) {
        int pr = ti + ty * 2 + r;
        if (pr >= rcnt) continue;
#pragma unroll
        for (int c = 0; c < 2; ++c) {
            int pc = tj + tx * 2 + c;
            if (pc >= ccnt) continue;
            float w2v = sqr[ty * 2 + r] + sqc[tx * 2 + c] - 2.f * acc[r][c];
            g_scs[bh][rbase + pr][cbase + pc] = -w2v * scale;
        }
    }
}

// =====================================================================
// K4b: softmax + probs scatter + context. grid 128, 256 thr.
// =====================================================================
__global__ void __launch_bounds__(256) softmax_ctx_kernel(float* __restrict__ out_probs)
{
    const int blk = blockIdx.x;
    const int bh = blk >> 4;
    const int b = bh >> 2, h = bh & 3;
    const int i0 = (blk & 15) * 8;
    const int t = threadIdx.x;
    const int lane = t & 31;

    __shared__ float sc[8 * 128];
    __shared__ int perm_s[128];
    __shared__ float ctxm[1024], ctxc[1024];

    if (t < 128) perm_s[t] = g_perm[b][t];
    {
        const float4* src = (const float4*)&g_scs[bh][i0][0];
        ((float4*)sc)[t] = src[t];
    }
    __syncthreads();

    // softmax: warp w owns sorted row pi = i0 + w
    {
        int w = t >> 5;
        float4* row = (float4*)(sc + w * 128);
        float4 x4 = row[lane];
        float m = fmaxf(fmaxf(x4.x, x4.y), fmaxf(x4.z, x4.w));
#pragma unroll
        for (int o = 16; o; o >>= 1) m = fmaxf(m, __shfl_xor_sync(0xFFFFFFFFu, m, o));
        float e0 = expf(x4.x - m), e1 = expf(x4.y - m);
        float e2 = expf(x4.z - m), e3 = expf(x4.w - m);
        float s = e0 + e1 + e2 + e3;
#pragma unroll
        for (int o = 16; o; o >>= 1) s += __shfl_xor_sync(0xFFFFFFFFu, s, o);
        float inv = 1.f / s;
        float4 p4 = make_float4(e0 * inv, e1 * inv, e2 * inv, e3 * inv);
        row[lane] = p4;
        // scatter probs into true (i, j) layout
        int i = perm_s[i0 + w];
        float* op = out_probs + (size_t)(bh * 128 + i) * 128;
        op[perm_s[4 * lane + 0]] = p4.x;
        op[perm_s[4 * lane + 1]] = p4.y;
        op[perm_s[4 * lane + 2]] = p4.z;
        op[perm_s[4 * lane + 3]] = p4.w;
    }
    __syncthreads();

    // context: mean = P @ v1, cov = P^2 @ v2 (cols gathered by perm)
    {
        int k = t & 127, half = t >> 7;
        float am[8] = {}, ac[8] = {};
        const float* v1 = &g_qkv[0][2][b][h][0][0];
        const float* v2 = &g_qkv[1][2][b][h][0][0];
        int j0 = half * 64;
#pragma unroll 4
        for (int pj = j0; pj < j0 + 64; ++pj) {
            int jv = perm_s[pj];
            float x1 = v1[(size_t)jv * 128 + k];
            float x2 = v2[(size_t)jv * 128 + k];
#pragma unroll
            for (int il = 0; il < 8; ++il) {
                float p = sc[il * 128 + pj];
                am[il] += p * x1;
                ac[il] += p * p * x2;
            }
        }
        if (half == 0) {
#pragma unroll
            for (int il = 0; il < 8; ++il) {
                ctxm[il * 128 + k] = am[il];
                ctxc[il * 128 + k] = ac[il];
            }
        }
        __syncthreads();
        if (half == 1) {
#pragma unroll
            for (int il = 0; il < 8; ++il) {
                int i = perm_s[i0 + il];
                g_ctx[0][b][i][h * 128 + k] = am[il] + ctxm[il * 128 + k];
                g_ctx[1][b][i][h * 128 + k] = ac[il] + ctxc[il * 128 + k];
            }
        }
    }
}

// =====================================================================
// K5: output GEMM + bias + residual. grid (8, 8, 2z), 128 threads, 32x64.
// =====================================================================
__global__ void __launch_bounds__(128) outgemm_kernel(
    const float* __restrict__ mean_w, const float* __restrict__ mean_b,
    const float* __restrict__ cov_w,  const float* __restrict__ cov_b,
    const float* __restrict__ x_m,    const float* __restrict__ x_c)
{
    int z = blockIdx.z;
    const float* W     = z ? cov_w  : mean_w;
    const float* bias  = z ? cov_b  : mean_b;
    const float* resid = z ? x_c    : x_m;
    const float* A = &g_ctx[z][0][0][0];
    float* out = &g_tmp[z][0][0][0];

    const int m0 = blockIdx.x * 32;
    const int n0 = blockIdx.y * 64;
    const int tid = threadIdx.x;
    const int tx = tid & 15, ty = tid >> 4;

    __shared__ __align__(16) float As[16][36];
    __shared__ __align__(16) float Bs[16][68];
    float acc[4][4] = {};

    const int a_row = tid >> 2;
    const int a_k4  = (tid & 3) * 4;

    for (int kk = 0; kk < 512; kk += 16) {
        float4 av = *(const float4*)&A[(size_t)(m0 + a_row) * 512 + kk + a_k4];
        As[a_k4 + 0][a_row] = av.x;
        As[a_k4 + 1][a_row] = av.y;
        As[a_k4 + 2][a_row] = av.z;
        As[a_k4 + 3][a_row] = av.w;
        {
            int c = tid >> 2, k4 = (tid & 3) * 4;
            float4 bv = *(const float4*)&W[(size_t)(n0 + c) * 512 + kk + k4];
            Bs[k4 + 0][c] = bv.x; Bs[k4 + 1][c] = bv.y;
            Bs[k4 + 2][c] = bv.z; Bs[k4 + 3][c] = bv.w;
            int c2 = c + 32;
            float4 bw = *(const float4*)&W[(size_t)(n0 + c2) * 512 + kk + k4];
            Bs[k4 + 0][c2] = bw.x; Bs[k4 + 1][c2] = bw.y;
            Bs[k4 + 2][c2] = bw.z; Bs[k4 + 3][c2] = bw.w;
        }
        __syncthreads();
#pragma unroll
        for (int kd = 0; kd < 16; ++kd) {
            float4 a4 = *(const float4*)&As[kd][ty * 4];
            float4 b4 = *(const float4*)&Bs[kd][tx * 4];
            float a[4] = {a4.x, a4.y, a4.z, a4.w};
            float bb[4] = {b4.x, b4.y, b4.z, b4.w};
#pragma unroll
            for (int r = 0; r < 4; ++r)
#pragma unroll
                for (int c = 0; c < 4; ++c) acc[r][c] += a[r] * bb[c];
        }
        __syncthreads();
    }

#pragma unroll
    for (int r = 0; r < 4; ++r) {
        int m = m0 + ty * 4 + r;
#pragma unroll
        for (int c = 0; c < 4; ++c) {
            int d = n0 + tx * 4 + c;
            out[(size_t)m * 512 + d] = acc[r][c] + bias[d] + resid[(size_t)m * 512 + d];
        }
    }
}

// =====================================================================
// K6: LayerNorm -> d_out
// =====================================================================
__global__ void ln_kernel(const float* __restrict__ ln_w, const float* __restrict__ ln_b,
                          float* __restrict__ d_out_f)
{
    int blk = blockIdx.x;
    int z = blk >> 8;
    int row = blk & 255;
    int tid = threadIdx.x;
    int w = tid >> 5, lane = tid & 31;
    __shared__ float red[8];

    const float* x = &g_tmp[z][0][0][0] + (size_t)row * 512;
    float a0 = x[tid], a1 = x[tid + 256];

    float s = a0 + a1;
#pragma unroll
    for (int o = 16; o; o >>= 1) s += __shfl_xor_sync(0xFFFFFFFFu, s, o);
    if (lane == 0) red[w] = s;
    __syncthreads();
    if (tid == 0) { float t2 = 0.f; for (int q = 0; q < 8; ++q) t2 += red[q]; red[0] = t2; }
    __syncthreads();
    float mean = red[0] * (1.f / 512.f);
    float d0 = a0 - mean, d1 = a1 - mean;
    float v = d0 * d0 + d1 * d1;
    __syncthreads();
#pragma unroll
    for (int o = 16; o; o >>= 1) v += __shfl_xor_sync(0xFFFFFFFFu, v, o);
    if (lane == 0) red[w] = v;
    __syncthreads();
    if (tid == 0) { float t2 = 0.f; for (int q = 0; q < 8; ++q) t2 += red[q]; red[0] = t2; }
    __syncthreads();
    float var = red[0] * (1.f / 512.f);
    float inv = 1.f / sqrtf(var + 1e-12f);

    float* o = d_out_f + (size_t)z * 131072 + (size_t)row * 512;
    o[tid]       = d0 * inv * ln_w[tid]       + ln_b[tid];
    o[tid + 256] = d1 * inv * ln_w[tid + 256] + ln_b[tid + 256];
}

// =====================================================================
extern "C" void kernel_launch(void* const* d_in, const int* in_sizes, int n_in,
                              void* d_out, int out_size)
{
    const float* x_m    = (const float*)d_in[0];
    const float* x_c    = (const float*)d_in[1];
    const float* b_m    = (const float*)d_in[2];
    const float* b_c    = (const float*)d_in[3];
    const float* bb_m   = (const float*)d_in[4];
    const float* bb_c   = (const float*)d_in[5];
    const float* p_m    = (const float*)d_in[6];
    const float* p_c    = (const float*)d_in[7];
    const float* W_xm   = (const float*)d_in[8];
    const float* W_xc   = (const float*)d_in[9];
    const float* W_bm   = (const float*)d_in[10];
    const float* W_bc   = (const float*)d_in[11];
    const float* Wq1_w  = (const float*)d_in[12];
    const float* Wq1_b  = (const float*)d_in[13];
    const float* Wq2_w  = (const float*)d_in[14];
    const float* Wq2_b  = (const float*)d_in[15];
    const float* Wk1_w  = (const float*)d_in[16];
    const float* Wk1_b  = (const float*)d_in[17];
    const float* Wk2_w  = (const float*)d_in[18];
    const float* Wk2_b  = (const float*)d_in[19];
    const float* mean_w = (const float*)d_in[20];
    const float* mean_b = (const float*)d_in[21];
    const float* cov_w  = (const float*)d_in[22];
    const float* cov_b  = (const float*)d_in[23];
    const float* ln_w   = (const float*)d_in[24];
    const float* ln_b   = (const float*)d_in[25];
    const int*   b_seq  = (const int*)d_in[26];

    float* out = (float*)d_out;
    float* out_probs = out + 262144;   // [mean | cov | probs]

    perm_kernel<<<2, 128>>>(b_seq);
    proj_tc_kernel<<<dim3(2, 24, 2), 256>>>(x_m, b_m, W_xm, W_bm, x_c, b_c, W_xc, W_bc);
    linqk_kernel<<<dim3(18, 2, 2), 256>>>(p_m, bb_m,
                                          Wq1_w, Wq1_b, Wq2_w, Wq2_b,
                                          Wk1_w, Wk1_b, Wk2_w, Wk2_b);
    build_fqfk<<<1024, 128>>>(bb_c, p_c, b_seq);
    scores_kernel<<<dim3(16, 16, 8), 256>>>();
    softmax_ctx_kernel<<<128, 256>>>(out_probs);
    outgemm_kernel<<<dim3(8, 8, 2), 128>>>(mean_w, mean_b, cov_w, cov_b, x_m, x_c);
    ln_kernel<<<512, 256>>>(ln_w, ln_b, out);
}

// round 12
// speedup vs baseline: 1.9200x; 1.1200x over previous
#include <cuda_runtime.h>
#include <cuda_bf16.h>
#include <mma.h>
#include <stdint.h>
#include <cstdint>
#include <math.h>

using namespace nvcuda;

#define BATCH 2
#define SEQ 128
#define NH 4
#define DKK 128
#define DD 512
#define NBB 4

// ---------------- scratch (device globals; no allocation allowed) ----------------
__device__ float g_qkv[2][3][BATCH][NH][SEQ][DKK]; // [fam(m/c)][q/k/v][b][h][n][k]
__device__ float g_bbQ[BATCH][NH][NBB][NBB][DKK];
__device__ float g_bbK[BATCH][NH][NBB][NBB][DKK];
__device__ float g_pq[BATCH][NH][SEQ][DKK];
__device__ float g_pk[BATCH][NH][SEQ][DKK];
__device__ float g_FQ[BATCH][NH][SEQ][NBB][2*DKK]; // [m(0..127) | sqrt(c)(128..255)]
__device__ float g_FK[BATCH][NH][SEQ][NBB][2*DKK];
__device__ float g_sqnq[BATCH][NH][SEQ][NBB];
__device__ float g_sqnk[BATCH][NH][SEQ][NBB];
__device__ int   g_perm[BATCH][SEQ];
__device__ int   g_off[BATCH][NBB + 1];
__device__ float g_scs[BATCH*NH][SEQ][SEQ];
__device__ float g_ctx[2][BATCH][SEQ][DD];
__device__ float g_tmp[2][BATCH][SEQ][DD];

// bf16 hi/lo operand copies (pre-split, W pre-transposed)
__device__ __nv_bfloat16 g_Xh[4][256][512];   // [fam*2+pair][m][k]
__device__ __nv_bfloat16 g_Xl[4][256][512];
__device__ __nv_bfloat16 g_WTh[12][512][512]; // [(fam*2+pair)*3+s][hk][k]  (transposed)
__device__ __nv_bfloat16 g_WTl[12][512][512];

// =====================================================================
// P1: convert X inputs to bf16 hi/lo. grid 512, 256 thr, 1 float4/thread.
// =====================================================================
__global__ void prep_x(const float* __restrict__ x_m, const float* __restrict__ b_m,
                       const float* __restrict__ x_c, const float* __restrict__ b_c)
{
    int idx = blockIdx.x * 256 + threadIdx.x;      // 0..131071 float4 groups
    int a = idx >> 15;                              // array 0..3
    int r = idx & 32767;
    const float* src = (a == 0) ? x_m : (a == 1) ? b_m : (a == 2) ? x_c : b_c;
    float4 v = ((const float4*)src)[r];
    __nv_bfloat16* oh = &g_Xh[0][0][0] + (size_t)a * 131072 + (size_t)r * 4;
    __nv_bfloat16* ol = &g_Xl[0][0][0] + (size_t)a * 131072 + (size_t)r * 4;
    float vv[4];
    vv[0] = v.x; vv[1] = v.y; vv[2] = v.z; vv[3] = v.w;
#pragma unroll
    for (int e = 0; e < 4; ++e) {
        __nv_bfloat16 hi = __float2bfloat16(vv[e]);
        oh[e] = hi;
        ol[e] = __float2bfloat16(vv[e] - __bfloat162float(hi));
    }
}

// =====================================================================
// P2: transpose + convert W to bf16 hi/lo [hk][k]. grid (16,16,6)x2.
// =====================================================================
__global__ void prep_w(const float* __restrict__ Wxm, const float* __restrict__ Wbm,
                       const float* __restrict__ Wxc, const float* __restrict__ Wbc,
                       int mbase)
{
    int mi = mbase + blockIdx.z;                   // 0..11
    int fam = mi / 6;
    int pair = (mi / 3) & 1;
    int s = mi % 3;
    const float* src = (fam == 0) ? (pair == 0 ? Wxm : Wbm)
                                  : (pair == 0 ? Wxc : Wbc);
    src += (size_t)s * 262144;

    int hk0 = blockIdx.x * 32, d0 = blockIdx.y * 32;
    __shared__ float tile[32][33];
    int r = threadIdx.x >> 3, c4 = (threadIdx.x & 7) * 4;
    float4 v = *(const float4*)&src[(size_t)(d0 + r) * 512 + hk0 + c4];
    tile[r][c4 + 0] = v.x; tile[r][c4 + 1] = v.y;
    tile[r][c4 + 2] = v.z; tile[r][c4 + 3] = v.w;
    __syncthreads();

    __nv_bfloat16* oh = &g_WTh[0][0][0] + (size_t)mi * 262144 + (size_t)(hk0 + r) * 512 + d0 + c4;
    __nv_bfloat16* ol = &g_WTl[0][0][0] + (size_t)mi * 262144 + (size_t)(hk0 + r) * 512 + d0 + c4;
#pragma unroll
    for (int e = 0; e < 4; ++e) {
        float f = tile[c4 + e][r];
        __nv_bfloat16 hi = __float2bfloat16(f);
        oh[e] = hi;
        ol[e] = __float2bfloat16(f - __bfloat162float(hi));
    }
}

// =====================================================================
// K0: counting sort of sequence positions by bucket id.
// =====================================================================
__global__ void perm_kernel(const int* __restrict__ b_seq)
{
    int b = blockIdx.x, t = threadIdx.x;
    __shared__ int keys[128];
    __shared__ int cnt[4];
    __shared__ int off[5];
    keys[t] = b_seq[b * 128 + t];
    if (t < 4) cnt[t] = 0;
    __syncthreads();
    int key = keys[t];
    int rank = 0;
    for (int u = 0; u < t; ++u) rank += (keys[u] == key);
    atomicAdd(&cnt[key], 1);
    __syncthreads();
    if (t == 0) {
        off[0] = 0;
        for (int q = 0; q < 4; ++q) off[q + 1] = off[q] + cnt[q];
    }
    __syncthreads();
    g_perm[b][off[key] + rank] = t;
    if (t < 5) g_off[b][t] = off[t];
}

// =====================================================================
// K1: wmma projection GEMM fed by pre-split bf16 operands.
// grid (2, 24, 2fam), 256 thr, 55296B dynamic smem (72-padded tiles).
// Tile M=128, N=64, K=1024 (2 operand pairs), 3-pass hi/lo split.
// Inner loop: pure uint4 staging (register-prefetched), wmma MMA phase.
// =====================================================================
#define PROJ_SMEM 55296

__global__ void __launch_bounds__(256) proj_wmma2()
{
    extern __shared__ char ds[];
    __nv_bfloat16* Ah = (__nv_bfloat16*)ds;       // [128][72]
    __nv_bfloat16* Al = Ah + 128 * 72;            // [128][72]
    __nv_bfloat16* Bh = Al + 128 * 72;            // [64][72]
    __nv_bfloat16* Bl = Bh + 64 * 72;             // [64][72]

    const int t = threadIdx.x;
    const int w = t >> 5;
    const int wm = (w >> 1) * 32;                 // 0,32,64,96
    const int wn = (w & 1) * 32;                  // 0,32

    const int fam = blockIdx.z;
    const int m0 = blockIdx.x * 128;              // batch tile
    const int n0g = blockIdx.y * 64;
    const int s_idx = n0g >> 9;
    const int cbase = n0g & 511;

    wmma::fragment<wmma::accumulator, 16, 16, 16, float> acc[2][2];
#pragma unroll
    for (int r = 0; r < 2; ++r)
#pragma unroll
        for (int c = 0; c < 2; ++c) wmma::fill_fragment(acc[r][c], 0.f);

    // per-thread staging slots: A rows (4 each for hi+lo), B rows (2 each)
    const int arowA = (t + 0) >> 3;               // with q offsets below
    (void)arowA;

    uint4 pf[12];

    // ---- prefetch chunk 0 ----
    {
        const int pair = 0, kk = 0;
        const int ai = fam * 2 + pair;
        const int mi = ai * 3 + s_idx;
        const __nv_bfloat16* Axh = &g_Xh[ai][m0][kk];
        const __nv_bfloat16* Axl = &g_Xl[ai][m0][kk];
        const __nv_bfloat16* Bxh = &g_WTh[0][0][0] + (size_t)mi * 262144 + (size_t)cbase * 512 + kk;
        const __nv_bfloat16* Bxl = &g_WTl[0][0][0] + (size_t)mi * 262144 + (size_t)cbase * 512 + kk;
#pragma unroll
        for (int q = 0; q < 4; ++q) {
            int s = t + 256 * q;
            int r = s >> 3, kb = s & 7;
            pf[q]     = *(const uint4*)(Axh + (size_t)r * 512 + kb * 8);
            pf[4 + q] = *(const uint4*)(Axl + (size_t)r * 512 + kb * 8);
        }
#pragma unroll
        for (int q = 0; q < 2; ++q) {
            int s = t + 256 * q;
            int r = s >> 3, kb = s & 7;
            pf[8 + q]  = *(const uint4*)(Bxh + (size_t)r * 512 + kb * 8);
            pf[10 + q] = *(const uint4*)(Bxl + (size_t)r * 512 + kb * 8);
        }
    }

    for (int c = 0; c < 16; ++c) {
        // store prefetched chunk c into smem (rows padded to 72 elems = 144B)
#pragma unroll
        for (int q = 0; q < 4; ++q) {
            int s = t + 256 * q;
            int r = s >> 3, kb = s & 7;
            *(uint4*)((char*)Ah + (size_t)r * 144 + kb * 16) = pf[q];
            *(uint4*)((char*)Al + (size_t)r * 144 + kb * 16) = pf[4 + q];
        }
#pragma unroll
        for (int q = 0; q < 2; ++q) {
            int s = t + 256 * q;
            int r = s >> 3, kb = s & 7;
            *(uint4*)((char*)Bh + (size_t)r * 144 + kb * 16) = pf[8 + q];
            *(uint4*)((char*)Bl + (size_t)r * 144 + kb * 16) = pf[10 + q];
        }
        __syncthreads();

        // prefetch chunk c+1 (overlaps the MMA phase)
        if (c + 1 < 16) {
            const int nx = c + 1;
            const int pair = nx >> 3;
            const int kk = (nx & 7) * 64;
            const int ai = fam * 2 + pair;
            const int mi = ai * 3 + s_idx;
            const __nv_bfloat16* Axh = &g_Xh[ai][m0][kk];
            const __nv_bfloat16* Axl = &g_Xl[ai][m0][kk];
            const __nv_bfloat16* Bxh = &g_WTh[0][0][0] + (size_t)mi * 262144 + (size_t)cbase * 512 + kk;
            const __nv_bfloat16* Bxl = &g_WTl[0][0][0] + (size_t)mi * 262144 + (size_t)cbase * 512 + kk;
#pragma unroll
            for (int q = 0; q < 4; ++q) {
                int s = t + 256 * q;
                int r = s >> 3, kb = s & 7;
                pf[q]     = *(const uint4*)(Axh + (size_t)r * 512 + kb * 8);
                pf[4 + q] = *(const uint4*)(Axl + (size_t)r * 512 + kb * 8);
            }
#pragma unroll
            for (int q = 0; q < 2; ++q) {
                int s = t + 256 * q;
                int r = s >> 3, kb = s & 7;
                pf[8 + q]  = *(const uint4*)(Bxh + (size_t)r * 512 + kb * 8);
                pf[10 + q] = *(const uint4*)(Bxl + (size_t)r * 512 + kb * 8);
            }
        }

        // MMA phase: 4 k16 steps, 3-pass split
#pragma unroll
        for (int ks = 0; ks < 4; ++ks) {
            wmma::fragment<wmma::matrix_a, 16, 16, 16, __nv_bfloat16, wmma::row_major> ah[2], al[2];
            wmma::fragment<wmma::matrix_b, 16, 16, 16, __nv_bfloat16, wmma::col_major> bh[2], bl[2];
#pragma unroll
            for (int r = 0; r < 2; ++r) {
                wmma::load_matrix_sync(ah[r], Ah + (wm + 16 * r) * 72 + ks * 16, 72);
                wmma::load_matrix_sync(al[r], Al + (wm + 16 * r) * 72 + ks * 16, 72);
            }
#pragma unroll
            for (int cb = 0; cb < 2; ++cb) {
                wmma::load_matrix_sync(bh[cb], Bh + (wn + 16 * cb) * 72 + ks * 16, 72);
                wmma::load_matrix_sync(bl[cb], Bl + (wn + 16 * cb) * 72 + ks * 16, 72);
            }
#pragma unroll
            for (int r = 0; r < 2; ++r)
#pragma unroll
                for (int cb = 0; cb < 2; ++cb) {
                    wmma::mma_sync(acc[r][cb], ah[r], bh[cb], acc[r][cb]);
                    wmma::mma_sync(acc[r][cb], ah[r], bl[cb], acc[r][cb]);
                    wmma::mma_sync(acc[r][cb], al[r], bh[cb], acc[r][cb]);
                }
        }
        __syncthreads();
    }

    // epilogue: optional elu1, direct store (m-tile = one batch, n-tile inside one head)
    const int h_idx = cbase >> 7;
    const int k0 = cbase & 127;
    const int b = m0 >> 7;
    float* outp = &g_qkv[fam][s_idx][b][h_idx][0][k0];

#pragma unroll
    for (int r = 0; r < 2; ++r)
#pragma unroll
        for (int cb = 0; cb < 2; ++cb) {
            if (fam == 1) {
#pragma unroll
                for (int e = 0; e < acc[r][cb].num_elements; ++e) {
                    float v = acc[r][cb].x[e];
                    acc[r][cb].x[e] = (v > 0.f) ? (v + 1.f) : expf(v);
                }
            }
            wmma::store_matrix_sync(&outp[(size_t)(wm + 16 * r) * 128 + wn + 16 * cb],
                                    acc[r][cb], 128, wmma::mem_row_major);
        }
}

// =====================================================================
// K2: fused small linears as one GEMM. M = 1024(p rows) + 128(bb rows).
// =====================================================================
__global__ void __launch_bounds__(256) linqk_kernel(
    const float* __restrict__ p_m,  const float* __restrict__ bb_m,
    const float* __restrict__ Wq1_w, const float* __restrict__ Wq1_b,
    const float* __restrict__ Wq2_w, const float* __restrict__ Wq2_b,
    const float* __restrict__ Wk1_w, const float* __restrict__ Wk1_b,
    const float* __restrict__ Wk2_w, const float* __restrict__ Wk2_b)
{
    const int sel = blockIdx.z;
    const int m0 = blockIdx.x * 64;
    const int n0 = blockIdx.y * 64;
    const bool bbreg = (m0 >= 1024);

    const float* W    = sel ? (bbreg ? Wk1_w : Wk2_w) : (bbreg ? Wq1_w : Wq2_w);
    const float* bias = sel ? (bbreg ? Wk1_b : Wk2_b) : (bbreg ? Wq1_b : Wq2_b);

    const int tid = threadIdx.x;
    const int tx = tid & 15, ty = tid >> 4;

    __shared__ __align__(16) float As[16][68];
    __shared__ __align__(16) float Bs[16][68];

    float acc[4][4] = {};

    const int a_row = tid >> 2;
    const int a_k4  = (tid & 3) * 4;

    for (int kk = 0; kk < 128; kk += 16) {
        {
            int r = m0 + a_row;
            const float* src;
            if (r < 1024) {
                int b = r >> 9, h = (r >> 7) & 3, n = r & 127;
                src = p_m + (size_t)(b * 128 + n) * 512 + h * 128 + kk + a_k4;
            } else {
                int r2 = r - 1024;
                int b = r2 >> 6, h = (r2 >> 4) & 3, nn = r2 & 15;
                src = bb_m + (size_t)(b * 16 + nn) * 512 + h * 128 + kk + a_k4;
            }
            float4 av = *(const float4*)src;
            As[a_k4 + 0][a_row] = av.x;
            As[a_k4 + 1][a_row] = av.y;
            As[a_k4 + 2][a_row] = av.z;
            As[a_k4 + 3][a_row] = av.w;
        }
        {
            int c = tid >> 2, k4 = (tid & 3) * 4;
            float4 bv = *(const float4*)&W[(size_t)(n0 + c) * 128 + kk + k4];
            Bs[k4 + 0][c] = bv.x;
            Bs[k4 + 1][c] = bv.y;
            Bs[k4 + 2][c] = bv.z;
            Bs[k4 + 3][c] = bv.w;
        }
        __syncthreads();
#pragma unroll
        for (int kd = 0; kd < 16; ++kd) {
            float4 a4 = *(const float4*)&As[kd][ty * 4];
            float4 b4 = *(const float4*)&Bs[kd][tx * 4];
            float a[4] = {a4.x, a4.y, a4.z, a4.w};
            float bb[4] = {b4.x, b4.y, b4.z, b4.w};
#pragma unroll
            for (int r = 0; r < 4; ++r)
#pragma unroll
                for (int c = 0; c < 4; ++c) acc[r][c] += a[r] * bb[c];
        }
        __syncthreads();
    }

    float* outp = sel ? &g_pk[0][0][0][0] : &g_pq[0][0][0][0];
    float* outb = sel ? &g_bbK[0][0][0][0][0] : &g_bbQ[0][0][0][0][0];
#pragma unroll
    for (int r = 0; r < 4; ++r) {
        int rr = m0 + ty * 4 + r;
#pragma unroll
        for (int c = 0; c < 4; ++c) {
            int col = n0 + tx * 4 + c;
            float v = acc[r][c] + bias[col];
            if (rr < 1024) outp[(size_t)rr * 128 + col] = v;
            else           outb[(size_t)(rr - 1024) * 128 + col] = v;
        }
    }
}

// =====================================================================
// K3: tri-SAGP fusion -> FQ/FK + squared norms.
// =====================================================================
__global__ void __launch_bounds__(128) build_fqfk(const float* __restrict__ bb_c,
                                                  const float* __restrict__ p_c,
                                                  const int* __restrict__ b_seq)
{
    int r = blockIdx.x;                 // 0..1023 = (b,h,i)
    int b  = r >> 9;
    int hh = (r >> 7) & 3;
    int i  = r & 127;
    int t  = threadIdx.x;               // 128
    int w = t >> 5, lane = t & 31;
    const float eps = 1e-24f;

    __shared__ float rq[4][4];
    __shared__ float rk[4][4];

    int si = b_seq[b * 128 + i];
    float c3 = p_c[(size_t)(b * 128 + i) * 512 + hh * 128 + t];
    float p3 = 1.f / fmaxf(c3, eps);

    float nq[4], nk[4];

    {
        float m1 = g_qkv[0][0][b][hh][i][t];
        float c1 = g_qkv[1][0][b][hh][i][t];
        float m3 = g_pq[b][hh][i][t];
        float p1 = 1.f / fmaxf(c1, eps);
        float base_m = m1 * p1 + m3 * p3;
        float base_p = p1 + p3;
#pragma unroll
        for (int sb = 0; sb < 4; ++sb) {
            float m2 = g_bbQ[b][hh][sb][si][t];
            float c2 = bb_c[(size_t)((b * 4 + sb) * 4 + si) * 512 + hh * 128 + t];
            float p2 = 1.f / fmaxf(c2, eps);
            float cf = 1.f / (base_p + p2);
            float mf = cf * (base_m + m2 * p2);
            float cfc = fmaxf(cf, eps);
            g_FQ[b][hh][i][sb][t]       = mf;
            g_FQ[b][hh][i][sb][128 + t] = sqrtf(cfc);
            nq[sb] = mf * mf + cfc;
        }
    }
    {
        float m1 = g_qkv[0][1][b][hh][i][t];
        float c1 = g_qkv[1][1][b][hh][i][t];
        float m3 = g_pk[b][hh][i][t];
        float p1 = 1.f / fmaxf(c1, eps);
        float base_m = m1 * p1 + m3 * p3;
        float base_p = p1 + p3;
        int sj = si;
#pragma unroll
        for (int sa = 0; sa < 4; ++sa) {
            float m2 = g_bbK[b][hh][sj][sa][t];
            float c2 = bb_c[(size_t)((b * 4 + sj) * 4 + sa) * 512 + hh * 128 + t];
            float p2 = 1.f / fmaxf(c2, eps);
            float cf = 1.f / (base_p + p2);
            float mf = cf * (base_m + m2 * p2);
            float cfc = fmaxf(cf, eps);
            g_FK[b][hh][i][sa][t]       = mf;
            g_FK[b][hh][i][sa][128 + t] = sqrtf(cfc);
            nk[sa] = mf * mf + cfc;
        }
    }

#pragma unroll
    for (int sb = 0; sb < 4; ++sb) {
        float a = nq[sb];
        float c = nk[sb];
#pragma unroll
        for (int o = 16; o; o >>= 1) {
            a += __shfl_xor_sync(0xFFFFFFFFu, a, o);
            c += __shfl_xor_sync(0xFFFFFFFFu, c, o);
        }
        if (lane == 0) { rq[w][sb] = a; rk[w][sb] = c; }
    }
    __syncthreads();
    if (t < 4) {
        g_sqnq[b][hh][i][t] = rq[0][t] + rq[1][t] + rq[2][t] + rq[3][t];
    } else if (t < 8) {
        int sb = t - 4;
        g_sqnk[b][hh][i][sb] = rk[0][sb] + rk[1][sb] + rk[2][sb] + rk[3][sb];
    }
}

// =====================================================================
// K4a: bucketed score GEMM.
// =====================================================================
__global__ void __launch_bounds__(256) scores_kernel()
{
    const int bh = blockIdx.z;
    const int b = bh >> 2, h = bh & 3;
    const int si = blockIdx.y >> 2, sb = blockIdx.y & 3;
    const int ti = (blockIdx.x >> 2) * 32, tj = (blockIdx.x & 3) * 32;

    const int rbase = g_off[b][si], rcnt = g_off[b][si + 1] - rbase;
    const int cbase = g_off[b][sb], ccnt = g_off[b][sb + 1] - cbase;
    if (ti >= rcnt || tj >= ccnt) return;

    const int t = threadIdx.x;
    const int tx = t & 15, ty = t >> 4;

    __shared__ __align__(16) float As[32][33];
    __shared__ __align__(16) float Bs[32][33];
    __shared__ int rid[32], cid[32];
    __shared__ float sqr[32], sqc[32];

    if (t < 32) {
        int pr = ti + t; if (pr > rcnt - 1) pr = rcnt - 1;
        int id = g_perm[b][rbase + pr];
        rid[t] = id;
        sqr[t] = g_sqnq[b][h][id][sb];
    } else if (t < 64) {
        int u = t - 32;
        int pc = tj + u; if (pc > ccnt - 1) pc = ccnt - 1;
        int id = g_perm[b][cbase + pc];
        cid[u] = id;
        sqc[u] = g_sqnk[b][h][id][si];
    }
    __syncthreads();

    float acc[2][2] = {};
    const int lr = t >> 3;
    const int d4 = (t & 7) * 4;

    for (int kk = 0; kk < 256; kk += 32) {
        float4 av = *(const float4*)&g_FQ[b][h][rid[lr]][sb][kk + d4];
        As[d4 + 0][lr] = av.x; As[d4 + 1][lr] = av.y;
        As[d4 + 2][lr] = av.z; As[d4 + 3][lr] = av.w;
        float4 bv = *(const float4*)&g_FK[b][h][cid[lr]][si][kk + d4];
        Bs[d4 + 0][lr] = bv.x; Bs[d4 + 1][lr] = bv.y;
        Bs[d4 + 2][lr] = bv.z; Bs[d4 + 3][lr] = bv.w;
        __syncthreads();
#pragma unroll
        for (int d = 0; d < 32; ++d) {
            float a0 = As[d][ty * 2], a1 = As[d][ty * 2 + 1];
            float b0 = Bs[d][tx * 2], b1 = Bs[d][tx * 2 + 1];
            acc[0][0] += a0 * b0; acc[0][1] += a0 * b1;
            acc[1][0] += a1 * b0; acc[1][1] += a1 * b1;
        }
        __syncthreads();
    }

    const float scale = 0.08838834764831845f;
#pragma unroll
    for (int r = 0; r < 2; ++r) {
        int pr = ti + ty * 2 + r;
        if (pr >= rcnt) continue;
#pragma unroll
        for (int c = 0; c < 2; ++c) {
            int pc = tj + tx * 2 + c;
            if (pc >= ccnt) continue;
            float w2v = sqr[ty * 2 + r] + sqc[tx * 2 + c] - 2.f * acc[r][c];
            g_scs[bh][rbase + pr][cbase + pc] = -w2v * scale;
        }
    }
}

// =====================================================================
// K4b: softmax + probs scatter + context.
// =====================================================================
__global__ void __launch_bounds__(256) softmax_ctx_kernel(float* __restrict__ out_probs)
{
    const int blk = blockIdx.x;
    const int bh = blk >> 4;
    const int b = bh >> 2, h = bh & 3;
    const int i0 = (blk & 15) * 8;
    const int t = threadIdx.x;
    const int lane = t & 31;

    __shared__ float sc[8 * 128];
    __shared__ int perm_s[128];
    __shared__ float ctxm[1024], ctxc[1024];

    if (t < 128) perm_s[t] = g_perm[b][t];
    {
        const float4* src = (const float4*)&g_scs[bh][i0][0];
        ((float4*)sc)[t] = src[t];
    }
    __syncthreads();

    {
        int w = t >> 5;
        float4* row = (float4*)(sc + w * 128);
        float4 x4 = row[lane];
        float m = fmaxf(fmaxf(x4.x, x4.y), fmaxf(x4.z, x4.w));
#pragma unroll
        for (int o = 16; o; o >>= 1) m = fmaxf(m, __shfl_xor_sync(0xFFFFFFFFu, m, o));
        float e0 = expf(x4.x - m), e1 = expf(x4.y - m);
        float e2 = expf(x4.z - m), e3 = expf(x4.w - m);
        float s = e0 + e1 + e2 + e3;
#pragma unroll
        for (int o = 16; o; o >>= 1) s += __shfl_xor_sync(0xFFFFFFFFu, s, o);
        float inv = 1.f / s;
        float4 p4 = make_float4(e0 * inv, e1 * inv, e2 * inv, e3 * inv);
        row[lane] = p4;
        int i = perm_s[i0 + w];
        float* op = out_probs + (size_t)(bh * 128 + i) * 128;
        op[perm_s[4 * lane + 0]] = p4.x;
        op[perm_s[4 * lane + 1]] = p4.y;
        op[perm_s[4 * lane + 2]] = p4.z;
        op[perm_s[4 * lane + 3]] = p4.w;
    }
    __syncthreads();

    {
        int k = t & 127, half = t >> 7;
        float am[8] = {}, ac[8] = {};
        const float* v1 = &g_qkv[0][2][b][h][0][0];
        const float* v2 = &g_qkv[1][2][b][h][0][0];
        int j0 = half * 64;
#pragma unroll 4
        for (int pj = j0; pj < j0 + 64; ++pj) {
            int jv = perm_s[pj];
            float x1 = v1[(size_t)jv * 128 + k];
            float x2 = v2[(size_t)jv * 128 + k];
#pragma unroll
            for (int il = 0; il < 8; ++il) {
                float p = sc[il * 128 + pj];
                am[il] += p * x1;
                ac[il] += p * p * x2;
            }
        }
        if (half == 0) {
#pragma unroll
            for (int il = 0; il < 8; ++il) {
                ctxm[il * 128 + k] = am[il];
                ctxc[il * 128 + k] = ac[il];
            }
        }
        __syncthreads();
        if (half == 1) {
#pragma unroll
            for (int il = 0; il < 8; ++il) {
                int i = perm_s[i0 + il];
                g_ctx[0][b][i][h * 128 + k] = am[il] + ctxm[il * 128 + k];
                g_ctx[1][b][i][h * 128 + k] = ac[il] + ctxc[il * 128 + k];
            }
        }
    }
}

// =====================================================================
// K5: output GEMM + bias + residual.
// =====================================================================
__global__ void __launch_bounds__(128) outgemm_kernel(
    const float* __restrict__ mean_w, const float* __restrict__ mean_b,
    const float* __restrict__ cov_w,  const float* __restrict__ cov_b,
    const float* __restrict__ x_m,    const float* __restrict__ x_c)
{
    int z = blockIdx.z;
    const float* W     = z ? cov_w  : mean_w;
    const float* bias  = z ? cov_b  : mean_b;
    const float* resid = z ? x_c    : x_m;
    const float* A = &g_ctx[z][0][0][0];
    float* out = &g_tmp[z][0][0][0];

    const int m0 = blockIdx.x * 32;
    const int n0 = blockIdx.y * 64;
    const int tid = threadIdx.x;
    const int tx = tid & 15, ty = tid >> 4;

    __shared__ __align__(16) float As[16][36];
    __shared__ __align__(16) float Bs[16][68];
    float acc[4][4] = {};

    const int a_row = tid >> 2;
    const int a_k4  = (tid & 3) * 4;

    for (int kk = 0; kk < 512; kk += 16) {
        float4 av = *(const float4*)&A[(size_t)(m0 + a_row) * 512 + kk + a_k4];
        As[a_k4 + 0][a_row] = av.x;
        As[a_k4 + 1][a_row] = av.y;
        As[a_k4 + 2][a_row] = av.z;
        As[a_k4 + 3][a_row] = av.w;
        {
            int c = tid >> 2, k4 = (tid & 3) * 4;
            float4 bv = *(const float4*)&W[(size_t)(n0 + c) * 512 + kk + k4];
            Bs[k4 + 0][c] = bv.x; Bs[k4 + 1][c] = bv.y;
            Bs[k4 + 2][c] = bv.z; Bs[k4 + 3][c] = bv.w;
            int c2 = c + 32;
            float4 bw = *(const float4*)&W[(size_t)(n0 + c2) * 512 + kk + k4];
            Bs[k4 + 0][c2] = bw.x; Bs[k4 + 1][c2] = bw.y;
            Bs[k4 + 2][c2] = bw.z; Bs[k4 + 3][c2] = bw.w;
        }
        __syncthreads();
#pragma unroll
        for (int kd = 0; kd < 16; ++kd) {
            float4 a4 = *(const float4*)&As[kd][ty * 4];
            float4 b4 = *(const float4*)&Bs[kd][tx * 4];
            float a[4] = {a4.x, a4.y, a4.z, a4.w};
            float bb[4] = {b4.x, b4.y, b4.z, b4.w};
#pragma unroll
            for (int r = 0; r < 4; ++r)
#pragma unroll
                for (int c = 0; c < 4; ++c) acc[r][c] += a[r] * bb[c];
        }
        __syncthreads();
    }

#pragma unroll
    for (int r = 0; r < 4; ++r) {
        int m = m0 + ty * 4 + r;
#pragma unroll
        for (int c = 0; c < 4; ++c) {
            int d = n0 + tx * 4 + c;
            out[(size_t)m * 512 + d] = acc[r][c] + bias[d] + resid[(size_t)m * 512 + d];
        }
    }
}

// =====================================================================
// K6: LayerNorm -> d_out
// =====================================================================
__global__ void ln_kernel(const float* __restrict__ ln_w, const float* __restrict__ ln_b,
                          float* __restrict__ d_out_f)
{
    int blk = blockIdx.x;
    int z = blk >> 8;
    int row = blk & 255;
    int tid = threadIdx.x;
    int w = tid >> 5, lane = tid & 31;
    __shared__ float red[8];

    const float* x = &g_tmp[z][0][0][0] + (size_t)row * 512;
    float a0 = x[tid], a1 = x[tid + 256];

    float s = a0 + a1;
#pragma unroll
    for (int o = 16; o; o >>= 1) s += __shfl_xor_sync(0xFFFFFFFFu, s, o);
    if (lane == 0) red[w] = s;
    __syncthreads();
    if (tid == 0) { float t2 = 0.f; for (int q = 0; q < 8; ++q) t2 += red[q]; red[0] = t2; }
    __syncthreads();
    float mean = red[0] * (1.f / 512.f);
    float d0 = a0 - mean, d1 = a1 - mean;
    float v = d0 * d0 + d1 * d1;
    __syncthreads();
#pragma unroll
    for (int o = 16; o; o >>= 1) v += __shfl_xor_sync(0xFFFFFFFFu, v, o);
    if (lane == 0) red[w] = v;
    __syncthreads();
    if (tid == 0) { float t2 = 0.f; for (int q = 0; q < 8; ++q) t2 += red[q]; red[0] = t2; }
    __syncthreads();
    float var = red[0] * (1.f / 512.f);
    float inv = 1.f / sqrtf(var + 1e-12f);

    float* o = d_out_f + (size_t)z * 131072 + (size_t)row * 512;
    o[tid]       = d0 * inv * ln_w[tid]       + ln_b[tid];
    o[tid + 256] = d1 * inv * ln_w[tid + 256] + ln_b[tid + 256];
}

// =====================================================================
extern "C" void kernel_launch(void* const* d_in, const int* in_sizes, int n_in,
                              void* d_out, int out_size)
{
    const float* x_m    = (const float*)d_in[0];
    const float* x_c    = (const float*)d_in[1];
    const float* b_m    = (const float*)d_in[2];
    const float* b_c    = (const float*)d_in[3];
    const float* bb_m   = (const float*)d_in[4];
    const float* bb_c   = (const float*)d_in[5];
    const float* p_m    = (const float*)d_in[6];
    const float* p_c    = (const float*)d_in[7];
    const float* W_xm   = (const float*)d_in[8];
    const float* W_xc   = (const float*)d_in[9];
    const float* W_bm   = (const float*)d_in[10];
    const float* W_bc   = (const float*)d_in[11];
    const float* Wq1_w  = (const float*)d_in[12];
    const float* Wq1_b  = (const float*)d_in[13];
    const float* Wq2_w  = (const float*)d_in[14];
    const float* Wq2_b  = (const float*)d_in[15];
    const float* Wk1_w  = (const float*)d_in[16];
    const float* Wk1_b  = (const float*)d_in[17];
    const float* Wk2_w  = (const float*)d_in[18];
    const float* Wk2_b  = (const float*)d_in[19];
    const float* mean_w = (const float*)d_in[20];
    const float* mean_b = (const float*)d_in[21];
    const float* cov_w  = (const float*)d_in[22];
    const float* cov_b  = (const float*)d_in[23];
    const float* ln_w   = (const float*)d_in[24];
    const float* ln_b   = (const float*)d_in[25];
    const int*   b_seq  = (const int*)d_in[26];

    float* out = (float*)d_out;
    float* out_probs = out + 262144;   // [mean | cov | probs]

    cudaFuncSetAttribute(proj_wmma2, cudaFuncAttributeMaxDynamicSharedMemorySize, PROJ_SMEM);

    // launch order keeps proj at ncu capture slot (-s 5 -c 1)
    prep_x<<<512, 256>>>(x_m, b_m, x_c, b_c);
    prep_w<<<dim3(16, 16, 6), 256>>>(W_xm, W_bm, W_xc, W_bc, 0);
    prep_w<<<dim3(16, 16, 6), 256>>>(W_xm, W_bm, W_xc, W_bc, 6);
    perm_kernel<<<2, 128>>>(b_seq);
    linqk_kernel<<<dim3(18, 2, 2), 256>>>(p_m, bb_m,
                                          Wq1_w, Wq1_b, Wq2_w, Wq2_b,
                                          Wk1_w, Wk1_b, Wk2_w, Wk2_b);
    proj_wmma2<<<dim3(2, 24, 2), 256, PROJ_SMEM>>>();
    build_fqfk<<<1024, 128>>>(bb_c, p_c, b_seq);
    scores_kernel<<<dim3(16, 16, 8), 256>>>();
    softmax_ctx_kernel<<<128, 256>>>(out_probs);
    outgemm_kernel<<<dim3(8, 8, 2), 128>>>(mean_w, mean_b, cov_w, cov_b, x_m, x_c);
    ln_kernel<<<512, 256>>>(ln_w, ln_b, out);
}

// round 13
// speedup vs baseline: 2.1139x; 1.1010x over previous
#include <cuda_runtime.h>
#include <cuda_bf16.h>
#include <mma.h>
#include <stdint.h>
#include <cstdint>
#include <math.h>

using namespace nvcuda;

#define BATCH 2
#define SEQ 128
#define NH 4
#define DKK 128
#define DD 512
#define NBB 4

// ---------------- scratch (device globals; no allocation allowed) ----------------
__device__ float g_qkv[2][3][BATCH][NH][SEQ][DKK]; // [fam(m/c)][q/k/v][b][h][n][k]
__device__ float g_bbQ[BATCH][NH][NBB][NBB][DKK];
__device__ float g_bbK[BATCH][NH][NBB][NBB][DKK];
__device__ float g_pq[BATCH][NH][SEQ][DKK];
__device__ float g_pk[BATCH][NH][SEQ][DKK];
__device__ float g_FQ[BATCH][NH][SEQ][NBB][2*DKK]; // [m(0..127) | sqrt(c)(128..255)]
__device__ float g_FK[BATCH][NH][SEQ][NBB][2*DKK];
__device__ float g_sqnq[BATCH][NH][SEQ][NBB];
__device__ float g_sqnk[BATCH][NH][SEQ][NBB];
__device__ int   g_perm[BATCH][SEQ];
__device__ int   g_off[BATCH][NBB + 1];
__device__ float g_scs[BATCH*NH][SEQ][SEQ];
__device__ float g_ctx[2][BATCH][SEQ][DD];
__device__ float g_tmp[2][BATCH][SEQ][DD];

// bf16 hi/lo operand copies (pre-split, W pre-transposed)
__device__ __nv_bfloat16 g_Xh[4][256][512];   // [fam*2+pair][m][k]
__device__ __nv_bfloat16 g_Xl[4][256][512];
__device__ __nv_bfloat16 g_WTh[12][512][512]; // [(fam*2+pair)*3+s][hk][k]  (transposed)
__device__ __nv_bfloat16 g_WTl[12][512][512];

// =====================================================================
// K_pre: fused prep_x + prep_w + perm. grid 3586 x 256 thr.
//   blocks [0,512):       X convert (hi/lo split)
//   blocks [512,3584):    W transpose+convert, mi = (blk-512)/256
//   blocks [3584,3586):   ballot-based counting sort per batch
// =====================================================================
__global__ void __launch_bounds__(256) prep_all(
    const float* __restrict__ x_m, const float* __restrict__ b_m,
    const float* __restrict__ x_c, const float* __restrict__ b_c,
    const float* __restrict__ Wxm, const float* __restrict__ Wbm,
    const float* __restrict__ Wxc, const float* __restrict__ Wbc,
    const int* __restrict__ b_seq)
{
    const int blk = blockIdx.x;
    const int t = threadIdx.x;

    if (blk < 512) {
        // ---- X convert ----
        int idx = blk * 256 + t;                    // 0..131071 float4 groups
        int a = idx >> 15;
        int r = idx & 32767;
        const float* src = (a == 0) ? x_m : (a == 1) ? b_m : (a == 2) ? x_c : b_c;
        float4 v = ((const float4*)src)[r];
        __nv_bfloat16* oh = &g_Xh[0][0][0] + (size_t)a * 131072 + (size_t)r * 4;
        __nv_bfloat16* ol = &g_Xl[0][0][0] + (size_t)a * 131072 + (size_t)r * 4;
        float vv[4];
        vv[0] = v.x; vv[1] = v.y; vv[2] = v.z; vv[3] = v.w;
#pragma unroll
        for (int e = 0; e < 4; ++e) {
            __nv_bfloat16 hi = __float2bfloat16(vv[e]);
            oh[e] = hi;
            ol[e] = __float2bfloat16(vv[e] - __bfloat162float(hi));
        }
    } else if (blk < 3584) {
        // ---- W transpose + convert ----
        int idx2 = blk - 512;                       // 0..3071
        int mi = idx2 >> 8;                         // 0..11
        int rem = idx2 & 255;
        int hk0 = (rem >> 4) * 32;
        int d0  = (rem & 15) * 32;
        int fam = mi / 6;
        int pair = (mi / 3) & 1;
        int s = mi % 3;
        const float* src = (fam == 0) ? (pair == 0 ? Wxm : Wbm)
                                      : (pair == 0 ? Wxc : Wbc);
        src += (size_t)s * 262144;

        __shared__ float tile[32][33];
        int r = t >> 3, c4 = (t & 7) * 4;
        float4 v = *(const float4*)&src[(size_t)(d0 + r) * 512 + hk0 + c4];
        tile[r][c4 + 0] = v.x; tile[r][c4 + 1] = v.y;
        tile[r][c4 + 2] = v.z; tile[r][c4 + 3] = v.w;
        __syncthreads();

        __nv_bfloat16* oh = &g_WTh[0][0][0] + (size_t)mi * 262144 + (size_t)(hk0 + r) * 512 + d0 + c4;
        __nv_bfloat16* ol = &g_WTl[0][0][0] + (size_t)mi * 262144 + (size_t)(hk0 + r) * 512 + d0 + c4;
#pragma unroll
        for (int e = 0; e < 4; ++e) {
            float f = tile[c4 + e][r];
            __nv_bfloat16 hi = __float2bfloat16(f);
            oh[e] = hi;
            ol[e] = __float2bfloat16(f - __bfloat162float(hi));
        }
    } else {
        // ---- ballot counting sort (1 block per batch) ----
        int b = blk - 3584;
        __shared__ int wcnt[4][4];                  // [warp][key]
        int w = t >> 5, lane = t & 31;
        int key = 0, rank_w = 0;
        if (t < 128) {
            key = b_seq[b * 128 + t];
            unsigned b0 = __ballot_sync(0xFFFFFFFFu, key == 0);
            unsigned b1 = __ballot_sync(0xFFFFFFFFu, key == 1);
            unsigned b2 = __ballot_sync(0xFFFFFFFFu, key == 2);
            unsigned b3 = __ballot_sync(0xFFFFFFFFu, key == 3);
            if (lane == 0) {
                wcnt[w][0] = __popc(b0); wcnt[w][1] = __popc(b1);
                wcnt[w][2] = __popc(b2); wcnt[w][3] = __popc(b3);
            }
            unsigned mymask = (key == 0) ? b0 : (key == 1) ? b1 : (key == 2) ? b2 : b3;
            rank_w = __popc(mymask & ((1u << lane) - 1u));
        }
        __syncthreads();
        if (t < 128) {
            int cnt[4];
#pragma unroll
            for (int k = 0; k < 4; ++k)
                cnt[k] = wcnt[0][k] + wcnt[1][k] + wcnt[2][k] + wcnt[3][k];
            int off = 0;
#pragma unroll
            for (int k = 0; k < 4; ++k) if (k < key) off += cnt[k];
            int pre = 0;
#pragma unroll
            for (int w2 = 0; w2 < 4; ++w2) if (w2 < w) pre += wcnt[w2][key];
            g_perm[b][off + pre + rank_w] = t;
            if (t < 5) {
                int o = 0;
                for (int k = 0; k < t; ++k) o += cnt[k];
                g_off[b][t] = o;
            }
        }
    }
}

// =====================================================================
// K_gemm: fused proj (wmma, blocks [0,96)) + linqk (blocks [96,168)).
// 256 thr; dynamic smem 55296B (proj), static ~8.7KB (linqk).
// =====================================================================
#define PROJ_SMEM 55296

__global__ void __launch_bounds__(256) gemm_fused(
    const float* __restrict__ p_m,  const float* __restrict__ bb_m,
    const float* __restrict__ Wq1_w, const float* __restrict__ Wq1_b,
    const float* __restrict__ Wq2_w, const float* __restrict__ Wq2_b,
    const float* __restrict__ Wk1_w, const float* __restrict__ Wk1_b,
    const float* __restrict__ Wk2_w, const float* __restrict__ Wk2_b)
{
    const int t = threadIdx.x;

    if (blockIdx.x < 96) {
        // ================= proj path =================
        extern __shared__ char ds[];
        __nv_bfloat16* Ah = (__nv_bfloat16*)ds;       // [128][72]
        __nv_bfloat16* Al = Ah + 128 * 72;
        __nv_bfloat16* Bh = Al + 128 * 72;            // [64][72]
        __nv_bfloat16* Bl = Bh + 64 * 72;

        const int u = blockIdx.x;
        const int fam = u / 48;
        const int v = u % 48;
        const int m0 = (v / 24) * 128;
        const int n0g = (v % 24) * 64;
        const int s_idx = n0g >> 9;
        const int cbase = n0g & 511;

        const int w = t >> 5;
        const int wm = (w >> 1) * 32;
        const int wn = (w & 1) * 32;

        wmma::fragment<wmma::accumulator, 16, 16, 16, float> acc[2][2];
#pragma unroll
        for (int r = 0; r < 2; ++r)
#pragma unroll
            for (int c = 0; c < 2; ++c) wmma::fill_fragment(acc[r][c], 0.f);

        uint4 pf[12];

        // prefetch chunk 0
        {
            const int ai = fam * 2;
            const int mi = ai * 3 + s_idx;
            const __nv_bfloat16* Axh = &g_Xh[ai][m0][0];
            const __nv_bfloat16* Axl = &g_Xl[ai][m0][0];
            const __nv_bfloat16* Bxh = &g_WTh[0][0][0] + (size_t)mi * 262144 + (size_t)cbase * 512;
            const __nv_bfloat16* Bxl = &g_WTl[0][0][0] + (size_t)mi * 262144 + (size_t)cbase * 512;
#pragma unroll
            for (int q = 0; q < 4; ++q) {
                int s = t + 256 * q;
                int r = s >> 3, kb = s & 7;
                pf[q]     = *(const uint4*)(Axh + (size_t)r * 512 + kb * 8);
                pf[4 + q] = *(const uint4*)(Axl + (size_t)r * 512 + kb * 8);
            }
#pragma unroll
            for (int q = 0; q < 2; ++q) {
                int s = t + 256 * q;
                int r = s >> 3, kb = s & 7;
                pf[8 + q]  = *(const uint4*)(Bxh + (size_t)r * 512 + kb * 8);
                pf[10 + q] = *(const uint4*)(Bxl + (size_t)r * 512 + kb * 8);
            }
        }

        for (int c = 0; c < 16; ++c) {
#pragma unroll
            for (int q = 0; q < 4; ++q) {
                int s = t + 256 * q;
                int r = s >> 3, kb = s & 7;
                *(uint4*)((char*)Ah + (size_t)r * 144 + kb * 16) = pf[q];
                *(uint4*)((char*)Al + (size_t)r * 144 + kb * 16) = pf[4 + q];
            }
#pragma unroll
            for (int q = 0; q < 2; ++q) {
                int s = t + 256 * q;
                int r = s >> 3, kb = s & 7;
                *(uint4*)((char*)Bh + (size_t)r * 144 + kb * 16) = pf[8 + q];
                *(uint4*)((char*)Bl + (size_t)r * 144 + kb * 16) = pf[10 + q];
            }
            __syncthreads();

            if (c + 1 < 16) {
                const int nx = c + 1;
                const int pair = nx >> 3;
                const int kk = (nx & 7) * 64;
                const int ai = fam * 2 + pair;
                const int mi = ai * 3 + s_idx;
                const __nv_bfloat16* Axh = &g_Xh[ai][m0][kk];
                const __nv_bfloat16* Axl = &g_Xl[ai][m0][kk];
                const __nv_bfloat16* Bxh = &g_WTh[0][0][0] + (size_t)mi * 262144 + (size_t)cbase * 512 + kk;
                const __nv_bfloat16* Bxl = &g_WTl[0][0][0] + (size_t)mi * 262144 + (size_t)cbase * 512 + kk;
#pragma unroll
                for (int q = 0; q < 4; ++q) {
                    int s = t + 256 * q;
                    int r = s >> 3, kb = s & 7;
                    pf[q]     = *(const uint4*)(Axh + (size_t)r * 512 + kb * 8);
                    pf[4 + q] = *(const uint4*)(Axl + (size_t)r * 512 + kb * 8);
                }
#pragma unroll
                for (int q = 0; q < 2; ++q) {
                    int s = t + 256 * q;
                    int r = s >> 3, kb = s & 7;
                    pf[8 + q]  = *(const uint4*)(Bxh + (size_t)r * 512 + kb * 8);
                    pf[10 + q] = *(const uint4*)(Bxl + (size_t)r * 512 + kb * 8);
                }
            }

#pragma unroll
            for (int ks = 0; ks < 4; ++ks) {
                wmma::fragment<wmma::matrix_a, 16, 16, 16, __nv_bfloat16, wmma::row_major> ah[2], al[2];
                wmma::fragment<wmma::matrix_b, 16, 16, 16, __nv_bfloat16, wmma::col_major> bh[2], bl[2];
#pragma unroll
                for (int r = 0; r < 2; ++r) {
                    wmma::load_matrix_sync(ah[r], Ah + (wm + 16 * r) * 72 + ks * 16, 72);
                    wmma::load_matrix_sync(al[r], Al + (wm + 16 * r) * 72 + ks * 16, 72);
                }
#pragma unroll
                for (int cb = 0; cb < 2; ++cb) {
                    wmma::load_matrix_sync(bh[cb], Bh + (wn + 16 * cb) * 72 + ks * 16, 72);
                    wmma::load_matrix_sync(bl[cb], Bl + (wn + 16 * cb) * 72 + ks * 16, 72);
                }
#pragma unroll
                for (int r = 0; r < 2; ++r)
#pragma unroll
                    for (int cb = 0; cb < 2; ++cb) {
                        wmma::mma_sync(acc[r][cb], ah[r], bh[cb], acc[r][cb]);
                        wmma::mma_sync(acc[r][cb], ah[r], bl[cb], acc[r][cb]);
                        wmma::mma_sync(acc[r][cb], al[r], bh[cb], acc[r][cb]);
                    }
            }
            __syncthreads();
        }

        const int h_idx = cbase >> 7;
        const int k0 = cbase & 127;
        const int b = m0 >> 7;
        float* outp = &g_qkv[fam][s_idx][b][h_idx][0][k0];

#pragma unroll
        for (int r = 0; r < 2; ++r)
#pragma unroll
            for (int cb = 0; cb < 2; ++cb) {
                if (fam == 1) {
#pragma unroll
                    for (int e = 0; e < acc[r][cb].num_elements; ++e) {
                        float vv = acc[r][cb].x[e];
                        acc[r][cb].x[e] = (vv > 0.f) ? (vv + 1.f) : expf(vv);
                    }
                }
                wmma::store_matrix_sync(&outp[(size_t)(wm + 16 * r) * 128 + wn + 16 * cb],
                                        acc[r][cb], 128, wmma::mem_row_major);
            }
    } else {
        // ================= linqk path =================
        const int u2 = blockIdx.x - 96;            // 0..71
        const int sel = u2 / 36;
        const int rr2 = u2 % 36;
        const int m0 = (rr2 >> 1) * 64;            // 0..1151
        const int n0 = (rr2 & 1) * 64;
        const bool bbreg = (m0 >= 1024);

        const float* W    = sel ? (bbreg ? Wk1_w : Wk2_w) : (bbreg ? Wq1_w : Wq2_w);
        const float* bias = sel ? (bbreg ? Wk1_b : Wk2_b) : (bbreg ? Wq1_b : Wq2_b);

        const int tx = t & 15, ty = t >> 4;

        __shared__ __align__(16) float As[16][68];
        __shared__ __align__(16) float Bs[16][68];

        float acc[4][4] = {};

        const int a_row = t >> 2;
        const int a_k4  = (t & 3) * 4;

        for (int kk = 0; kk < 128; kk += 16) {
            {
                int r = m0 + a_row;
                const float* src;
                if (r < 1024) {
                    int b = r >> 9, h = (r >> 7) & 3, n = r & 127;
                    src = p_m + (size_t)(b * 128 + n) * 512 + h * 128 + kk + a_k4;
                } else {
                    int r2 = r - 1024;
                    int b = r2 >> 6, h = (r2 >> 4) & 3, nn = r2 & 15;
                    src = bb_m + (size_t)(b * 16 + nn) * 512 + h * 128 + kk + a_k4;
                }
                float4 av = *(const float4*)src;
                As[a_k4 + 0][a_row] = av.x;
                As[a_k4 + 1][a_row] = av.y;
                As[a_k4 + 2][a_row] = av.z;
                As[a_k4 + 3][a_row] = av.w;
            }
            {
                int c = t >> 2, k4 = (t & 3) * 4;
                float4 bv = *(const float4*)&W[(size_t)(n0 + c) * 128 + kk + k4];
                Bs[k4 + 0][c] = bv.x;
                Bs[k4 + 1][c] = bv.y;
                Bs[k4 + 2][c] = bv.z;
                Bs[k4 + 3][c] = bv.w;
            }
            __syncthreads();
#pragma unroll
            for (int kd = 0; kd < 16; ++kd) {
                float4 a4 = *(const float4*)&As[kd][ty * 4];
                float4 b4 = *(const float4*)&Bs[kd][tx * 4];
                float a[4] = {a4.x, a4.y, a4.z, a4.w};
                float bb[4] = {b4.x, b4.y, b4.z, b4.w};
#pragma unroll
                for (int r = 0; r < 4; ++r)
#pragma unroll
                    for (int c = 0; c < 4; ++c) acc[r][c] += a[r] * bb[c];
            }
            __syncthreads();
        }

        float* outp = sel ? &g_pk[0][0][0][0] : &g_pq[0][0][0][0];
        float* outb = sel ? &g_bbK[0][0][0][0][0] : &g_bbQ[0][0][0][0][0];
#pragma unroll
        for (int r = 0; r < 4; ++r) {
            int rr = m0 + ty * 4 + r;
#pragma unroll
            for (int c = 0; c < 4; ++c) {
                int col = n0 + tx * 4 + c;
                float v = acc[r][c] + bias[col];
                if (rr < 1024) outp[(size_t)rr * 128 + col] = v;
                else           outb[(size_t)(rr - 1024) * 128 + col] = v;
            }
        }
    }
}

// =====================================================================
// K3: tri-SAGP fusion -> FQ/FK + squared norms.
// =====================================================================
__global__ void __launch_bounds__(128) build_fqfk(const float* __restrict__ bb_c,
                                                  const float* __restrict__ p_c,
                                                  const int* __restrict__ b_seq)
{
    int r = blockIdx.x;                 // 0..1023 = (b,h,i)
    int b  = r >> 9;
    int hh = (r >> 7) & 3;
    int i  = r & 127;
    int t  = threadIdx.x;               // 128
    int w = t >> 5, lane = t & 31;
    const float eps = 1e-24f;

    __shared__ float rq[4][4];
    __shared__ float rk[4][4];

    int si = b_seq[b * 128 + i];
    float c3 = p_c[(size_t)(b * 128 + i) * 512 + hh * 128 + t];
    float p3 = 1.f / fmaxf(c3, eps);

    float nq[4], nk[4];

    {
        float m1 = g_qkv[0][0][b][hh][i][t];
        float c1 = g_qkv[1][0][b][hh][i][t];
        float m3 = g_pq[b][hh][i][t];
        float p1 = 1.f / fmaxf(c1, eps);
        float base_m = m1 * p1 + m3 * p3;
        float base_p = p1 + p3;
#pragma unroll
        for (int sb = 0; sb < 4; ++sb) {
            float m2 = g_bbQ[b][hh][sb][si][t];
            float c2 = bb_c[(size_t)((b * 4 + sb) * 4 + si) * 512 + hh * 128 + t];
            float p2 = 1.f / fmaxf(c2, eps);
            float cf = 1.f / (base_p + p2);
            float mf = cf * (base_m + m2 * p2);
            float cfc = fmaxf(cf, eps);
            g_FQ[b][hh][i][sb][t]       = mf;
            g_FQ[b][hh][i][sb][128 + t] = sqrtf(cfc);
            nq[sb] = mf * mf + cfc;
        }
    }
    {
        float m1 = g_qkv[0][1][b][hh][i][t];
        float c1 = g_qkv[1][1][b][hh][i][t];
        float m3 = g_pk[b][hh][i][t];
        float p1 = 1.f / fmaxf(c1, eps);
        float base_m = m1 * p1 + m3 * p3;
        float base_p = p1 + p3;
        int sj = si;
#pragma unroll
        for (int sa = 0; sa < 4; ++sa) {
            float m2 = g_bbK[b][hh][sj][sa][t];
            float c2 = bb_c[(size_t)((b * 4 + sj) * 4 + sa) * 512 + hh * 128 + t];
            float p2 = 1.f / fmaxf(c2, eps);
            float cf = 1.f / (base_p + p2);
            float mf = cf * (base_m + m2 * p2);
            float cfc = fmaxf(cf, eps);
            g_FK[b][hh][i][sa][t]       = mf;
            g_FK[b][hh][i][sa][128 + t] = sqrtf(cfc);
            nk[sa] = mf * mf + cfc;
        }
    }

#pragma unroll
    for (int sb = 0; sb < 4; ++sb) {
        float a = nq[sb];
        float c = nk[sb];
#pragma unroll
        for (int o = 16; o; o >>= 1) {
            a += __shfl_xor_sync(0xFFFFFFFFu, a, o);
            c += __shfl_xor_sync(0xFFFFFFFFu, c, o);
        }
        if (lane == 0) { rq[w][sb] = a; rk[w][sb] = c; }
    }
    __syncthreads();
    if (t < 4) {
        g_sqnq[b][hh][i][t] = rq[0][t] + rq[1][t] + rq[2][t] + rq[3][t];
    } else if (t < 8) {
        int sb = t - 4;
        g_sqnk[b][hh][i][sb] = rk[0][sb] + rk[1][sb] + rk[2][sb] + rk[3][sb];
    }
}

// =====================================================================
// K4a: bucketed score GEMM.
// =====================================================================
__global__ void __launch_bounds__(256) scores_kernel()
{
    const int bh = blockIdx.z;
    const int b = bh >> 2, h = bh & 3;
    const int si = blockIdx.y >> 2, sb = blockIdx.y & 3;
    const int ti = (blockIdx.x >> 2) * 32, tj = (blockIdx.x & 3) * 32;

    const int rbase = g_off[b][si], rcnt = g_off[b][si + 1] - rbase;
    const int cbase = g_off[b][sb], ccnt = g_off[b][sb + 1] - cbase;
    if (ti >= rcnt || tj >= ccnt) return;

    const int t = threadIdx.x;
    const int tx = t & 15, ty = t >> 4;

    __shared__ __align__(16) float As[32][33];
    __shared__ __align__(16) float Bs[32][33];
    __shared__ int rid[32], cid[32];
    __shared__ float sqr[32], sqc[32];

    if (t < 32) {
        int pr = ti + t; if (pr > rcnt - 1) pr = rcnt - 1;
        int id = g_perm[b][rbase + pr];
        rid[t] = id;
        sqr[t] = g_sqnq[b][h][id][sb];
    } else if (t < 64) {
        int u = t - 32;
        int pc = tj + u; if (pc > ccnt - 1) pc = ccnt - 1;
        int id = g_perm[b][cbase + pc];
        cid[u] = id;
        sqc[u] = g_sqnk[b][h][id][si];
    }
    __syncthreads();

    float acc[2][2] = {};
    const int lr = t >> 3;
    const int d4 = (t & 7) * 4;

    for (int kk = 0; kk < 256; kk += 32) {
        float4 av = *(const float4*)&g_FQ[b][h][rid[lr]][sb][kk + d4];
        As[d4 + 0][lr] = av.x; As[d4 + 1][lr] = av.y;
        As[d4 + 2][lr] = av.z; As[d4 + 3][lr] = av.w;
        float4 bv = *(const float4*)&g_FK[b][h][cid[lr]][si][kk + d4];
        Bs[d4 + 0][lr] = bv.x; Bs[d4 + 1][lr] = bv.y;
        Bs[d4 + 2][lr] = bv.z; Bs[d4 + 3][lr] = bv.w;
        __syncthreads();
#pragma unroll
        for (int d = 0; d < 32; ++d) {
            float a0 = As[d][ty * 2], a1 = As[d][ty * 2 + 1];
            float b0 = Bs[d][tx * 2], b1 = Bs[d][tx * 2 + 1];
            acc[0][0] += a0 * b0; acc[0][1] += a0 * b1;
            acc[1][0] += a1 * b0; acc[1][1] += a1 * b1;
        }
        __syncthreads();
    }

    const float scale = 0.08838834764831845f;
#pragma unroll
    for (int r = 0; r < 2; ++r) {
        int pr = ti + ty * 2 + r;
        if (pr >= rcnt) continue;
#pragma unroll
        for (int c = 0; c < 2; ++c) {
            int pc = tj + tx * 2 + c;
            if (pc >= ccnt) continue;
            float w2v = sqr[ty * 2 + r] + sqc[tx * 2 + c] - 2.f * acc[r][c];
            g_scs[bh][rbase + pr][cbase + pc] = -w2v * scale;
        }
    }
}

// =====================================================================
// K4b: softmax + probs scatter + context.
// =====================================================================
__global__ void __launch_bounds__(256) softmax_ctx_kernel(float* __restrict__ out_probs)
{
    const int blk = blockIdx.x;
    const int bh = blk >> 4;
    const int b = bh >> 2, h = bh & 3;
    const int i0 = (blk & 15) * 8;
    const int t = threadIdx.x;
    const int lane = t & 31;

    __shared__ float sc[8 * 128];
    __shared__ int perm_s[128];
    __shared__ float ctxm[1024], ctxc[1024];

    if (t < 128) perm_s[t] = g_perm[b][t];
    {
        const float4* src = (const float4*)&g_scs[bh][i0][0];
        ((float4*)sc)[t] = src[t];
    }
    __syncthreads();

    {
        int w = t >> 5;
        float4* row = (float4*)(sc + w * 128);
        float4 x4 = row[lane];
        float m = fmaxf(fmaxf(x4.x, x4.y), fmaxf(x4.z, x4.w));
#pragma unroll
        for (int o = 16; o; o >>= 1) m = fmaxf(m, __shfl_xor_sync(0xFFFFFFFFu, m, o));
        float e0 = expf(x4.x - m), e1 = expf(x4.y - m);
        float e2 = expf(x4.z - m), e3 = expf(x4.w - m);
        float s = e0 + e1 + e2 + e3;
#pragma unroll
        for (int o = 16; o; o >>= 1) s += __shfl_xor_sync(0xFFFFFFFFu, s, o);
        float inv = 1.f / s;
        float4 p4 = make_float4(e0 * inv, e1 * inv, e2 * inv, e3 * inv);
        row[lane] = p4;
        int i = perm_s[i0 + w];
        float* op = out_probs + (size_t)(bh * 128 + i) * 128;
        op[perm_s[4 * lane + 0]] = p4.x;
        op[perm_s[4 * lane + 1]] = p4.y;
        op[perm_s[4 * lane + 2]] = p4.z;
        op[perm_s[4 * lane + 3]] = p4.w;
    }
    __syncthreads();

    {
        int k = t & 127, half = t >> 7;
        float am[8] = {}, ac[8] = {};
        const float* v1 = &g_qkv[0][2][b][h][0][0];
        const float* v2 = &g_qkv[1][2][b][h][0][0];
        int j0 = half * 64;
#pragma unroll 4
        for (int pj = j0; pj < j0 + 64; ++pj) {
            int jv = perm_s[pj];
            float x1 = v1[(size_t)jv * 128 + k];
            float x2 = v2[(size_t)jv * 128 + k];
#pragma unroll
            for (int il = 0; il < 8; ++il) {
                float p = sc[il * 128 + pj];
                am[il] += p * x1;
                ac[il] += p * p * x2;
            }
        }
        if (half == 0) {
#pragma unroll
            for (int il = 0; il < 8; ++il) {
                ctxm[il * 128 + k] = am[il];
                ctxc[il * 128 + k] = ac[il];
            }
        }
        __syncthreads();
        if (half == 1) {
#pragma unroll
            for (int il = 0; il < 8; ++il) {
                int i = perm_s[i0 + il];
                g_ctx[0][b][i][h * 128 + k] = am[il] + ctxm[il * 128 + k];
                g_ctx[1][b][i][h * 128 + k] = ac[il] + ctxc[il * 128 + k];
            }
        }
    }
}

// =====================================================================
// K5: output GEMM + bias + residual.
// =====================================================================
__global__ void __launch_bounds__(128) outgemm_kernel(
    const float* __restrict__ mean_w, const float* __restrict__ mean_b,
    const float* __restrict__ cov_w,  const float* __restrict__ cov_b,
    const float* __restrict__ x_m,    const float* __restrict__ x_c)
{
    int z = blockIdx.z;
    const float* W     = z ? cov_w  : mean_w;
    const float* bias  = z ? cov_b  : mean_b;
    const float* resid = z ? x_c    : x_m;
    const float* A = &g_ctx[z][0][0][0];
    float* out = &g_tmp[z][0][0][0];

    const int m0 = blockIdx.x * 32;
    const int n0 = blockIdx.y * 64;
    const int tid = threadIdx.x;
    const int tx = tid & 15, ty = tid >> 4;

    __shared__ __align__(16) float As[16][36];
    __shared__ __align__(16) float Bs[16][68];
    float acc[4][4] = {};

    const int a_row = tid >> 2;
    const int a_k4  = (tid & 3) * 4;

    for (int kk = 0; kk < 512; kk += 16) {
        float4 av = *(const float4*)&A[(size_t)(m0 + a_row) * 512 + kk + a_k4];
        As[a_k4 + 0][a_row] = av.x;
        As[a_k4 + 1][a_row] = av.y;
        As[a_k4 + 2][a_row] = av.z;
        As[a_k4 + 3][a_row] = av.w;
        {
            int c = tid >> 2, k4 = (tid & 3) * 4;
            float4 bv = *(const float4*)&W[(size_t)(n0 + c) * 512 + kk + k4];
            Bs[k4 + 0][c] = bv.x; Bs[k4 + 1][c] = bv.y;
            Bs[k4 + 2][c] = bv.z; Bs[k4 + 3][c] = bv.w;
            int c2 = c + 32;
            float4 bw = *(const float4*)&W[(size_t)(n0 + c2) * 512 + kk + k4];
            Bs[k4 + 0][c2] = bw.x; Bs[k4 + 1][c2] = bw.y;
            Bs[k4 + 2][c2] = bw.z; Bs[k4 + 3][c2] = bw.w;
        }
        __syncthreads();
#pragma unroll
        for (int kd = 0; kd < 16; ++kd) {
            float4 a4 = *(const float4*)&As[kd][ty * 4];
            float4 b4 = *(const float4*)&Bs[kd][tx * 4];
            float a[4] = {a4.x, a4.y, a4.z, a4.w};
            float bb[4] = {b4.x, b4.y, b4.z, b4.w};
#pragma unroll
            for (int r = 0; r < 4; ++r)
#pragma unroll
                for (int c = 0; c < 4; ++c) acc[r][c] += a[r] * bb[c];
        }
        __syncthreads();
    }

#pragma unroll
    for (int r = 0; r < 4; ++r) {
        int m = m0 + ty * 4 + r;
#pragma unroll
        for (int c = 0; c < 4; ++c) {
            int d = n0 + tx * 4 + c;
            out[(size_t)m * 512 + d] = acc[r][c] + bias[d] + resid[(size_t)m * 512 + d];
        }
    }
}

// =====================================================================
// K6: LayerNorm -> d_out
// =====================================================================
__global__ void ln_kernel(const float* __restrict__ ln_w, const float* __restrict__ ln_b,
                          float* __restrict__ d_out_f)
{
    int blk = blockIdx.x;
    int z = blk >> 8;
    int row = blk & 255;
    int tid = threadIdx.x;
    int w = tid >> 5, lane = tid & 31;
    __shared__ float red[8];

    const float* x = &g_tmp[z][0][0][0] + (size_t)row * 512;
    float a0 = x[tid], a1 = x[tid + 256];

    float s = a0 + a1;
#pragma unroll
    for (int o = 16; o; o >>= 1) s += __shfl_xor_sync(0xFFFFFFFFu, s, o);
    if (lane == 0) red[w] = s;
    __syncthreads();
    if (tid == 0) { float t2 = 0.f; for (int q = 0; q < 8; ++q) t2 += red[q]; red[0] = t2; }
    __syncthreads();
    float mean = red[0] * (1.f / 512.f);
    float d0 = a0 - mean, d1 = a1 - mean;
    float v = d0 * d0 + d1 * d1;
    __syncthreads();
#pragma unroll
    for (int o = 16; o; o >>= 1) v += __shfl_xor_sync(0xFFFFFFFFu, v, o);
    if (lane == 0) red[w] = v;
    __syncthreads();
    if (tid == 0) { float t2 = 0.f; for (int q = 0; q < 8; ++q) t2 += red[q]; red[0] = t2; }
    __syncthreads();
    float var = red[0] * (1.f / 512.f);
    float inv = 1.f / sqrtf(var + 1e-12f);

    float* o = d_out_f + (size_t)z * 131072 + (size_t)row * 512;
    o[tid]       = d0 * inv * ln_w[tid]       + ln_b[tid];
    o[tid + 256] = d1 * inv * ln_w[tid + 256] + ln_b[tid + 256];
}

// =====================================================================
extern "C" void kernel_launch(void* const* d_in, const int* in_sizes, int n_in,
                              void* d_out, int out_size)
{
    const float* x_m    = (const float*)d_in[0];
    const float* x_c    = (const float*)d_in[1];
    const float* b_m    = (const float*)d_in[2];
    const float* b_c    = (const float*)d_in[3];
    const float* bb_m   = (const float*)d_in[4];
    const float* bb_c   = (const float*)d_in[5];
    const float* p_m    = (const float*)d_in[6];
    const float* p_c    = (const float*)d_in[7];
    const float* W_xm   = (const float*)d_in[8];
    const float* W_xc   = (const float*)d_in[9];
    const float* W_bm   = (const float*)d_in[10];
    const float* W_bc   = (const float*)d_in[11];
    const float* Wq1_w  = (const float*)d_in[12];
    const float* Wq1_b  = (const float*)d_in[13];
    const float* Wq2_w  = (const float*)d_in[14];
    const float* Wq2_b  = (const float*)d_in[15];
    const float* Wk1_w  = (const float*)d_in[16];
    const float* Wk1_b  = (const float*)d_in[17];
    const float* Wk2_w  = (const float*)d_in[18];
    const float* Wk2_b  = (const float*)d_in[19];
    const float* mean_w = (const float*)d_in[20];
    const float* mean_b = (const float*)d_in[21];
    const float* cov_w  = (const float*)d_in[22];
    const float* cov_b  = (const float*)d_in[23];
    const float* ln_w   = (const float*)d_in[24];
    const float* ln_b   = (const float*)d_in[25];
    const int*   b_seq  = (const int*)d_in[26];

    float* out = (float*)d_out;
    float* out_probs = out + 262144;   // [mean | cov | probs]

    cudaFuncSetAttribute(gemm_fused, cudaFuncAttributeMaxDynamicSharedMemorySize, PROJ_SMEM);

    prep_all<<<3586, 256>>>(x_m, b_m, x_c, b_c, W_xm, W_bm, W_xc, W_bc, b_seq);
    gemm_fused<<<168, 256, PROJ_SMEM>>>(p_m, bb_m,
                                        Wq1_w, Wq1_b, Wq2_w, Wq2_b,
                                        Wk1_w, Wk1_b, Wk2_w, Wk2_b);
    build_fqfk<<<1024, 128>>>(bb_c, p_c, b_seq);
    scores_kernel<<<dim3(16, 16, 8), 256>>>();
    softmax_ctx_kernel<<<128, 256>>>(out_probs);
    outgemm_kernel<<<dim3(8, 8, 2), 128>>>(mean_w, mean_b, cov_w, cov_b, x_m, x_c);
    ln_kernel<<<512, 256>>>(ln_w, ln_b, out);
}

// round 14
// speedup vs baseline: 2.2347x; 1.0572x over previous
#include <cuda_runtime.h>
#include <cuda_bf16.h>
#include <mma.h>
#include <stdint.h>
#include <cstdint>
#include <math.h>

using namespace nvcuda;

#define BATCH 2
#define SEQ 128
#define NH 4
#define DKK 128
#define DD 512
#define NBB 4

// ---------------- scratch (device globals; no allocation allowed) ----------------
__device__ float g_qkv[2][3][BATCH][NH][SEQ][DKK]; // [fam(m/c)][q/k/v][b][h][n][k]
__device__ float g_bbQ[BATCH][NH][NBB][NBB][DKK];
__device__ float g_bbK[BATCH][NH][NBB][NBB][DKK];
__device__ float g_pq[BATCH][NH][SEQ][DKK];
__device__ float g_pk[BATCH][NH][SEQ][DKK];
__device__ float g_FQ[BATCH][NH][SEQ][NBB][2*DKK]; // [m(0..127) | sqrt(c)(128..255)]
__device__ float g_FK[BATCH][NH][SEQ][NBB][2*DKK];
__device__ float g_sqnq[BATCH][NH][SEQ][NBB];
__device__ float g_sqnk[BATCH][NH][SEQ][NBB];
__device__ int   g_perm[BATCH][SEQ];
__device__ int   g_off[BATCH][NBB + 1];
__device__ float g_scs[BATCH*NH][SEQ][SEQ];
__device__ float g_ctx[2][BATCH][SEQ][DD];
__device__ float g_tmp[2][BATCH][SEQ][DD];

// bf16 hi/lo operand copies (pre-split, W pre-transposed)
__device__ __nv_bfloat16 g_Xh[4][256][512];   // [fam*2+pair][m][k]
__device__ __nv_bfloat16 g_Xl[4][256][512];
__device__ __nv_bfloat16 g_WTh[12][512][512]; // [(fam*2+pair)*3+s][hk][k]  (transposed)
__device__ __nv_bfloat16 g_WTl[12][512][512];

// =====================================================================
// K_pre: fused prep_x + prep_w + perm. grid 3586 x 256 thr.
// =====================================================================
__global__ void __launch_bounds__(256) prep_all(
    const float* __restrict__ x_m, const float* __restrict__ b_m,
    const float* __restrict__ x_c, const float* __restrict__ b_c,
    const float* __restrict__ Wxm, const float* __restrict__ Wbm,
    const float* __restrict__ Wxc, const float* __restrict__ Wbc,
    const int* __restrict__ b_seq)
{
    const int blk = blockIdx.x;
    const int t = threadIdx.x;

    if (blk < 512) {
        // ---- X convert ----
        int idx = blk * 256 + t;
        int a = idx >> 15;
        int r = idx & 32767;
        const float* src = (a == 0) ? x_m : (a == 1) ? b_m : (a == 2) ? x_c : b_c;
        float4 v = ((const float4*)src)[r];
        __nv_bfloat16* oh = &g_Xh[0][0][0] + (size_t)a * 131072 + (size_t)r * 4;
        __nv_bfloat16* ol = &g_Xl[0][0][0] + (size_t)a * 131072 + (size_t)r * 4;
        float vv[4];
        vv[0] = v.x; vv[1] = v.y; vv[2] = v.z; vv[3] = v.w;
#pragma unroll
        for (int e = 0; e < 4; ++e) {
            __nv_bfloat16 hi = __float2bfloat16(vv[e]);
            oh[e] = hi;
            ol[e] = __float2bfloat16(vv[e] - __bfloat162float(hi));
        }
    } else if (blk < 3584) {
        // ---- W transpose + convert ----
        int idx2 = blk - 512;
        int mi = idx2 >> 8;
        int rem = idx2 & 255;
        int hk0 = (rem >> 4) * 32;
        int d0  = (rem & 15) * 32;
        int fam = mi / 6;
        int pair = (mi / 3) & 1;
        int s = mi % 3;
        const float* src = (fam == 0) ? (pair == 0 ? Wxm : Wbm)
                                      : (pair == 0 ? Wxc : Wbc);
        src += (size_t)s * 262144;

        __shared__ float tile[32][33];
        int r = t >> 3, c4 = (t & 7) * 4;
        float4 v = *(const float4*)&src[(size_t)(d0 + r) * 512 + hk0 + c4];
        tile[r][c4 + 0] = v.x; tile[r][c4 + 1] = v.y;
        tile[r][c4 + 2] = v.z; tile[r][c4 + 3] = v.w;
        __syncthreads();

        __nv_bfloat16* oh = &g_WTh[0][0][0] + (size_t)mi * 262144 + (size_t)(hk0 + r) * 512 + d0 + c4;
        __nv_bfloat16* ol = &g_WTl[0][0][0] + (size_t)mi * 262144 + (size_t)(hk0 + r) * 512 + d0 + c4;
#pragma unroll
        for (int e = 0; e < 4; ++e) {
            float f = tile[c4 + e][r];
            __nv_bfloat16 hi = __float2bfloat16(f);
            oh[e] = hi;
            ol[e] = __float2bfloat16(f - __bfloat162float(hi));
        }
    } else {
        // ---- ballot counting sort (1 block per batch) ----
        int b = blk - 3584;
        __shared__ int wcnt[4][4];
        int w = t >> 5, lane = t & 31;
        int key = 0, rank_w = 0;
        if (t < 128) {
            key = b_seq[b * 128 + t];
            unsigned b0 = __ballot_sync(0xFFFFFFFFu, key == 0);
            unsigned b1 = __ballot_sync(0xFFFFFFFFu, key == 1);
            unsigned b2 = __ballot_sync(0xFFFFFFFFu, key == 2);
            unsigned b3 = __ballot_sync(0xFFFFFFFFu, key == 3);
            if (lane == 0) {
                wcnt[w][0] = __popc(b0); wcnt[w][1] = __popc(b1);
                wcnt[w][2] = __popc(b2); wcnt[w][3] = __popc(b3);
            }
            unsigned mymask = (key == 0) ? b0 : (key == 1) ? b1 : (key == 2) ? b2 : b3;
            rank_w = __popc(mymask & ((1u << lane) - 1u));
        }
        __syncthreads();
        if (t < 128) {
            int cnt[4];
#pragma unroll
            for (int k = 0; k < 4; ++k)
                cnt[k] = wcnt[0][k] + wcnt[1][k] + wcnt[2][k] + wcnt[3][k];
            int off = 0;
#pragma unroll
            for (int k = 0; k < 4; ++k) if (k < key) off += cnt[k];
            int pre = 0;
#pragma unroll
            for (int w2 = 0; w2 < 4; ++w2) if (w2 < w) pre += wcnt[w2][key];
            g_perm[b][off + pre + rank_w] = t;
            if (t < 5) {
                int o = 0;
                for (int k = 0; k < t; ++k) o += cnt[k];
                g_off[b][t] = o;
            }
        }
    }
}

// =====================================================================
// K_gemm: fused proj (wmma, blocks [0,96)) + linqk (blocks [96,168)).
// =====================================================================
#define PROJ_SMEM 55296

__global__ void __launch_bounds__(256) gemm_fused(
    const float* __restrict__ p_m,  const float* __restrict__ bb_m,
    const float* __restrict__ Wq1_w, const float* __restrict__ Wq1_b,
    const float* __restrict__ Wq2_w, const float* __restrict__ Wq2_b,
    const float* __restrict__ Wk1_w, const float* __restrict__ Wk1_b,
    const float* __restrict__ Wk2_w, const float* __restrict__ Wk2_b)
{
    const int t = threadIdx.x;

    if (blockIdx.x < 96) {
        // ================= proj path =================
        extern __shared__ char ds[];
        __nv_bfloat16* Ah = (__nv_bfloat16*)ds;       // [128][72]
        __nv_bfloat16* Al = Ah + 128 * 72;
        __nv_bfloat16* Bh = Al + 128 * 72;            // [64][72]
        __nv_bfloat16* Bl = Bh + 64 * 72;

        const int u = blockIdx.x;
        const int fam = u / 48;
        const int v = u % 48;
        const int m0 = (v / 24) * 128;
        const int n0g = (v % 24) * 64;
        const int s_idx = n0g >> 9;
        const int cbase = n0g & 511;

        const int w = t >> 5;
        const int wm = (w >> 1) * 32;
        const int wn = (w & 1) * 32;

        wmma::fragment<wmma::accumulator, 16, 16, 16, float> acc[2][2];
#pragma unroll
        for (int r = 0; r < 2; ++r)
#pragma unroll
            for (int c = 0; c < 2; ++c) wmma::fill_fragment(acc[r][c], 0.f);

        uint4 pf[12];

        // prefetch chunk 0
        {
            const int ai = fam * 2;
            const int mi = ai * 3 + s_idx;
            const __nv_bfloat16* Axh = &g_Xh[ai][m0][0];
            const __nv_bfloat16* Axl = &g_Xl[ai][m0][0];
            const __nv_bfloat16* Bxh = &g_WTh[0][0][0] + (size_t)mi * 262144 + (size_t)cbase * 512;
            const __nv_bfloat16* Bxl = &g_WTl[0][0][0] + (size_t)mi * 262144 + (size_t)cbase * 512;
#pragma unroll
            for (int q = 0; q < 4; ++q) {
                int s = t + 256 * q;
                int r = s >> 3, kb = s & 7;
                pf[q]     = *(const uint4*)(Axh + (size_t)r * 512 + kb * 8);
                pf[4 + q] = *(const uint4*)(Axl + (size_t)r * 512 + kb * 8);
            }
#pragma unroll
            for (int q = 0; q < 2; ++q) {
                int s = t + 256 * q;
                int r = s >> 3, kb = s & 7;
                pf[8 + q]  = *(const uint4*)(Bxh + (size_t)r * 512 + kb * 8);
                pf[10 + q] = *(const uint4*)(Bxl + (size_t)r * 512 + kb * 8);
            }
        }

        for (int c = 0; c < 16; ++c) {
#pragma unroll
            for (int q = 0; q < 4; ++q) {
                int s = t + 256 * q;
                int r = s >> 3, kb = s & 7;
                *(uint4*)((char*)Ah + (size_t)r * 144 + kb * 16) = pf[q];
                *(uint4*)((char*)Al + (size_t)r * 144 + kb * 16) = pf[4 + q];
            }
#pragma unroll
            for (int q = 0; q < 2; ++q) {
                int s = t + 256 * q;
                int r = s >> 3, kb = s & 7;
                *(uint4*)((char*)Bh + (size_t)r * 144 + kb * 16) = pf[8 + q];
                *(uint4*)((char*)Bl + (size_t)r * 144 + kb * 16) = pf[10 + q];
            }
            __syncthreads();

            if (c + 1 < 16) {
                const int nx = c + 1;
                const int pair = nx >> 3;
                const int kk = (nx & 7) * 64;
                const int ai = fam * 2 + pair;
                const int mi = ai * 3 + s_idx;
                const __nv_bfloat16* Axh = &g_Xh[ai][m0][kk];
                const __nv_bfloat16* Axl = &g_Xl[ai][m0][kk];
                const __nv_bfloat16* Bxh = &g_WTh[0][0][0] + (size_t)mi * 262144 + (size_t)cbase * 512 + kk;
                const __nv_bfloat16* Bxl = &g_WTl[0][0][0] + (size_t)mi * 262144 + (size_t)cbase * 512 + kk;
#pragma unroll
                for (int q = 0; q < 4; ++q) {
                    int s = t + 256 * q;
                    int r = s >> 3, kb = s & 7;
                    pf[q]     = *(const uint4*)(Axh + (size_t)r * 512 + kb * 8);
                    pf[4 + q] = *(const uint4*)(Axl + (size_t)r * 512 + kb * 8);
                }
#pragma unroll
                for (int q = 0; q < 2; ++q) {
                    int s = t + 256 * q;
                    int r = s >> 3, kb = s & 7;
                    pf[8 + q]  = *(const uint4*)(Bxh + (size_t)r * 512 + kb * 8);
                    pf[10 + q] = *(const uint4*)(Bxl + (size_t)r * 512 + kb * 8);
                }
            }

#pragma unroll
            for (int ks = 0; ks < 4; ++ks) {
                wmma::fragment<wmma::matrix_a, 16, 16, 16, __nv_bfloat16, wmma::row_major> ah[2], al[2];
                wmma::fragment<wmma::matrix_b, 16, 16, 16, __nv_bfloat16, wmma::col_major> bh[2], bl[2];
#pragma unroll
                for (int r = 0; r < 2; ++r) {
                    wmma::load_matrix_sync(ah[r], Ah + (wm + 16 * r) * 72 + ks * 16, 72);
                    wmma::load_matrix_sync(al[r], Al + (wm + 16 * r) * 72 + ks * 16, 72);
                }
#pragma unroll
                for (int cb = 0; cb < 2; ++cb) {
                    wmma::load_matrix_sync(bh[cb], Bh + (wn + 16 * cb) * 72 + ks * 16, 72);
                    wmma::load_matrix_sync(bl[cb], Bl + (wn + 16 * cb) * 72 + ks * 16, 72);
                }
#pragma unroll
                for (int r = 0; r < 2; ++r)
#pragma unroll
                    for (int cb = 0; cb < 2; ++cb) {
                        wmma::mma_sync(acc[r][cb], ah[r], bh[cb], acc[r][cb]);
                        wmma::mma_sync(acc[r][cb], ah[r], bl[cb], acc[r][cb]);
                        wmma::mma_sync(acc[r][cb], al[r], bh[cb], acc[r][cb]);
                    }
            }
            __syncthreads();
        }

        const int h_idx = cbase >> 7;
        const int k0 = cbase & 127;
        const int b = m0 >> 7;
        float* outp = &g_qkv[fam][s_idx][b][h_idx][0][k0];

#pragma unroll
        for (int r = 0; r < 2; ++r)
#pragma unroll
            for (int cb = 0; cb < 2; ++cb) {
                if (fam == 1) {
#pragma unroll
                    for (int e = 0; e < acc[r][cb].num_elements; ++e) {
                        float vv = acc[r][cb].x[e];
                        acc[r][cb].x[e] = (vv > 0.f) ? (vv + 1.f) : expf(vv);
                    }
                }
                wmma::store_matrix_sync(&outp[(size_t)(wm + 16 * r) * 128 + wn + 16 * cb],
                                        acc[r][cb], 128, wmma::mem_row_major);
            }
    } else {
        // ================= linqk path =================
        const int u2 = blockIdx.x - 96;
        const int sel = u2 / 36;
        const int rr2 = u2 % 36;
        const int m0 = (rr2 >> 1) * 64;
        const int n0 = (rr2 & 1) * 64;
        const bool bbreg = (m0 >= 1024);

        const float* W    = sel ? (bbreg ? Wk1_w : Wk2_w) : (bbreg ? Wq1_w : Wq2_w);
        const float* bias = sel ? (bbreg ? Wk1_b : Wk2_b) : (bbreg ? Wq1_b : Wq2_b);

        const int tx = t & 15, ty = t >> 4;

        __shared__ __align__(16) float As[16][68];
        __shared__ __align__(16) float Bs[16][68];

        float acc[4][4] = {};

        const int a_row = t >> 2;
        const int a_k4  = (t & 3) * 4;

        for (int kk = 0; kk < 128; kk += 16) {
            {
                int r = m0 + a_row;
                const float* src;
                if (r < 1024) {
                    int b = r >> 9, h = (r >> 7) & 3, n = r & 127;
                    src = p_m + (size_t)(b * 128 + n) * 512 + h * 128 + kk + a_k4;
                } else {
                    int r2 = r - 1024;
                    int b = r2 >> 6, h = (r2 >> 4) & 3, nn = r2 & 15;
                    src = bb_m + (size_t)(b * 16 + nn) * 512 + h * 128 + kk + a_k4;
                }
                float4 av = *(const float4*)src;
                As[a_k4 + 0][a_row] = av.x;
                As[a_k4 + 1][a_row] = av.y;
                As[a_k4 + 2][a_row] = av.z;
                As[a_k4 + 3][a_row] = av.w;
            }
            {
                int c = t >> 2, k4 = (t & 3) * 4;
                float4 bv = *(const float4*)&W[(size_t)(n0 + c) * 128 + kk + k4];
                Bs[k4 + 0][c] = bv.x;
                Bs[k4 + 1][c] = bv.y;
                Bs[k4 + 2][c] = bv.z;
                Bs[k4 + 3][c] = bv.w;
            }
            __syncthreads();
#pragma unroll
            for (int kd = 0; kd < 16; ++kd) {
                float4 a4 = *(const float4*)&As[kd][ty * 4];
                float4 b4 = *(const float4*)&Bs[kd][tx * 4];
                float a[4] = {a4.x, a4.y, a4.z, a4.w};
                float bb[4] = {b4.x, b4.y, b4.z, b4.w};
#pragma unroll
                for (int r = 0; r < 4; ++r)
#pragma unroll
                    for (int c = 0; c < 4; ++c) acc[r][c] += a[r] * bb[c];
            }
            __syncthreads();
        }

        float* outp = sel ? &g_pk[0][0][0][0] : &g_pq[0][0][0][0];
        float* outb = sel ? &g_bbK[0][0][0][0][0] : &g_bbQ[0][0][0][0][0];
#pragma unroll
        for (int r = 0; r < 4; ++r) {
            int rr = m0 + ty * 4 + r;
#pragma unroll
            for (int c = 0; c < 4; ++c) {
                int col = n0 + tx * 4 + c;
                float v = acc[r][c] + bias[col];
                if (rr < 1024) outp[(size_t)rr * 128 + col] = v;
                else           outb[(size_t)(rr - 1024) * 128 + col] = v;
            }
        }
    }
}

// =====================================================================
// K3: tri-SAGP fusion -> FQ/FK + squared norms.
// =====================================================================
__global__ void __launch_bounds__(128) build_fqfk(const float* __restrict__ bb_c,
                                                  const float* __restrict__ p_c,
                                                  const int* __restrict__ b_seq)
{
    int r = blockIdx.x;                 // 0..1023 = (b,h,i)
    int b  = r >> 9;
    int hh = (r >> 7) & 3;
    int i  = r & 127;
    int t  = threadIdx.x;               // 128
    int w = t >> 5, lane = t & 31;
    const float eps = 1e-24f;

    __shared__ float rq[4][4];
    __shared__ float rk[4][4];

    int si = b_seq[b * 128 + i];
    float c3 = p_c[(size_t)(b * 128 + i) * 512 + hh * 128 + t];
    float p3 = 1.f / fmaxf(c3, eps);

    float nq[4], nk[4];

    {
        float m1 = g_qkv[0][0][b][hh][i][t];
        float c1 = g_qkv[1][0][b][hh][i][t];
        float m3 = g_pq[b][hh][i][t];
        float p1 = 1.f / fmaxf(c1, eps);
        float base_m = m1 * p1 + m3 * p3;
        float base_p = p1 + p3;
#pragma unroll
        for (int sb = 0; sb < 4; ++sb) {
            float m2 = g_bbQ[b][hh][sb][si][t];
            float c2 = bb_c[(size_t)((b * 4 + sb) * 4 + si) * 512 + hh * 128 + t];
            float p2 = 1.f / fmaxf(c2, eps);
            float cf = 1.f / (base_p + p2);
            float mf = cf * (base_m + m2 * p2);
            float cfc = fmaxf(cf, eps);
            g_FQ[b][hh][i][sb][t]       = mf;
            g_FQ[b][hh][i][sb][128 + t] = sqrtf(cfc);
            nq[sb] = mf * mf + cfc;
        }
    }
    {
        float m1 = g_qkv[0][1][b][hh][i][t];
        float c1 = g_qkv[1][1][b][hh][i][t];
        float m3 = g_pk[b][hh][i][t];
        float p1 = 1.f / fmaxf(c1, eps);
        float base_m = m1 * p1 + m3 * p3;
        float base_p = p1 + p3;
        int sj = si;
#pragma unroll
        for (int sa = 0; sa < 4; ++sa) {
            float m2 = g_bbK[b][hh][sj][sa][t];
            float c2 = bb_c[(size_t)((b * 4 + sj) * 4 + sa) * 512 + hh * 128 + t];
            float p2 = 1.f / fmaxf(c2, eps);
            float cf = 1.f / (base_p + p2);
            float mf = cf * (base_m + m2 * p2);
            float cfc = fmaxf(cf, eps);
            g_FK[b][hh][i][sa][t]       = mf;
            g_FK[b][hh][i][sa][128 + t] = sqrtf(cfc);
            nk[sa] = mf * mf + cfc;
        }
    }

#pragma unroll
    for (int sb = 0; sb < 4; ++sb) {
        float a = nq[sb];
        float c = nk[sb];
#pragma unroll
        for (int o = 16; o; o >>= 1) {
            a += __shfl_xor_sync(0xFFFFFFFFu, a, o);
            c += __shfl_xor_sync(0xFFFFFFFFu, c, o);
        }
        if (lane == 0) { rq[w][sb] = a; rk[w][sb] = c; }
    }
    __syncthreads();
    if (t < 4) {
        g_sqnq[b][hh][i][t] = rq[0][t] + rq[1][t] + rq[2][t] + rq[3][t];
    } else if (t < 8) {
        int sb = t - 4;
        g_sqnk[b][hh][i][sb] = rk[0][sb] + rk[1][sb] + rk[2][sb] + rk[3][sb];
    }
}

// =====================================================================
// K4a: bucketed score GEMM. 128 thr, K-split halves, 4x4 register tiles.
// grid (16, 16, 8): x = 4x4 subtile, y = (si,sb), z = bh.
// =====================================================================
__global__ void __launch_bounds__(128) scores_kernel()
{
    const int bh = blockIdx.z;
    const int b = bh >> 2, h = bh & 3;
    const int si = blockIdx.y >> 2, sb = blockIdx.y & 3;
    const int ti = (blockIdx.x >> 2) * 32, tj = (blockIdx.x & 3) * 32;

    const int rbase = g_off[b][si], rcnt = g_off[b][si + 1] - rbase;
    const int cbase = g_off[b][sb], ccnt = g_off[b][sb + 1] - cbase;
    if (ti >= rcnt || tj >= ccnt) return;

    const int t = threadIdx.x;
    const int half = t >> 6;            // K-split: half 0 -> K[0,128), half 1 -> K[128,256)
    const int lt = t & 63;
    const int tx = lt & 7;              // 8 col groups x 4
    const int ty = lt >> 3;             // 8 row groups x 4

    __shared__ __align__(16) float As[2][16][36];
    __shared__ __align__(16) float Bs[2][16][36];
    __shared__ __align__(16) float Ps[32][33];
    __shared__ int rid[32], cid[32];
    __shared__ float sqr[32], sqc[32];

    if (t < 32) {
        int pr = ti + t; if (pr > rcnt - 1) pr = rcnt - 1;
        int id = g_perm[b][rbase + pr];
        rid[t] = id;
        sqr[t] = g_sqnq[b][h][id][sb];
    } else if (t < 64) {
        int u = t - 32;
        int pc = tj + u; if (pc > ccnt - 1) pc = ccnt - 1;
        int id = g_perm[b][cbase + pc];
        cid[u] = id;
        sqc[u] = g_sqnk[b][h][id][si];
    }
    __syncthreads();

    float acc[4][4] = {};
    const int kh = half * 128;          // this half's K base
    // staging: per half, 128 float4 slots: s = lt + 64q, row = s>>2, k4 = (s&3)*4
    const int sr0 = lt >> 2;            // q=0 row
    const int sk4 = (lt & 3) * 4;

    for (int kk = 0; kk < 128; kk += 16) {
        {
            float4 av0 = *(const float4*)&g_FQ[b][h][rid[sr0]][sb][kh + kk + sk4];
            As[half][sk4 + 0][sr0] = av0.x;
            As[half][sk4 + 1][sr0] = av0.y;
            As[half][sk4 + 2][sr0] = av0.z;
            As[half][sk4 + 3][sr0] = av0.w;
            int sr1 = sr0 + 16;
            float4 av1 = *(const float4*)&g_FQ[b][h][rid[sr1]][sb][kh + kk + sk4];
            As[half][sk4 + 0][sr1] = av1.x;
            As[half][sk4 + 1][sr1] = av1.y;
            As[half][sk4 + 2][sr1] = av1.z;
            As[half][sk4 + 3][sr1] = av1.w;
            float4 bv0 = *(const float4*)&g_FK[b][h][cid[sr0]][si][kh + kk + sk4];
            Bs[half][sk4 + 0][sr0] = bv0.x;
            Bs[half][sk4 + 1][sr0] = bv0.y;
            Bs[half][sk4 + 2][sr0] = bv0.z;
            Bs[half][sk4 + 3][sr0] = bv0.w;
            float4 bv1 = *(const float4*)&g_FK[b][h][cid[sr1]][si][kh + kk + sk4];
            Bs[half][sk4 + 0][sr1] = bv1.x;
            Bs[half][sk4 + 1][sr1] = bv1.y;
            Bs[half][sk4 + 2][sr1] = bv1.z;
            Bs[half][sk4 + 3][sr1] = bv1.w;
        }
        __syncthreads();
#pragma unroll
        for (int kd = 0; kd < 16; ++kd) {
            float4 a4 = *(const float4*)&As[half][kd][ty * 4];
            float4 b4 = *(const float4*)&Bs[half][kd][tx * 4];
            float a[4] = {a4.x, a4.y, a4.z, a4.w};
            float bb[4] = {b4.x, b4.y, b4.z, b4.w};
#pragma unroll
            for (int r = 0; r < 4; ++r)
#pragma unroll
                for (int c = 0; c < 4; ++c) acc[r][c] += a[r] * bb[c];
        }
        __syncthreads();
    }

    // combine halves
    if (half == 0) {
#pragma unroll
        for (int r = 0; r < 4; ++r)
#pragma unroll
            for (int c = 0; c < 4; ++c)
                Ps[ty * 4 + r][tx * 4 + c] = acc[r][c];
    }
    __syncthreads();
    if (half == 1) {
        const float scale = 0.08838834764831845f;   // 1/sqrt(128)
#pragma unroll
        for (int r = 0; r < 4; ++r) {
            int pr = ti + ty * 4 + r;
            if (pr >= rcnt) continue;
#pragma unroll
            for (int c = 0; c < 4; ++c) {
                int pc = tj + tx * 4 + c;
                if (pc >= ccnt) continue;
                float dot = acc[r][c] + Ps[ty * 4 + r][tx * 4 + c];
                float w2v = sqr[ty * 4 + r] + sqc[tx * 4 + c] - 2.f * dot;
                g_scs[bh][rbase + pr][cbase + pc] = -w2v * scale;
            }
        }
    }
}

// =====================================================================
// K4b: softmax + probs scatter + context.
// =====================================================================
__global__ void __launch_bounds__(256) softmax_ctx_kernel(float* __restrict__ out_probs)
{
    const int blk = blockIdx.x;
    const int bh = blk >> 4;
    const int b = bh >> 2, h = bh & 3;
    const int i0 = (blk & 15) * 8;
    const int t = threadIdx.x;
    const int lane = t & 31;

    __shared__ float sc[8 * 128];
    __shared__ int perm_s[128];
    __shared__ float ctxm[1024], ctxc[1024];

    if (t < 128) perm_s[t] = g_perm[b][t];
    {
        const float4* src = (const float4*)&g_scs[bh][i0][0];
        ((float4*)sc)[t] = src[t];
    }
    __syncthreads();

    {
        int w = t >> 5;
        float4* row = (float4*)(sc + w * 128);
        float4 x4 = row[lane];
        float m = fmaxf(fmaxf(x4.x, x4.y), fmaxf(x4.z, x4.w));
#pragma unroll
        for (int o = 16; o; o >>= 1) m = fmaxf(m, __shfl_xor_sync(0xFFFFFFFFu, m, o));
        float e0 = expf(x4.x - m), e1 = expf(x4.y - m);
        float e2 = expf(x4.z - m), e3 = expf(x4.w - m);
        float s = e0 + e1 + e2 + e3;
#pragma unroll
        for (int o = 16; o; o >>= 1) s += __shfl_xor_sync(0xFFFFFFFFu, s, o);
        float inv = 1.f / s;
        float4 p4 = make_float4(e0 * inv, e1 * inv, e2 * inv, e3 * inv);
        row[lane] = p4;
        int i = perm_s[i0 + w];
        float* op = out_probs + (size_t)(bh * 128 + i) * 128;
        op[perm_s[4 * lane + 0]] = p4.x;
        op[perm_s[4 * lane + 1]] = p4.y;
        op[perm_s[4 * lane + 2]] = p4.z;
        op[perm_s[4 * lane + 3]] = p4.w;
    }
    __syncthreads();

    {
        int k = t & 127, half = t >> 7;
        float am[8] = {}, ac[8] = {};
        const float* v1 = &g_qkv[0][2][b][h][0][0];
        const float* v2 = &g_qkv[1][2][b][h][0][0];
        int j0 = half * 64;
#pragma unroll 4
        for (int pj = j0; pj < j0 + 64; ++pj) {
            int jv = perm_s[pj];
            float x1 = v1[(size_t)jv * 128 + k];
            float x2 = v2[(size_t)jv * 128 + k];
#pragma unroll
            for (int il = 0; il < 8; ++il) {
                float p = sc[il * 128 + pj];
                am[il] += p * x1;
                ac[il] += p * p * x2;
            }
        }
        if (half == 0) {
#pragma unroll
            for (int il = 0; il < 8; ++il) {
                ctxm[il * 128 + k] = am[il];
                ctxc[il * 128 + k] = ac[il];
            }
        }
        __syncthreads();
        if (half == 1) {
#pragma unroll
            for (int il = 0; il < 8; ++il) {
                int i = perm_s[i0 + il];
                g_ctx[0][b][i][h * 128 + k] = am[il] + ctxm[il * 128 + k];
                g_ctx[1][b][i][h * 128 + k] = ac[il] + ctxc[il * 128 + k];
            }
        }
    }
}

// =====================================================================
// K5: output GEMM + bias + residual.
// =====================================================================
__global__ void __launch_bounds__(128) outgemm_kernel(
    const float* __restrict__ mean_w, const float* __restrict__ mean_b,
    const float* __restrict__ cov_w,  const float* __restrict__ cov_b,
    const float* __restrict__ x_m,    const float* __restrict__ x_c)
{
    int z = blockIdx.z;
    const float* W     = z ? cov_w  : mean_w;
    const float* bias  = z ? cov_b  : mean_b;
    const float* resid = z ? x_c    : x_m;
    const float* A = &g_ctx[z][0][0][0];
    float* out = &g_tmp[z][0][0][0];

    const int m0 = blockIdx.x * 32;
    const int n0 = blockIdx.y * 64;
    const int tid = threadIdx.x;
    const int tx = tid & 15, ty = tid >> 4;

    __shared__ __align__(16) float As[16][36];
    __shared__ __align__(16) float Bs[16][68];
    float acc[4][4] = {};

    const int a_row = tid >> 2;
    const int a_k4  = (tid & 3) * 4;

    for (int kk = 0; kk < 512; kk += 16) {
        float4 av = *(const float4*)&A[(size_t)(m0 + a_row) * 512 + kk + a_k4];
        As[a_k4 + 0][a_row] = av.x;
        As[a_k4 + 1][a_row] = av.y;
        As[a_k4 + 2][a_row] = av.z;
        As[a_k4 + 3][a_row] = av.w;
        {
            int c = tid >> 2, k4 = (tid & 3) * 4;
            float4 bv = *(const float4*)&W[(size_t)(n0 + c) * 512 + kk + k4];
            Bs[k4 + 0][c] = bv.x; Bs[k4 + 1][c] = bv.y;
            Bs[k4 + 2][c] = bv.z; Bs[k4 + 3][c] = bv.w;
            int c2 = c + 32;
            float4 bw = *(const float4*)&W[(size_t)(n0 + c2) * 512 + kk + k4];
            Bs[k4 + 0][c2] = bw.x; Bs[k4 + 1][c2] = bw.y;
            Bs[k4 + 2][c2] = bw.z; Bs[k4 + 3][c2] = bw.w;
        }
        __syncthreads();
#pragma unroll
        for (int kd = 0; kd < 16; ++kd) {
            float4 a4 = *(const float4*)&As[kd][ty * 4];
            float4 b4 = *(const float4*)&Bs[kd][tx * 4];
            float a[4] = {a4.x, a4.y, a4.z, a4.w};
            float bb[4] = {b4.x, b4.y, b4.z, b4.w};
#pragma unroll
            for (int r = 0; r < 4; ++r)
#pragma unroll
                for (int c = 0; c < 4; ++c) acc[r][c] += a[r] * bb[c];
        }
        __syncthreads();
    }

#pragma unroll
    for (int r = 0; r < 4; ++r) {
        int m = m0 + ty * 4 + r;
#pragma unroll
        for (int c = 0; c < 4; ++c) {
            int d = n0 + tx * 4 + c;
            out[(size_t)m * 512 + d] = acc[r][c] + bias[d] + resid[(size_t)m * 512 + d];
        }
    }
}

// =====================================================================
// K6: LayerNorm -> d_out
// =====================================================================
__global__ void ln_kernel(const float* __restrict__ ln_w, const float* __restrict__ ln_b,
                          float* __restrict__ d_out_f)
{
    int blk = blockIdx.x;
    int z = blk >> 8;
    int row = blk & 255;
    int tid = threadIdx.x;
    int w = tid >> 5, lane = tid & 31;
    __shared__ float red[8];

    const float* x = &g_tmp[z][0][0][0] + (size_t)row * 512;
    float a0 = x[tid], a1 = x[tid + 256];

    float s = a0 + a1;
#pragma unroll
    for (int o = 16; o; o >>= 1) s += __shfl_xor_sync(0xFFFFFFFFu, s, o);
    if (lane == 0) red[w] = s;
    __syncthreads();
    if (tid == 0) { float t2 = 0.f; for (int q = 0; q < 8; ++q) t2 += red[q]; red[0] = t2; }
    __syncthreads();
    float mean = red[0] * (1.f / 512.f);
    float d0 = a0 - mean, d1 = a1 - mean;
    float v = d0 * d0 + d1 * d1;
    __syncthreads();
#pragma unroll
    for (int o = 16; o; o >>= 1) v += __shfl_xor_sync(0xFFFFFFFFu, v, o);
    if (lane == 0) red[w] = v;
    __syncthreads();
    if (tid == 0) { float t2 = 0.f; for (int q = 0; q < 8; ++q) t2 += red[q]; red[0] = t2; }
    __syncthreads();
    float var = red[0] * (1.f / 512.f);
    float inv = 1.f / sqrtf(var + 1e-12f);

    float* o = d_out_f + (size_t)z * 131072 + (size_t)row * 512;
    o[tid]       = d0 * inv * ln_w[tid]       + ln_b[tid];
    o[tid + 256] = d1 * inv * ln_w[tid + 256] + ln_b[tid + 256];
}

// =====================================================================
extern "C" void kernel_launch(void* const* d_in, const int* in_sizes, int n_in,
                              void* d_out, int out_size)
{
    const float* x_m    = (const float*)d_in[0];
    const float* x_c    = (const float*)d_in[1];
    const float* b_m    = (const float*)d_in[2];
    const float* b_c    = (const float*)d_in[3];
    const float* bb_m   = (const float*)d_in[4];
    const float* bb_c   = (const float*)d_in[5];
    const float* p_m    = (const float*)d_in[6];
    const float* p_c    = (const float*)d_in[7];
    const float* W_xm   = (const float*)d_in[8];
    const float* W_xc   = (const float*)d_in[9];
    const float* W_bm   = (const float*)d_in[10];
    const float* W_bc   = (const float*)d_in[11];
    const float* Wq1_w  = (const float*)d_in[12];
    const float* Wq1_b  = (const float*)d_in[13];
    const float* Wq2_w  = (const float*)d_in[14];
    const float* Wq2_b  = (const float*)d_in[15];
    const float* Wk1_w  = (const float*)d_in[16];
    const float* Wk1_b  = (const float*)d_in[17];
    const float* Wk2_w  = (const float*)d_in[18];
    const float* Wk2_b  = (const float*)d_in[19];
    const float* mean_w = (const float*)d_in[20];
    const float* mean_b = (const float*)d_in[21];
    const float* cov_w  = (const float*)d_in[22];
    const float* cov_b  = (const float*)d_in[23];
    const float* ln_w   = (const float*)d_in[24];
    const float* ln_b   = (const float*)d_in[25];
    const int*   b_seq  = (const int*)d_in[26];

    float* out = (float*)d_out;
    float* out_probs = out + 262144;   // [mean | cov | probs]

    cudaFuncSetAttribute(gemm_fused, cudaFuncAttributeMaxDynamicSharedMemorySize, PROJ_SMEM);

    prep_all<<<3586, 256>>>(x_m, b_m, x_c, b_c, W_xm, W_bm, W_xc, W_bc, b_seq);
    gemm_fused<<<168, 256, PROJ_SMEM>>>(p_m, bb_m,
                                        Wq1_w, Wq1_b, Wq2_w, Wq2_b,
                                        Wk1_w, Wk1_b, Wk2_w, Wk2_b);
    build_fqfk<<<1024, 128>>>(bb_c, p_c, b_seq);
    scores_kernel<<<dim3(16, 16, 8), 128>>>();
    softmax_ctx_kernel<<<128, 256>>>(out_probs);
    outgemm_kernel<<<dim3(8, 8, 2), 128>>>(mean_w, mean_b, cov_w, cov_b, x_m, x_c);
    ln_kernel<<<512, 256>>>(ln_w, ln_b, out);
}